// round 4
// baseline (speedup 1.0000x reference)
#include <cuda_runtime.h>
#include <cuda_bf16.h>
#include <math.h>

#define NB      4
#define SEQ     8192
#define DM      512
#define NH      8
#define DH      64
#define NM      256
#define LG      32
#define BH      32          // NB*NH
#define TRIPLE  1536
#define ROWS    32768       // NB*SEQ

// ---------------- scratch (device globals; no allocations allowed) -------
__device__ float g_qkv[(size_t)ROWS * TRIPLE];        // 201 MB
__device__ float g_q [(size_t)BH * SEQ * DH];         // packed, pre-scaled by dh^-0.5
__device__ float g_k [(size_t)BH * SEQ * DH];
__device__ float g_v [(size_t)BH * SEQ * DH];
__device__ float g_ql[BH * NM * DH];
__device__ float g_kl[BH * NM * DH];
__device__ float g_X [BH * NM * NM];                  // attn2
__device__ float g_Za[BH * NM * NM];
__device__ float g_Zb[BH * NM * NM];
__device__ float g_XZ[BH * NM * NM];
__device__ float g_T1[BH * NM * NM];
__device__ float g_T2[BH * NM * NM];
__device__ float g_S [(size_t)BH * NM * SEQ];         // sim3 then sim1 (268 MB)
__device__ float g_C2p[8 * BH * NM * DH];             // split-K partials
__device__ float g_C2[BH * NM * DH];
__device__ float g_Cm[BH * NM * DH];                  // Z @ C2
__device__ float g_O1[(size_t)BH * SEQ * DH];         // attn1 @ Cm
__device__ float g_Y [(size_t)ROWS * DM];             // pre-out-proj
__device__ unsigned int g_mx[2];

// =====================================================================
// SGEMM: C[M,N] = A[M,K]@B[K,N] (+bias). 128x128 tile, BK=8, double buffered.
// M,N multiples of 128; K multiple of 8.
// =====================================================================
__global__ __launch_bounds__(256)
void k_sgemm(const float* __restrict__ A, const float* __restrict__ B,
             const float* __restrict__ bias, float* __restrict__ C,
             int M, int N, int K) {
    __shared__ float As[2][8][132];
    __shared__ float Bs[2][8][128];
    const int tid = threadIdx.x, bx = blockIdx.x, by = blockIdx.y;
    const int aR = tid >> 1, aC = (tid & 1) << 2;
    const int bR = tid >> 5, bC = (tid & 31) << 2;
    const float* Ag = A + (size_t)(by * 128 + aR) * K + aC;
    const float* Bg = B + (size_t)bR * N + bx * 128 + bC;

    float4 av = *(const float4*)Ag;
    float4 bv = *(const float4*)Bg;
    As[0][aC + 0][aR] = av.x; As[0][aC + 1][aR] = av.y;
    As[0][aC + 2][aR] = av.z; As[0][aC + 3][aR] = av.w;
    *(float4*)&Bs[0][bR][bC] = bv;
    __syncthreads();

    float acc[8][8];
    #pragma unroll
    for (int i = 0; i < 8; i++)
        #pragma unroll
        for (int j = 0; j < 8; j++) acc[i][j] = 0.f;

    const int tx = (tid & 15) << 3, ty = (tid >> 4) << 3;
    const int nT = K >> 3;

    for (int t = 0; t < nT; t++) {
        const int cur = t & 1;
        if (t + 1 < nT) {
            av = *(const float4*)(Ag + (t + 1) * 8);
            bv = *(const float4*)(Bg + (size_t)(t + 1) * 8 * N);
        }
        #pragma unroll
        for (int k = 0; k < 8; k++) {
            float a[8], b[8];
            *(float4*)&a[0] = *(float4*)&As[cur][k][ty];
            *(float4*)&a[4] = *(float4*)&As[cur][k][ty + 4];
            *(float4*)&b[0] = *(float4*)&Bs[cur][k][tx];
            *(float4*)&b[4] = *(float4*)&Bs[cur][k][tx + 4];
            #pragma unroll
            for (int i = 0; i < 8; i++)
                #pragma unroll
                for (int j = 0; j < 8; j++) acc[i][j] += a[i] * b[j];
        }
        if (t + 1 < nT) {
            const int nx = cur ^ 1;
            As[nx][aC + 0][aR] = av.x; As[nx][aC + 1][aR] = av.y;
            As[nx][aC + 2][aR] = av.z; As[nx][aC + 3][aR] = av.w;
            *(float4*)&Bs[nx][bR][bC] = bv;
        }
        __syncthreads();
    }

    #pragma unroll
    for (int i = 0; i < 8; i++) {
        float* Cr = C + (size_t)(by * 128 + ty + i) * N + bx * 128 + tx;
        #pragma unroll
        for (int j = 0; j < 8; j++) {
            float bb = bias ? bias[bx * 128 + tx + j] : 0.f;
            Cr[j] = acc[i][j] + bb;
        }
    }
}

// =====================================================================
// pack qkv -> per-head contiguous q (scaled), k, v: [bh][seq][64]
// =====================================================================
__global__ void k_pack() {
    int idx = blockIdx.x * blockDim.x + threadIdx.x;   // BH*SEQ*DH
    int d = idx & 63, i = (idx >> 6) & 8191, bh = idx >> 19;
    int b = bh >> 3, h = bh & 7;
    size_t src = (size_t)(b * SEQ + i) * TRIPLE + h * DH + d;
    g_q[idx] = g_qkv[src] * 0.125f;     // dh^-0.5
    g_k[idx] = g_qkv[src + 512];
    g_v[idx] = g_qkv[src + 1024];
}

// landmarks: mean over 32 consecutive tokens
__global__ void k_land() {
    int idx = blockIdx.x * blockDim.x + threadIdx.x;   // BH*NM*DH
    int d = idx & 63, i = (idx >> 6) & 255, bh = idx >> 14;
    size_t base = (size_t)bh * SEQ * DH + (size_t)i * LG * DH + d;
    float qs = 0.f, ks = 0.f;
    #pragma unroll 8
    for (int j = 0; j < LG; j++) { qs += g_q[base + j * 64]; ks += g_k[base + j * 64]; }
    g_ql[idx] = qs * (1.f / LG);
    g_kl[idx] = ks * (1.f / LG);
}

// =====================================================================
// Batched NT GEMM, K=64 fixed: C[M,N] = A[M,64] @ B[N,64]^T
// lda=ldb=64. 64x64 tile. grid (N/64, M/64, batch)
// =====================================================================
__global__ __launch_bounds__(256)
void k_ntgemm(const float* __restrict__ A, long long sA,
              const float* __restrict__ B, long long sB,
              float* __restrict__ C, int ldc, long long sC) {
    __shared__ float As[64][68];
    __shared__ float Bs[64][68];
    const int tid = threadIdx.x, z = blockIdx.z;
    const float* Ab = A + (size_t)z * sA + (size_t)blockIdx.y * 64 * 64;
    const float* Bb = B + (size_t)z * sB + (size_t)blockIdx.x * 64 * 64;
    const int r = tid & 63, c = (tid >> 6) << 4;
    #pragma unroll
    for (int u = 0; u < 4; u++) {
        float4 t = *(const float4*)(Ab + r * 64 + c + u * 4);
        As[c + u * 4 + 0][r] = t.x; As[c + u * 4 + 1][r] = t.y;
        As[c + u * 4 + 2][r] = t.z; As[c + u * 4 + 3][r] = t.w;
        float4 s = *(const float4*)(Bb + r * 64 + c + u * 4);
        Bs[c + u * 4 + 0][r] = s.x; Bs[c + u * 4 + 1][r] = s.y;
        Bs[c + u * 4 + 2][r] = s.z; Bs[c + u * 4 + 3][r] = s.w;
    }
    __syncthreads();
    float acc[4][4];
    #pragma unroll
    for (int i = 0; i < 4; i++)
        #pragma unroll
        for (int j = 0; j < 4; j++) acc[i][j] = 0.f;
    const int tx = (tid & 15) << 2, ty = (tid >> 4) << 2;
    #pragma unroll 16
    for (int d = 0; d < 64; d++) {
        float4 a = *(float4*)&As[d][ty];
        float4 b = *(float4*)&Bs[d][tx];
        float ar[4] = {a.x, a.y, a.z, a.w};
        float br[4] = {b.x, b.y, b.z, b.w};
        #pragma unroll
        for (int i = 0; i < 4; i++)
            #pragma unroll
            for (int j = 0; j < 4; j++) acc[i][j] += ar[i] * br[j];
    }
    float* Cb = C + (size_t)z * sC;
    #pragma unroll
    for (int i = 0; i < 4; i++)
        #pragma unroll
        for (int j = 0; j < 4; j++)
            Cb[(size_t)(blockIdx.y * 64 + ty + i) * ldc + blockIdx.x * 64 + tx + j] = acc[i][j];
}

// =====================================================================
// Row softmax, COLS = CT*256. One block (256 thr) per row.
// =====================================================================
template<int CT>
__global__ void k_softmax(float* __restrict__ X) {
    const size_t base = (size_t)blockIdx.x * (CT * 256);
    const int tid = threadIdx.x, lane = tid & 31, wp = tid >> 5;
    __shared__ float red[8];
    float v[CT];
    float m = -1e30f;
    #pragma unroll
    for (int t = 0; t < CT; t++) { v[t] = X[base + t * 256 + tid]; m = fmaxf(m, v[t]); }
    #pragma unroll
    for (int off = 16; off; off >>= 1) m = fmaxf(m, __shfl_xor_sync(0xffffffffu, m, off));
    if (!lane) red[wp] = m;
    __syncthreads();
    float M = red[0];
    #pragma unroll
    for (int w = 1; w < 8; w++) M = fmaxf(M, red[w]);
    __syncthreads();
    float s = 0.f;
    #pragma unroll
    for (int t = 0; t < CT; t++) { v[t] = expf(v[t] - M); s += v[t]; }
    #pragma unroll
    for (int off = 16; off; off >>= 1) s += __shfl_xor_sync(0xffffffffu, s, off);
    if (!lane) red[wp] = s;
    __syncthreads();
    float S = 0.f;
    #pragma unroll
    for (int w = 0; w < 8; w++) S += red[w];
    float inv = 1.f / S;
    #pragma unroll
    for (int t = 0; t < CT; t++) X[base + t * 256 + tid] = v[t] * inv;
}

// global max of row-sums (axis -1) and col-sums (axis -2) over ALL bh
__global__ void k_reset() { if (threadIdx.x < 2) g_mx[threadIdx.x] = 0u; }

__global__ void k_colrowmax() {
    const int bh = blockIdx.x, tid = threadIdx.x, lane = tid & 31, wp = tid >> 5;
    __shared__ float red[8];
    const float* Xb = g_X + (size_t)bh * NM * NM;
    float cs = 0.f;
    for (int i = 0; i < NM; i++) cs += Xb[i * NM + tid];
    float m = cs;
    #pragma unroll
    for (int off = 16; off; off >>= 1) m = fmaxf(m, __shfl_xor_sync(0xffffffffu, m, off));
    if (!lane) red[wp] = m;
    __syncthreads();
    if (tid == 0) {
        float M = red[0];
        #pragma unroll
        for (int w = 1; w < 8; w++) M = fmaxf(M, red[w]);
        atomicMax(&g_mx[1], __float_as_uint(M));
    }
    __syncthreads();
    float rs = 0.f;
    const float* Xr = Xb + (size_t)tid * NM;
    for (int j = 0; j < NM; j++) rs += Xr[j];
    m = rs;
    #pragma unroll
    for (int off = 16; off; off >>= 1) m = fmaxf(m, __shfl_xor_sync(0xffffffffu, m, off));
    if (!lane) red[wp] = m;
    __syncthreads();
    if (tid == 0) {
        float M = red[0];
        #pragma unroll
        for (int w = 1; w < 8; w++) M = fmaxf(M, red[w]);
        atomicMax(&g_mx[0], __float_as_uint(M));
    }
}

__global__ void k_zinit() {
    int idx = blockIdx.x * blockDim.x + threadIdx.x;   // BH*NM*NM
    float inv = 1.f / (__uint_as_float(g_mx[0]) * __uint_as_float(g_mx[1]));
    int j = idx & 255, i = (idx >> 8) & 255, bh = idx >> 16;
    g_Za[idx] = g_X[(size_t)bh * NM * NM + j * NM + i] * inv;
}

// =====================================================================
// Batched NN GEMM: C = alpha*(A@B) + beta*D. 64x64 tile, BK=16.
// A[M,K] lda, B[K,N] ldb, C/D ldc. Optional K-split: z = bh*ksplit + s,
// each split handles K elems starting at s*K; C indexed by z.
// =====================================================================
__global__ __launch_bounds__(256)
void k_bgemm(const float* __restrict__ A, int lda, long long sA,
             const float* __restrict__ B, int ldb, long long sB,
             const float* __restrict__ D, long long sD,
             float* __restrict__ C, int ldc, long long sC,
             int K, float alpha, float beta, int ksplit) {
    __shared__ float As[64][17];
    __shared__ float Bs[16][64];
    const int tid = threadIdx.x, z = blockIdx.z;
    const int bh = z / ksplit, s = z - bh * ksplit;
    const float* Ab = A + (size_t)bh * sA + (size_t)blockIdx.y * 64 * lda + (size_t)s * K;
    const float* Bb = B + (size_t)bh * sB + (size_t)s * K * ldb + blockIdx.x * 64;
    const float* Db = D ? (D + (size_t)bh * sD) : (const float*)0;
    float* Cb = C + (size_t)z * sC;
    const int am = tid >> 2, ak = (tid & 3) << 2;
    const int bk = tid >> 4, bn = (tid & 15) << 2;
    const int tx = (tid & 15) << 2, ty = (tid >> 4) << 2;
    float acc[4][4];
    #pragma unroll
    for (int i = 0; i < 4; i++)
        #pragma unroll
        for (int j = 0; j < 4; j++) acc[i][j] = 0.f;

    for (int kb = 0; kb < K; kb += 16) {
        float4 a4 = *(const float4*)(Ab + (size_t)am * lda + kb + ak);
        As[am][ak + 0] = a4.x; As[am][ak + 1] = a4.y;
        As[am][ak + 2] = a4.z; As[am][ak + 3] = a4.w;
        *(float4*)&Bs[bk][bn] = *(const float4*)(Bb + (size_t)(kb + bk) * ldb + bn);
        __syncthreads();
        #pragma unroll
        for (int k = 0; k < 16; k++) {
            float4 b4 = *(float4*)&Bs[k][tx];
            float br[4] = {b4.x, b4.y, b4.z, b4.w};
            float ar[4];
            #pragma unroll
            for (int i = 0; i < 4; i++) ar[i] = As[ty + i][k];
            #pragma unroll
            for (int i = 0; i < 4; i++)
                #pragma unroll
                for (int j = 0; j < 4; j++) acc[i][j] += ar[i] * br[j];
        }
        __syncthreads();
    }
    #pragma unroll
    for (int i = 0; i < 4; i++) {
        int row = blockIdx.y * 64 + ty + i;
        #pragma unroll
        for (int j = 0; j < 4; j++) {
            int col = blockIdx.x * 64 + tx + j;
            float dv = Db ? Db[(size_t)row * ldc + col] : 0.f;
            Cb[(size_t)row * ldc + col] = alpha * acc[i][j] + beta * dv;
        }
    }
}

__global__ void k_combine() {
    int idx = blockIdx.x * blockDim.x + threadIdx.x;   // BH*NM*DH
    int bh = idx >> 14, r = idx & 16383;
    float s = 0.f;
    #pragma unroll
    for (int p = 0; p < 8; p++) s += g_C2p[(size_t)(bh * 8 + p) * 16384 + r];
    g_C2[idx] = s;
}

// =====================================================================
// epilogue: O1 + depthwise conv(v, 33) over seq, transposed into Y[b*n][h*64+d]
// grid: (SEQ/128, BH), block 256
// =====================================================================
__global__ __launch_bounds__(256)
void k_post(const float* __restrict__ wres) {
    __shared__ float vs[160][64];
    __shared__ float w[33];
    const int bh = blockIdx.y, b = bh >> 3, h = bh & 7;
    const int i0 = blockIdx.x * 128;
    const int tid = threadIdx.x;
    if (tid < 33) w[tid] = wres[h * 33 + tid];
    const float* vb = g_v + (size_t)bh * SEQ * DH;
    for (int p = tid; p < 2560; p += 256) {            // 160 rows x 16 float4
        int row = p >> 4, q4 = (p & 15) << 2;
        int gi = i0 - 16 + row;
        float4 t = (gi >= 0 && gi < SEQ) ? *(const float4*)(vb + (size_t)gi * 64 + q4)
                                         : make_float4(0.f, 0.f, 0.f, 0.f);
        *(float4*)&vs[row][q4] = t;
    }
    __syncthreads();
    const int d = tid & 63, rg = tid >> 6;
    const float* o1 = g_O1 + (size_t)bh * SEQ * DH;
    for (int l = rg; l < 128; l += 4) {
        float acc = 0.f;
        #pragma unroll
        for (int t = 0; t < 33; t++) acc += w[t] * vs[l + t][d];
        int i = i0 + l;
        g_Y[(size_t)(b * SEQ + i) * DM + h * DH + d] = o1[(size_t)i * DH + d] + acc;
    }
}

// =====================================================================
extern "C" void kernel_launch(void* const* d_in, const int* in_sizes, int n_in,
                              void* d_out, int out_size) {
    const float* x     = (const float*)d_in[0];
    const float* w_qkv = (const float*)d_in[1];
    const float* w_out = (const float*)d_in[2];
    const float* b_out = (const float*)d_in[3];
    const float* w_res = (const float*)d_in[4];
    float* out = (float*)d_out;

    float *qkv, *q, *k_, *v, *ql, *kl, *X, *Za, *Zb, *XZ, *T1, *T2, *S, *C2p, *C2, *Cm, *O1, *Y;
    cudaGetSymbolAddress((void**)&qkv, g_qkv);
    cudaGetSymbolAddress((void**)&q,   g_q);
    cudaGetSymbolAddress((void**)&k_,  g_k);
    cudaGetSymbolAddress((void**)&v,   g_v);
    cudaGetSymbolAddress((void**)&ql,  g_ql);
    cudaGetSymbolAddress((void**)&kl,  g_kl);
    cudaGetSymbolAddress((void**)&X,   g_X);
    cudaGetSymbolAddress((void**)&Za,  g_Za);
    cudaGetSymbolAddress((void**)&Zb,  g_Zb);
    cudaGetSymbolAddress((void**)&XZ,  g_XZ);
    cudaGetSymbolAddress((void**)&T1,  g_T1);
    cudaGetSymbolAddress((void**)&T2,  g_T2);
    cudaGetSymbolAddress((void**)&S,   g_S);
    cudaGetSymbolAddress((void**)&C2p, g_C2p);
    cudaGetSymbolAddress((void**)&C2,  g_C2);
    cudaGetSymbolAddress((void**)&Cm,  g_Cm);
    cudaGetSymbolAddress((void**)&O1,  g_O1);
    cudaGetSymbolAddress((void**)&Y,   g_Y);

    // 1. qkv = x @ w_qkv
    k_sgemm<<<dim3(TRIPLE / 128, ROWS / 128), 256>>>(x, w_qkv, (const float*)0, qkv,
                                                     ROWS, TRIPLE, DM);
    // 2. pack (q pre-scaled)
    k_pack<<<(BH * SEQ * DH) / 256, 256>>>();
    // 3. landmarks
    k_land<<<(BH * NM * DH) / 256, 256>>>();
    // 4. attn2 = softmax(q_land @ k_land^T)
    k_ntgemm<<<dim3(4, 4, BH), 256>>>(ql, 16384LL, kl, 16384LL, X, NM, 65536LL);
    k_softmax<1><<<BH * NM, 256>>>(X);
    // 5. pinv init
    k_reset<<<1, 32>>>();
    k_colrowmax<<<BH, 256>>>();
    k_zinit<<<(BH * NM * NM) / 256, 256>>>();
    // 6. 6 Newton iterations: 4 bgemms each (K=256)
    float* Zc = Za; float* Zn = Zb;
    for (int it = 0; it < 6; it++) {
        k_bgemm<<<dim3(4, 4, BH), 256>>>(X, NM, 65536LL, Zc, NM, 65536LL,
                                         (const float*)0, 0LL, XZ, NM, 65536LL,
                                         NM, 1.f, 0.f, 1);
        k_bgemm<<<dim3(4, 4, BH), 256>>>(XZ, NM, 65536LL, XZ, NM, 65536LL,
                                         XZ, 65536LL, T1, NM, 65536LL,
                                         NM, -1.f, 7.f, 1);
        k_bgemm<<<dim3(4, 4, BH), 256>>>(XZ, NM, 65536LL, T1, NM, 65536LL,
                                         XZ, 65536LL, T2, NM, 65536LL,
                                         NM, -1.f, 15.f, 1);
        k_bgemm<<<dim3(4, 4, BH), 256>>>(Zc, NM, 65536LL, T2, NM, 65536LL,
                                         Zc, 65536LL, Zn, NM, 65536LL,
                                         NM, -0.25f, 3.25f, 1);
        float* tmp = Zc; Zc = Zn; Zn = tmp;
    }
    // 7. attn3 = softmax(q_land @ k^T)  [bh][256][8192]
    k_ntgemm<<<dim3(128, 4, BH), 256>>>(ql, 16384LL, k_, 524288LL, S, SEQ, 2097152LL);
    k_softmax<32><<<BH * NM, 256>>>(S);
    // 8. C2 = attn3 @ v  (split-K 8)
    k_bgemm<<<dim3(1, 4, BH * 8), 256>>>(S, SEQ, 2097152LL, v, DH, 524288LL,
                                         (const float*)0, 0LL, C2p, DH, 16384LL,
                                         1024, 1.f, 0.f, 8);
    k_combine<<<(BH * NM * DH) / 256, 256>>>();
    // 9. Cm = Z @ C2
    k_bgemm<<<dim3(1, 4, BH), 256>>>(Zc, NM, 65536LL, C2, DH, 16384LL,
                                     (const float*)0, 0LL, Cm, DH, 16384LL,
                                     NM, 1.f, 0.f, 1);
    // 10. attn1 = softmax(q @ k_land^T)  [bh][8192][256]
    k_ntgemm<<<dim3(4, 128, BH), 256>>>(q, 524288LL, kl, 16384LL, S, NM, 2097152LL);
    k_softmax<1><<<BH * SEQ, 256>>>(S);
    // 11. O1 = attn1 @ Cm
    k_bgemm<<<dim3(1, 128, BH), 256>>>(S, NM, 2097152LL, Cm, DH, 16384LL,
                                       (const float*)0, 0LL, O1, DH, 524288LL,
                                       NM, 1.f, 0.f, 1);
    // 12. conv residual + transpose -> Y
    k_post<<<dim3(SEQ / 128, BH), 256>>>(w_res);
    // 13. out = Y @ w_out + b_out
    k_sgemm<<<dim3(DM / 128, ROWS / 128), 256>>>(Y, w_out, b_out, out, ROWS, DM, DM);
}

// round 5
// speedup vs baseline: 1.4303x; 1.4303x over previous
#include <cuda_runtime.h>
#include <cuda_bf16.h>
#include <math.h>

#define NB      4
#define SEQ     8192
#define DM      512
#define NH      8
#define DH      64
#define NM      256
#define LG      32
#define BH      32          // NB*NH
#define TRIPLE  1536
#define ROWS    32768       // NB*SEQ

// ---------------- scratch (device globals; no allocations allowed) -------
__device__ float g_q [(size_t)BH * SEQ * DH];         // packed, pre-scaled by dh^-0.5
__device__ float g_k [(size_t)BH * SEQ * DH];
__device__ float g_v [(size_t)BH * SEQ * DH];
__device__ float g_ql[BH * NM * DH];
__device__ float g_kl[BH * NM * DH];
__device__ float g_X [BH * NM * NM];                  // attn2
__device__ float g_Za[BH * NM * NM];
__device__ float g_Zb[BH * NM * NM];
__device__ float g_XZ[BH * NM * NM];
__device__ float g_T1[BH * NM * NM];
__device__ float g_T2[BH * NM * NM];
__device__ float g_S [(size_t)BH * NM * SEQ];         // sim3 then sim1 (268 MB)
__device__ float g_C2p[8 * BH * NM * DH];             // split-K partials
__device__ float g_C2[BH * NM * DH];
__device__ float g_Cm[BH * NM * DH];                  // Z @ C2
__device__ float g_O1[(size_t)BH * SEQ * DH];         // attn1 @ Cm
__device__ float g_Y [(size_t)ROWS * DM];             // pre-out-proj
__device__ unsigned int g_mx[2];

// ---------------- tf32 helpers ----------------
__device__ __forceinline__ float to_tf32(float x) {
    unsigned u; asm("cvt.rna.tf32.f32 %0, %1;" : "=r"(u) : "f"(x));
    return __uint_as_float(u);
}
__device__ __forceinline__ void mma8(float4& d, float a0, float a1, float a2, float a3,
                                     float b0, float b1) {
    asm volatile(
        "mma.sync.aligned.m16n8k8.row.col.f32.tf32.tf32.f32 "
        "{%0,%1,%2,%3}, {%4,%5,%6,%7}, {%8,%9}, {%0,%1,%2,%3};"
        : "+f"(d.x), "+f"(d.y), "+f"(d.z), "+f"(d.w)
        : "r"(__float_as_uint(a0)), "r"(__float_as_uint(a1)),
          "r"(__float_as_uint(a2)), "r"(__float_as_uint(a3)),
          "r"(__float_as_uint(b0)), "r"(__float_as_uint(b1)));
}

// =====================================================================
// TF32 tensor-core GEMM. BM=128 fixed, BN in {128,64}. BK=16, double buffer.
// C = alpha*(A@B[^T]) + beta*D (+bias).  Batched (z) with optional K-split.
// EPI==1: qkv scatter epilogue into g_q/g_k/g_v (q scaled by 0.125).
// smem layout: As[stage][kk][g=row%8][(row/8) ^ ((kk&3)*4)]  (16-wide, XOR swz)
//              Bs[stage][kk][g=col%8][(col/8) ^ ((kk&3)*4)]
// Warp tile 32x64: 2 m16 tiles x 8 n8 tiles. WARPS_M=4 fixed.
// =====================================================================
template<int BN, int WARPS_N, bool TRANSB, int EPI>
__global__ __launch_bounds__(128 * WARPS_N)
void t_gemm(const float* __restrict__ A, int lda, long long sA,
            const float* __restrict__ B, int ldb, long long sB,
            const float* __restrict__ D, long long sD,
            const float* __restrict__ bias,
            float* __restrict__ C, int ldc, long long sC,
            int K, float alpha, float beta, int ksplit,
            float* __restrict__ qp, float* __restrict__ kp, float* __restrict__ vp)
{
    constexpr int NT = 128 * WARPS_N;
    constexpr int CA = 512 / NT;             // A float4 per thread per stage
    constexpr int CB = (16 * BN / 4) / NT;   // B float4 per thread per stage
    __shared__ __align__(16) float As[2][16][8][16];
    __shared__ __align__(16) float Bs[2][16][8][16];

    const int tid = threadIdx.x;
    const int z = blockIdx.z;
    const int bh = z / ksplit, sk = z - bh * ksplit;
    const float* Ab = A + (size_t)bh * sA + (size_t)blockIdx.y * 128 * lda + (size_t)sk * K;
    const float* Bb;
    if (TRANSB) Bb = B + (size_t)bh * sB + (size_t)blockIdx.x * BN * ldb + (size_t)sk * K;
    else        Bb = B + (size_t)bh * sB + (size_t)sk * K * ldb + blockIdx.x * BN;

    const int lane = tid & 31, g = lane >> 2, tg = lane & 3;
    const int wid = tid >> 5, wm = wid & 3, wn = wid >> 2;
    const int sw = tg << 2;

    float4 rA[CA], rB[CB];

    auto g2r = [&](int kb) {
        #pragma unroll
        for (int i = 0; i < CA; i++) {
            int t4 = tid + i * NT;
            int row = t4 >> 2, kq = (t4 & 3) << 2;
            rA[i] = *(const float4*)(Ab + (size_t)row * lda + kb * 16 + kq);
        }
        #pragma unroll
        for (int i = 0; i < CB; i++) {
            int t4 = tid + i * NT;
            if constexpr (TRANSB) {
                int row = t4 >> 2, kq = (t4 & 3) << 2;
                rB[i] = *(const float4*)(Bb + (size_t)row * ldb + kb * 16 + kq);
            } else {
                constexpr int B4 = BN / 4;
                int row = t4 / B4, cq = (t4 % B4) << 2;
                rB[i] = *(const float4*)(Bb + (size_t)(kb * 16 + row) * ldb + cq);
            }
        }
    };
    auto r2s = [&](int st) {
        #pragma unroll
        for (int i = 0; i < CA; i++) {
            int t4 = tid + i * NT;
            int row = t4 >> 2, kq = (t4 & 3) << 2;
            float v[4] = {rA[i].x, rA[i].y, rA[i].z, rA[i].w};
            #pragma unroll
            for (int j = 0; j < 4; j++) {
                int kk = kq + j;
                As[st][kk][row & 7][(row >> 3) ^ ((kk & 3) << 2)] = to_tf32(v[j]);
            }
        }
        #pragma unroll
        for (int i = 0; i < CB; i++) {
            int t4 = tid + i * NT;
            float v[4] = {rB[i].x, rB[i].y, rB[i].z, rB[i].w};
            if constexpr (TRANSB) {
                int row = t4 >> 2, kq = (t4 & 3) << 2;
                #pragma unroll
                for (int j = 0; j < 4; j++) {
                    int kk = kq + j;
                    Bs[st][kk][row & 7][(row >> 3) ^ ((kk & 3) << 2)] = to_tf32(v[j]);
                }
            } else {
                constexpr int B4 = BN / 4;
                int row = t4 / B4, cq = (t4 % B4) << 2;
                #pragma unroll
                for (int j = 0; j < 4; j++) {
                    int col = cq + j;
                    Bs[st][row][col & 7][(col >> 3) ^ ((row & 3) << 2)] = to_tf32(v[j]);
                }
            }
        }
    };

    float4 acc[2][8];
    #pragma unroll
    for (int i = 0; i < 2; i++)
        #pragma unroll
        for (int j = 0; j < 8; j++) acc[i][j] = make_float4(0.f, 0.f, 0.f, 0.f);

    const int kblocks = K >> 4;
    g2r(0); r2s(0); __syncthreads();
    for (int kb = 0; kb < kblocks; kb++) {
        const int cur = kb & 1;
        if (kb + 1 < kblocks) g2r(kb + 1);
        #pragma unroll
        for (int s8 = 0; s8 < 16; s8 += 8) {
            const int k0 = s8 + tg;
            float4 aLo = *(const float4*)&As[cur][k0    ][g][(wm * 4) ^ sw];
            float4 aHi = *(const float4*)&As[cur][k0 + 4][g][(wm * 4) ^ sw];
            float4 b0l = *(const float4*)&Bs[cur][k0    ][g][(wn * 8) ^ sw];
            float4 b0h = *(const float4*)&Bs[cur][k0    ][g][(wn * 8 + 4) ^ sw];
            float4 b1l = *(const float4*)&Bs[cur][k0 + 4][g][(wn * 8) ^ sw];
            float4 b1h = *(const float4*)&Bs[cur][k0 + 4][g][(wn * 8 + 4) ^ sw];
            float bb0[8] = {b0l.x, b0l.y, b0l.z, b0l.w, b0h.x, b0h.y, b0h.z, b0h.w};
            float bb1[8] = {b1l.x, b1l.y, b1l.z, b1l.w, b1h.x, b1h.y, b1h.z, b1h.w};
            float am[2][4] = {{aLo.x, aLo.y, aHi.x, aHi.y}, {aLo.z, aLo.w, aHi.z, aHi.w}};
            #pragma unroll
            for (int mt = 0; mt < 2; mt++)
                #pragma unroll
                for (int nt = 0; nt < 8; nt++)
                    mma8(acc[mt][nt], am[mt][0], am[mt][1], am[mt][2], am[mt][3],
                         bb0[nt], bb1[nt]);
        }
        if (kb + 1 < kblocks) { r2s(cur ^ 1); __syncthreads(); }
    }

    // epilogue
    const int r00 = blockIdx.y * 128 + wm * 32;
    #pragma unroll
    for (int mt = 0; mt < 2; mt++) {
        #pragma unroll
        for (int nt = 0; nt < 8; nt++) {
            const int r0 = r00 + mt * 16 + g;
            const int cb = blockIdx.x * BN + wn * 64 + nt * 8 + tg * 2;
            float4 v = acc[mt][nt];
            if constexpr (EPI == 1) {
                const int which = cb >> 9, rem = cb & 511;
                const int h = rem >> 6, d = rem & 63;
                const float s = (which == 0) ? 0.125f : 1.0f;
                float* dst = (which == 0) ? qp : ((which == 1) ? kp : vp);
                int b = r0 >> 13, ii = r0 & 8191;
                float2 lo; lo.x = v.x * s; lo.y = v.y * s;
                *(float2*)&dst[(((size_t)(b * 8 + h) * 8192 + ii) << 6) + d] = lo;
                const int r1 = r0 + 8; b = r1 >> 13; ii = r1 & 8191;
                float2 hi; hi.x = v.z * s; hi.y = v.w * s;
                *(float2*)&dst[(((size_t)(b * 8 + h) * 8192 + ii) << 6) + d] = hi;
            } else {
                float* Cb = C + (size_t)z * sC;
                const float* Db = D + (size_t)bh * sD;
                float2 lo, hi;
                lo.x = alpha * v.x; lo.y = alpha * v.y;
                hi.x = alpha * v.z; hi.y = alpha * v.w;
                if (beta != 0.f) {
                    float2 dlo = *(const float2*)&Db[(size_t)r0 * ldc + cb];
                    float2 dhi = *(const float2*)&Db[(size_t)(r0 + 8) * ldc + cb];
                    lo.x += beta * dlo.x; lo.y += beta * dlo.y;
                    hi.x += beta * dhi.x; hi.y += beta * dhi.y;
                }
                if (bias) {
                    float2 bv = *(const float2*)&bias[cb];
                    lo.x += bv.x; lo.y += bv.y; hi.x += bv.x; hi.y += bv.y;
                }
                *(float2*)&Cb[(size_t)r0 * ldc + cb] = lo;
                *(float2*)&Cb[(size_t)(r0 + 8) * ldc + cb] = hi;
            }
        }
    }
}

// landmarks: mean over 32 consecutive tokens
__global__ void k_land() {
    int idx = blockIdx.x * blockDim.x + threadIdx.x;   // BH*NM*DH
    int d = idx & 63, i = (idx >> 6) & 255, bh = idx >> 14;
    size_t base = (size_t)bh * SEQ * DH + (size_t)i * LG * DH + d;
    float qs = 0.f, ks = 0.f;
    #pragma unroll 8
    for (int j = 0; j < LG; j++) { qs += g_q[base + j * 64]; ks += g_k[base + j * 64]; }
    g_ql[idx] = qs * (1.f / LG);
    g_kl[idx] = ks * (1.f / LG);
}

// =====================================================================
// Row softmax, COLS = CT*256. One block (256 thr) per row.
// =====================================================================
template<int CT>
__global__ void k_softmax(float* __restrict__ X) {
    const size_t base = (size_t)blockIdx.x * (CT * 256);
    const int tid = threadIdx.x, lane = tid & 31, wp = tid >> 5;
    __shared__ float red[8];
    float v[CT];
    float m = -1e30f;
    #pragma unroll
    for (int t = 0; t < CT; t++) { v[t] = X[base + t * 256 + tid]; m = fmaxf(m, v[t]); }
    #pragma unroll
    for (int off = 16; off; off >>= 1) m = fmaxf(m, __shfl_xor_sync(0xffffffffu, m, off));
    if (!lane) red[wp] = m;
    __syncthreads();
    float M = red[0];
    #pragma unroll
    for (int w = 1; w < 8; w++) M = fmaxf(M, red[w]);
    __syncthreads();
    float s = 0.f;
    #pragma unroll
    for (int t = 0; t < CT; t++) { v[t] = expf(v[t] - M); s += v[t]; }
    #pragma unroll
    for (int off = 16; off; off >>= 1) s += __shfl_xor_sync(0xffffffffu, s, off);
    if (!lane) red[wp] = s;
    __syncthreads();
    float S = 0.f;
    #pragma unroll
    for (int w = 0; w < 8; w++) S += red[w];
    float inv = 1.f / S;
    #pragma unroll
    for (int t = 0; t < CT; t++) X[base + t * 256 + tid] = v[t] * inv;
}

// global max of row-sums (axis -1) and col-sums (axis -2) over ALL bh
__global__ void k_reset() { if (threadIdx.x < 2) g_mx[threadIdx.x] = 0u; }

__global__ void k_colrowmax() {
    const int bh = blockIdx.x, tid = threadIdx.x, lane = tid & 31, wp = tid >> 5;
    __shared__ float red[8];
    const float* Xb = g_X + (size_t)bh * NM * NM;
    float cs = 0.f;
    for (int i = 0; i < NM; i++) cs += Xb[i * NM + tid];
    float m = cs;
    #pragma unroll
    for (int off = 16; off; off >>= 1) m = fmaxf(m, __shfl_xor_sync(0xffffffffu, m, off));
    if (!lane) red[wp] = m;
    __syncthreads();
    if (tid == 0) {
        float M = red[0];
        #pragma unroll
        for (int w = 1; w < 8; w++) M = fmaxf(M, red[w]);
        atomicMax(&g_mx[1], __float_as_uint(M));
    }
    __syncthreads();
    float rs = 0.f;
    const float* Xr = Xb + (size_t)tid * NM;
    for (int j = 0; j < NM; j++) rs += Xr[j];
    m = rs;
    #pragma unroll
    for (int off = 16; off; off >>= 1) m = fmaxf(m, __shfl_xor_sync(0xffffffffu, m, off));
    if (!lane) red[wp] = m;
    __syncthreads();
    if (tid == 0) {
        float M = red[0];
        #pragma unroll
        for (int w = 1; w < 8; w++) M = fmaxf(M, red[w]);
        atomicMax(&g_mx[0], __float_as_uint(M));
    }
}

__global__ void k_zinit() {
    int idx = blockIdx.x * blockDim.x + threadIdx.x;   // BH*NM*NM
    float inv = 1.f / (__uint_as_float(g_mx[0]) * __uint_as_float(g_mx[1]));
    int j = idx & 255, i = (idx >> 8) & 255, bh = idx >> 16;
    g_Za[idx] = g_X[(size_t)bh * NM * NM + j * NM + i] * inv;
}

__global__ void k_combine() {
    int idx = blockIdx.x * blockDim.x + threadIdx.x;   // BH*NM*DH
    int bh = idx >> 14, r = idx & 16383;
    float s = 0.f;
    #pragma unroll
    for (int p = 0; p < 8; p++) s += g_C2p[(size_t)(bh * 8 + p) * 16384 + r];
    g_C2[idx] = s;
}

// =====================================================================
// epilogue: O1 + depthwise conv(v, 33) over seq, transposed into Y[b*n][h*64+d]
// =====================================================================
__global__ __launch_bounds__(256)
void k_post(const float* __restrict__ wres) {
    __shared__ float vs[160][64];
    __shared__ float w[33];
    const int bh = blockIdx.y, b = bh >> 3, h = bh & 7;
    const int i0 = blockIdx.x * 128;
    const int tid = threadIdx.x;
    if (tid < 33) w[tid] = wres[h * 33 + tid];
    const float* vb = g_v + (size_t)bh * SEQ * DH;
    for (int p = tid; p < 2560; p += 256) {
        int row = p >> 4, q4 = (p & 15) << 2;
        int gi = i0 - 16 + row;
        float4 t = (gi >= 0 && gi < SEQ) ? *(const float4*)(vb + (size_t)gi * 64 + q4)
                                         : make_float4(0.f, 0.f, 0.f, 0.f);
        *(float4*)&vs[row][q4] = t;
    }
    __syncthreads();
    const int d = tid & 63, rg = tid >> 6;
    const float* o1 = g_O1 + (size_t)bh * SEQ * DH;
    for (int l = rg; l < 128; l += 4) {
        float acc = 0.f;
        #pragma unroll
        for (int t = 0; t < 33; t++) acc += w[t] * vs[l + t][d];
        int i = i0 + l;
        g_Y[(size_t)(b * SEQ + i) * DM + h * DH + d] = o1[(size_t)i * DH + d] + acc;
    }
}

// =====================================================================
extern "C" void kernel_launch(void* const* d_in, const int* in_sizes, int n_in,
                              void* d_out, int out_size) {
    const float* x     = (const float*)d_in[0];
    const float* w_qkv = (const float*)d_in[1];
    const float* w_out = (const float*)d_in[2];
    const float* b_out = (const float*)d_in[3];
    const float* w_res = (const float*)d_in[4];
    float* out = (float*)d_out;

    float *q, *k_, *v, *ql, *kl, *X, *Za, *Zb, *XZ, *T1, *T2, *S, *C2p, *C2, *Cm, *O1, *Y;
    cudaGetSymbolAddress((void**)&q,   g_q);
    cudaGetSymbolAddress((void**)&k_,  g_k);
    cudaGetSymbolAddress((void**)&v,   g_v);
    cudaGetSymbolAddress((void**)&ql,  g_ql);
    cudaGetSymbolAddress((void**)&kl,  g_kl);
    cudaGetSymbolAddress((void**)&X,   g_X);
    cudaGetSymbolAddress((void**)&Za,  g_Za);
    cudaGetSymbolAddress((void**)&Zb,  g_Zb);
    cudaGetSymbolAddress((void**)&XZ,  g_XZ);
    cudaGetSymbolAddress((void**)&T1,  g_T1);
    cudaGetSymbolAddress((void**)&T2,  g_T2);
    cudaGetSymbolAddress((void**)&S,   g_S);
    cudaGetSymbolAddress((void**)&C2p, g_C2p);
    cudaGetSymbolAddress((void**)&C2,  g_C2);
    cudaGetSymbolAddress((void**)&Cm,  g_Cm);
    cudaGetSymbolAddress((void**)&O1,  g_O1);
    cudaGetSymbolAddress((void**)&Y,   g_Y);

    const float* NUL = (const float*)0;

    // 1. qkv = x @ w_qkv, scattered directly to packed q (scaled), k, v
    t_gemm<128, 2, false, 1><<<dim3(TRIPLE / 128, ROWS / 128, 1), 256>>>(
        x, DM, 0LL, w_qkv, TRIPLE, 0LL, NUL, 0LL, NUL, q, TRIPLE, 0LL,
        DM, 1.f, 0.f, 1, q, k_, v);
    // 2. landmarks
    k_land<<<(BH * NM * DH) / 256, 256>>>();
    // 3. attn2 = softmax(q_land @ k_land^T)
    t_gemm<128, 2, true, 0><<<dim3(2, 2, BH), 256>>>(
        ql, DH, 16384LL, kl, DH, 16384LL, NUL, 0LL, NUL, X, NM, 65536LL,
        DH, 1.f, 0.f, 1, (float*)0, (float*)0, (float*)0);
    k_softmax<1><<<BH * NM, 256>>>(X);
    // 4. pinv init
    k_reset<<<1, 32>>>();
    k_colrowmax<<<BH, 256>>>();
    k_zinit<<<(BH * NM * NM) / 256, 256>>>();
    // 5. 6 Newton iterations
    float* Zc = Za; float* Zn = Zb;
    for (int it = 0; it < 6; it++) {
        t_gemm<128, 2, false, 0><<<dim3(2, 2, BH), 256>>>(
            X, NM, 65536LL, Zc, NM, 65536LL, NUL, 0LL, NUL, XZ, NM, 65536LL,
            NM, 1.f, 0.f, 1, (float*)0, (float*)0, (float*)0);
        t_gemm<128, 2, false, 0><<<dim3(2, 2, BH), 256>>>(
            XZ, NM, 65536LL, XZ, NM, 65536LL, XZ, 65536LL, NUL, T1, NM, 65536LL,
            NM, -1.f, 7.f, 1, (float*)0, (float*)0, (float*)0);
        t_gemm<128, 2, false, 0><<<dim3(2, 2, BH), 256>>>(
            XZ, NM, 65536LL, T1, NM, 65536LL, XZ, 65536LL, NUL, T2, NM, 65536LL,
            NM, -1.f, 15.f, 1, (float*)0, (float*)0, (float*)0);
        t_gemm<128, 2, false, 0><<<dim3(2, 2, BH), 256>>>(
            Zc, NM, 65536LL, T2, NM, 65536LL, Zc, 65536LL, NUL, Zn, NM, 65536LL,
            NM, -0.25f, 3.25f, 1, (float*)0, (float*)0, (float*)0);
        float* tmp = Zc; Zc = Zn; Zn = tmp;
    }
    // 6. sim3 = q_land @ k^T -> softmax
    t_gemm<128, 2, true, 0><<<dim3(SEQ / 128, 2, BH), 256>>>(
        ql, DH, 16384LL, k_, DH, 524288LL, NUL, 0LL, NUL, S, SEQ, 2097152LL,
        DH, 1.f, 0.f, 1, (float*)0, (float*)0, (float*)0);
    k_softmax<32><<<BH * NM, 256>>>(S);
    // 7. C2 = attn3 @ v  (split-K 8)
    t_gemm<64, 1, false, 0><<<dim3(1, 2, BH * 8), 128>>>(
        S, SEQ, 2097152LL, v, DH, 524288LL, NUL, 0LL, NUL, C2p, DH, 16384LL,
        1024, 1.f, 0.f, 8, (float*)0, (float*)0, (float*)0);
    k_combine<<<(BH * NM * DH) / 256, 256>>>();
    // 8. Cm = Z @ C2
    t_gemm<64, 1, false, 0><<<dim3(1, 2, BH), 128>>>(
        Zc, NM, 65536LL, C2, DH, 16384LL, NUL, 0LL, NUL, Cm, DH, 16384LL,
        NM, 1.f, 0.f, 1, (float*)0, (float*)0, (float*)0);
    // 9. sim1 = q @ k_land^T -> softmax
    t_gemm<128, 2, true, 0><<<dim3(2, SEQ / 128, BH), 256>>>(
        q, DH, 524288LL, kl, DH, 16384LL, NUL, 0LL, NUL, S, NM, 2097152LL,
        DH, 1.f, 0.f, 1, (float*)0, (float*)0, (float*)0);
    k_softmax<1><<<BH * SEQ, 256>>>(S);
    // 10. O1 = attn1 @ Cm
    t_gemm<64, 1, false, 0><<<dim3(1, SEQ / 128, BH), 128>>>(
        S, NM, 2097152LL, Cm, DH, 16384LL, NUL, 0LL, NUL, O1, DH, 524288LL,
        NM, 1.f, 0.f, 1, (float*)0, (float*)0, (float*)0);
    // 11. conv residual + transpose -> Y
    k_post<<<dim3(SEQ / 128, BH), 256>>>(w_res);
    // 12. out = Y @ w_out + b_out
    t_gemm<128, 2, false, 0><<<dim3(DM / 128, ROWS / 128, 1), 256>>>(
        Y, DM, 0LL, w_out, DM, 0LL, NUL, 0LL, b_out, out, DM, 0LL,
        DM, 1.f, 0.f, 1, (float*)0, (float*)0, (float*)0);
}

// round 6
// speedup vs baseline: 1.5385x; 1.0757x over previous
#include <cuda_runtime.h>
#include <cuda_bf16.h>
#include <math.h>

#define NB      4
#define SEQ     8192
#define DM      512
#define NH      8
#define DH      64
#define NM      256
#define LG      32
#define BH      32          // NB*NH
#define TRIPLE  1536
#define ROWS    32768       // NB*SEQ

// ---------------- scratch (device globals; no allocations allowed) -------
__device__ float g_q [(size_t)BH * SEQ * DH];         // packed, pre-scaled by dh^-0.5
__device__ float g_k [(size_t)BH * SEQ * DH];
__device__ float g_v [(size_t)BH * SEQ * DH];
__device__ float g_ql[BH * NM * DH];
__device__ float g_kl[BH * NM * DH];
__device__ float g_X [BH * NM * NM];                  // attn2
__device__ float g_Za[BH * NM * NM];
__device__ float g_Zb[BH * NM * NM];
__device__ float g_XZ[BH * NM * NM];
__device__ float g_T1[BH * NM * NM];
__device__ float g_T2[BH * NM * NM];
__device__ float g_S [(size_t)BH * NM * SEQ];         // sim3 raw scores (268 MB)
__device__ float g_C2p[8 * BH * NM * DH];             // split-K partials
__device__ float g_C2[BH * NM * DH];
__device__ float g_Cm[BH * NM * DH];                  // Z @ C2
__device__ float g_O1[(size_t)BH * SEQ * DH];         // attn1 @ Cm
__device__ float g_Y [(size_t)ROWS * DM];             // pre-out-proj
__device__ float g_M3[BH * NM];                       // sim3 row max
__device__ float g_L3[BH * NM];                       // sim3 row sumexp
__device__ unsigned int g_mx[2];

// ---------------- tf32 helpers ----------------
__device__ __forceinline__ float to_tf32(float x) {
    unsigned u; asm("cvt.rna.tf32.f32 %0, %1;" : "=r"(u) : "f"(x));
    return __uint_as_float(u);
}
__device__ __forceinline__ void mma8(float4& d, float a0, float a1, float a2, float a3,
                                     float b0, float b1) {
    asm volatile(
        "mma.sync.aligned.m16n8k8.row.col.f32.tf32.tf32.f32 "
        "{%0,%1,%2,%3}, {%4,%5,%6,%7}, {%8,%9}, {%0,%1,%2,%3};"
        : "+f"(d.x), "+f"(d.y), "+f"(d.z), "+f"(d.w)
        : "r"(__float_as_uint(a0)), "r"(__float_as_uint(a1)),
          "r"(__float_as_uint(a2)), "r"(__float_as_uint(a3)),
          "r"(__float_as_uint(b0)), "r"(__float_as_uint(b1)));
}

// =====================================================================
// TF32 tensor-core GEMM. BM=128, BN in {128,64}. BK=16, double buffer.
// EPI==0: C = alpha*(A@B[^T]) + beta*D (+bias)
// EPI==1: qkv scatter epilogue into q/k/v (q scaled by 0.125)
// EPI==2: A elements -> exp(a - mrow[row]) on load; normal store.
// =====================================================================
template<int BN, int WARPS_N, bool TRANSB, int EPI>
__global__ __launch_bounds__(128 * WARPS_N)
void t_gemm(const float* __restrict__ A, int lda, long long sA,
            const float* __restrict__ B, int ldb, long long sB,
            const float* __restrict__ D, long long sD,
            const float* __restrict__ bias,
            float* __restrict__ C, int ldc, long long sC,
            int K, float alpha, float beta, int ksplit,
            float* __restrict__ qp, float* __restrict__ kp, float* __restrict__ vp,
            const float* __restrict__ mrow)
{
    constexpr int NT = 128 * WARPS_N;
    constexpr int CA = 512 / NT;             // A float4 per thread per stage
    constexpr int CB = (16 * BN / 4) / NT;   // B float4 per thread per stage
    __shared__ __align__(16) float As[2][16][8][16];
    __shared__ __align__(16) float Bs[2][16][8][16];

    const int tid = threadIdx.x;
    const int z = blockIdx.z;
    const int bh = z / ksplit, sk = z - bh * ksplit;
    const float* Ab = A + (size_t)bh * sA + (size_t)blockIdx.y * 128 * lda + (size_t)sk * K;
    const float* Bb;
    if (TRANSB) Bb = B + (size_t)bh * sB + (size_t)blockIdx.x * BN * ldb + (size_t)sk * K;
    else        Bb = B + (size_t)bh * sB + (size_t)sk * K * ldb + blockIdx.x * BN;

    const int lane = tid & 31, g = lane >> 2, tg = lane & 3;
    const int wid = tid >> 5, wm = wid & 3, wn = wid >> 2;
    const int sw = tg << 2;

    float4 rA[CA], rB[CB];

    auto g2r = [&](int kb) {
        #pragma unroll
        for (int i = 0; i < CA; i++) {
            int t4 = tid + i * NT;
            int row = t4 >> 2, kq = (t4 & 3) << 2;
            rA[i] = *(const float4*)(Ab + (size_t)row * lda + kb * 16 + kq);
        }
        #pragma unroll
        for (int i = 0; i < CB; i++) {
            int t4 = tid + i * NT;
            if constexpr (TRANSB) {
                int row = t4 >> 2, kq = (t4 & 3) << 2;
                rB[i] = *(const float4*)(Bb + (size_t)row * ldb + kb * 16 + kq);
            } else {
                constexpr int B4 = BN / 4;
                int row = t4 / B4, cq = (t4 % B4) << 2;
                rB[i] = *(const float4*)(Bb + (size_t)(kb * 16 + row) * ldb + cq);
            }
        }
    };
    auto r2s = [&](int st) {
        #pragma unroll
        for (int i = 0; i < CA; i++) {
            int t4 = tid + i * NT;
            int row = t4 >> 2, kq = (t4 & 3) << 2;
            float v[4] = {rA[i].x, rA[i].y, rA[i].z, rA[i].w};
            if constexpr (EPI == 2) {
                float M = mrow[bh * NM + blockIdx.y * 128 + row];
                #pragma unroll
                for (int j = 0; j < 4; j++) v[j] = expf(v[j] - M);
            }
            #pragma unroll
            for (int j = 0; j < 4; j++) {
                int kk = kq + j;
                As[st][kk][row & 7][(row >> 3) ^ ((kk & 3) << 2)] = to_tf32(v[j]);
            }
        }
        #pragma unroll
        for (int i = 0; i < CB; i++) {
            int t4 = tid + i * NT;
            float v[4] = {rB[i].x, rB[i].y, rB[i].z, rB[i].w};
            if constexpr (TRANSB) {
                int row = t4 >> 2, kq = (t4 & 3) << 2;
                #pragma unroll
                for (int j = 0; j < 4; j++) {
                    int kk = kq + j;
                    Bs[st][kk][row & 7][(row >> 3) ^ ((kk & 3) << 2)] = to_tf32(v[j]);
                }
            } else {
                constexpr int B4 = BN / 4;
                int row = t4 / B4, cq = (t4 % B4) << 2;
                #pragma unroll
                for (int j = 0; j < 4; j++) {
                    int col = cq + j;
                    Bs[st][row][col & 7][(col >> 3) ^ ((row & 3) << 2)] = to_tf32(v[j]);
                }
            }
        }
    };

    float4 acc[2][8];
    #pragma unroll
    for (int i = 0; i < 2; i++)
        #pragma unroll
        for (int j = 0; j < 8; j++) acc[i][j] = make_float4(0.f, 0.f, 0.f, 0.f);

    const int kblocks = K >> 4;
    g2r(0); r2s(0); __syncthreads();
    for (int kb = 0; kb < kblocks; kb++) {
        const int cur = kb & 1;
        if (kb + 1 < kblocks) g2r(kb + 1);
        #pragma unroll
        for (int s8 = 0; s8 < 16; s8 += 8) {
            const int k0 = s8 + tg;
            float4 aLo = *(const float4*)&As[cur][k0    ][g][(wm * 4) ^ sw];
            float4 aHi = *(const float4*)&As[cur][k0 + 4][g][(wm * 4) ^ sw];
            float4 b0l = *(const float4*)&Bs[cur][k0    ][g][(wn * 8) ^ sw];
            float4 b0h = *(const float4*)&Bs[cur][k0    ][g][(wn * 8 + 4) ^ sw];
            float4 b1l = *(const float4*)&Bs[cur][k0 + 4][g][(wn * 8) ^ sw];
            float4 b1h = *(const float4*)&Bs[cur][k0 + 4][g][(wn * 8 + 4) ^ sw];
            float bb0[8] = {b0l.x, b0l.y, b0l.z, b0l.w, b0h.x, b0h.y, b0h.z, b0h.w};
            float bb1[8] = {b1l.x, b1l.y, b1l.z, b1l.w, b1h.x, b1h.y, b1h.z, b1h.w};
            float am[2][4] = {{aLo.x, aLo.y, aHi.x, aHi.y}, {aLo.z, aLo.w, aHi.z, aHi.w}};
            #pragma unroll
            for (int mt = 0; mt < 2; mt++)
                #pragma unroll
                for (int nt = 0; nt < 8; nt++)
                    mma8(acc[mt][nt], am[mt][0], am[mt][1], am[mt][2], am[mt][3],
                         bb0[nt], bb1[nt]);
        }
        if (kb + 1 < kblocks) { r2s(cur ^ 1); __syncthreads(); }
    }

    // epilogue
    const int r00 = blockIdx.y * 128 + wm * 32;
    #pragma unroll
    for (int mt = 0; mt < 2; mt++) {
        #pragma unroll
        for (int nt = 0; nt < 8; nt++) {
            const int r0 = r00 + mt * 16 + g;
            const int cb = blockIdx.x * BN + wn * 64 + nt * 8 + tg * 2;
            float4 v = acc[mt][nt];
            if constexpr (EPI == 1) {
                const int which = cb >> 9, rem = cb & 511;
                const int h = rem >> 6, d = rem & 63;
                const float s = (which == 0) ? 0.125f : 1.0f;
                float* dst = (which == 0) ? qp : ((which == 1) ? kp : vp);
                int b = r0 >> 13, ii = r0 & 8191;
                float2 lo; lo.x = v.x * s; lo.y = v.y * s;
                *(float2*)&dst[(((size_t)(b * 8 + h) * 8192 + ii) << 6) + d] = lo;
                const int r1 = r0 + 8; b = r1 >> 13; ii = r1 & 8191;
                float2 hi; hi.x = v.z * s; hi.y = v.w * s;
                *(float2*)&dst[(((size_t)(b * 8 + h) * 8192 + ii) << 6) + d] = hi;
            } else {
                float* Cb = C + (size_t)z * sC;
                const float* Db = D + (size_t)bh * sD;
                float2 lo, hi;
                lo.x = alpha * v.x; lo.y = alpha * v.y;
                hi.x = alpha * v.z; hi.y = alpha * v.w;
                if (beta != 0.f) {
                    float2 dlo = *(const float2*)&Db[(size_t)r0 * ldc + cb];
                    float2 dhi = *(const float2*)&Db[(size_t)(r0 + 8) * ldc + cb];
                    lo.x += beta * dlo.x; lo.y += beta * dlo.y;
                    hi.x += beta * dhi.x; hi.y += beta * dhi.y;
                }
                if (bias) {
                    float2 bv = *(const float2*)&bias[cb];
                    lo.x += bv.x; lo.y += bv.y; hi.x += bv.x; hi.y += bv.y;
                }
                *(float2*)&Cb[(size_t)r0 * ldc + cb] = lo;
                *(float2*)&Cb[(size_t)(r0 + 8) * ldc + cb] = hi;
            }
        }
    }
}

// =====================================================================
// Fused attn1 path: O1[64 rows] = softmax(q_tile @ kl^T) @ Cm, one CTA per
// (64 q-rows, bh). smem: Qs (A-fmt, 32K) + Ks (B-fmt, 64K, aliased by Ps
// after stage1) + CmS [256][68] (68K) + reduction arrays.
// =====================================================================
#define FA1_SMEM (169984)
__global__ __launch_bounds__(256)
void k_fattn1(const float* __restrict__ qg, const float* __restrict__ klg,
              const float* __restrict__ cmg, float* __restrict__ o1)
{
    extern __shared__ float sm[];
    float* Qs   = sm;                    // [kk<64][g<8][x<16]
    float* Ks   = sm + 8192;             // [kk<64][g<8][x<32]
    float* Ps   = sm + 8192;             // [k<256][g<8][x<8]   (aliases Ks)
    float* Cs   = sm + 24576;            // [k<256][c<68]
    float* Mred = sm + 24576 + 17408;    // [4][64]
    float* Lred = Mred + 256;            // [4][64]

    const int bh = blockIdx.y;
    const int i0 = blockIdx.x * 64;
    const int tid = threadIdx.x;
    const int lane = tid & 31, g = lane >> 2, tg = lane & 3;
    const int wid = tid >> 5, wm = wid & 1, wn = wid >> 1;
    const int sw = tg << 2;

    // ---- fill ----
    const float* qb = qg + ((size_t)bh * SEQ + i0) * 64;
    #pragma unroll
    for (int i = 0; i < 4; i++) {
        int t4 = tid + i * 256; int row = t4 >> 4, kq = (t4 & 15) << 2;
        float4 v = *(const float4*)(qb + row * 64 + kq);
        float vv[4] = {v.x, v.y, v.z, v.w};
        #pragma unroll
        for (int j = 0; j < 4; j++) {
            int kk = kq + j;
            Qs[kk * 128 + (row & 7) * 16 + ((row >> 3) ^ ((kk & 3) << 2))] = to_tf32(vv[j]);
        }
    }
    const float* kb = klg + (size_t)bh * NM * 64;
    #pragma unroll
    for (int i = 0; i < 16; i++) {
        int t4 = tid + i * 256; int l = t4 >> 4, kq = (t4 & 15) << 2;
        float4 v = *(const float4*)(kb + l * 64 + kq);
        float vv[4] = {v.x, v.y, v.z, v.w};
        #pragma unroll
        for (int j = 0; j < 4; j++) {
            int kk = kq + j;
            Ks[kk * 256 + (l & 7) * 32 + ((l >> 3) ^ ((kk & 3) << 2))] = to_tf32(vv[j]);
        }
    }
    const float* cb = cmg + (size_t)bh * NM * 64;
    #pragma unroll
    for (int i = 0; i < 16; i++) {
        int t4 = tid + i * 256; int k = t4 >> 4, nq = (t4 & 15) << 2;
        float4 v = *(const float4*)(cb + k * 64 + nq);
        float4 w; w.x = to_tf32(v.x); w.y = to_tf32(v.y);
        w.z = to_tf32(v.z); w.w = to_tf32(v.w);
        *(float4*)&Cs[k * 68 + nq] = w;
    }
    __syncthreads();

    // ---- stage 1: scores 64x256 ----
    float4 acc1[2][8];
    #pragma unroll
    for (int i = 0; i < 2; i++)
        #pragma unroll
        for (int j = 0; j < 8; j++) acc1[i][j] = make_float4(0.f, 0.f, 0.f, 0.f);

    #pragma unroll
    for (int s8 = 0; s8 < 64; s8 += 8) {
        const int k0 = s8 + tg;
        float4 aLo = *(const float4*)&Qs[k0 * 128 + g * 16 + ((wm * 4) ^ sw)];
        float4 aHi = *(const float4*)&Qs[(k0 + 4) * 128 + g * 16 + ((wm * 4) ^ sw)];
        float4 b0l = *(const float4*)&Ks[k0 * 256 + g * 32 + ((wn * 8) ^ sw)];
        float4 b0h = *(const float4*)&Ks[k0 * 256 + g * 32 + ((wn * 8 + 4) ^ sw)];
        float4 b1l = *(const float4*)&Ks[(k0 + 4) * 256 + g * 32 + ((wn * 8) ^ sw)];
        float4 b1h = *(const float4*)&Ks[(k0 + 4) * 256 + g * 32 + ((wn * 8 + 4) ^ sw)];
        float bb0[8] = {b0l.x, b0l.y, b0l.z, b0l.w, b0h.x, b0h.y, b0h.z, b0h.w};
        float bb1[8] = {b1l.x, b1l.y, b1l.z, b1l.w, b1h.x, b1h.y, b1h.z, b1h.w};
        float am[2][4] = {{aLo.x, aLo.y, aHi.x, aHi.y}, {aLo.z, aLo.w, aHi.z, aHi.w}};
        #pragma unroll
        for (int mt = 0; mt < 2; mt++)
            #pragma unroll
            for (int nt = 0; nt < 8; nt++)
                mma8(acc1[mt][nt], am[mt][0], am[mt][1], am[mt][2], am[mt][3],
                     bb0[nt], bb1[nt]);
    }

    // ---- softmax: rows rl = 32*wm + 8*t + g, t=0..3 ----
    float rmax[4];
    #pragma unroll
    for (int t = 0; t < 4; t++) {
        const int mt = t >> 1; const bool hi = t & 1;
        float m = -1e30f;
        #pragma unroll
        for (int nt = 0; nt < 8; nt++) {
            float4 a = acc1[mt][nt];
            m = fmaxf(m, hi ? fmaxf(a.z, a.w) : fmaxf(a.x, a.y));
        }
        m = fmaxf(m, __shfl_xor_sync(0xffffffffu, m, 1));
        m = fmaxf(m, __shfl_xor_sync(0xffffffffu, m, 2));
        rmax[t] = m;
    }
    if (tg == 0) {
        #pragma unroll
        for (int t = 0; t < 4; t++) Mred[wn * 64 + 32 * wm + 8 * t + g] = rmax[t];
    }
    __syncthreads();   // also guards Ks -> Ps reuse
    #pragma unroll
    for (int t = 0; t < 4; t++) {
        const int rl = 32 * wm + 8 * t + g;
        rmax[t] = fmaxf(fmaxf(Mred[rl], Mred[64 + rl]),
                        fmaxf(Mred[128 + rl], Mred[192 + rl]));
    }
    #pragma unroll
    for (int t = 0; t < 4; t++) {
        const int mt = t >> 1; const bool hi = t & 1;
        const int rl = 32 * wm + 8 * t + g;
        const int rh = rl >> 3;            // = 4*wm + t
        const float M = rmax[t];
        float s = 0.f;
        #pragma unroll
        for (int nt = 0; nt < 8; nt++) {
            float4 a = acc1[mt][nt];
            float v0 = hi ? a.z : a.x, v1 = hi ? a.w : a.y;
            float e0 = expf(v0 - M), e1 = expf(v1 - M);
            s += e0 + e1;
            int c0 = wn * 64 + nt * 8 + 2 * tg;
            Ps[c0 * 64 + g * 8 + (rh ^ (c0 & 7))] = to_tf32(e0);
            Ps[(c0 + 1) * 64 + g * 8 + (rh ^ ((c0 + 1) & 7))] = to_tf32(e1);
        }
        s += __shfl_xor_sync(0xffffffffu, s, 1);
        s += __shfl_xor_sync(0xffffffffu, s, 2);
        if (tg == 0) Lred[wn * 64 + rl] = s;
    }
    __syncthreads();

    // ---- stage 2: O1 tile = P(64x256) @ Cm(256x64), warp tile 32x16 ----
    float4 acc2[2][2];
    #pragma unroll
    for (int i = 0; i < 2; i++)
        #pragma unroll
        for (int j = 0; j < 2; j++) acc2[i][j] = make_float4(0.f, 0.f, 0.f, 0.f);

    #pragma unroll 4
    for (int s8 = 0; s8 < 256; s8 += 8) {
        const int k0 = s8 + tg, k1 = k0 + 4;
        float a_[2][4], b_[2][2];
        #pragma unroll
        for (int mt = 0; mt < 2; mt++) {
            const int rh = 4 * wm + 2 * mt;
            a_[mt][0] = Ps[k0 * 64 + g * 8 + (rh ^ (k0 & 7))];
            a_[mt][1] = Ps[k0 * 64 + g * 8 + ((rh + 1) ^ (k0 & 7))];
            a_[mt][2] = Ps[k1 * 64 + g * 8 + (rh ^ (k1 & 7))];
            a_[mt][3] = Ps[k1 * 64 + g * 8 + ((rh + 1) ^ (k1 & 7))];
        }
        #pragma unroll
        for (int nt = 0; nt < 2; nt++) {
            const int c = wn * 16 + nt * 8 + g;
            b_[nt][0] = Cs[k0 * 68 + c];
            b_[nt][1] = Cs[k1 * 68 + c];
        }
        #pragma unroll
        for (int mt = 0; mt < 2; mt++)
            #pragma unroll
            for (int nt = 0; nt < 2; nt++)
                mma8(acc2[mt][nt], a_[mt][0], a_[mt][1], a_[mt][2], a_[mt][3],
                     b_[nt][0], b_[nt][1]);
    }

    float invL[4];
    #pragma unroll
    for (int t = 0; t < 4; t++) {
        const int rl = 32 * wm + 8 * t + g;
        float L = Lred[rl] + Lred[64 + rl] + Lred[128 + rl] + Lred[192 + rl];
        invL[t] = 1.f / L;
    }
    float* ob = o1 + ((size_t)bh * SEQ + i0) * 64;
    #pragma unroll
    for (int mt = 0; mt < 2; mt++) {
        #pragma unroll
        for (int nt = 0; nt < 2; nt++) {
            const int c = wn * 16 + nt * 8 + 2 * tg;
            const int r0 = 32 * wm + 16 * mt + g;
            float4 v = acc2[mt][nt];
            float2 lo; lo.x = v.x * invL[2 * mt]; lo.y = v.y * invL[2 * mt];
            float2 hi; hi.x = v.z * invL[2 * mt + 1]; hi.y = v.w * invL[2 * mt + 1];
            *(float2*)&ob[(size_t)r0 * 64 + c] = lo;
            *(float2*)&ob[(size_t)(r0 + 8) * 64 + c] = hi;
        }
    }
}

// landmarks: mean over 32 consecutive tokens
__global__ void k_land() {
    int idx = blockIdx.x * blockDim.x + threadIdx.x;   // BH*NM*DH
    int d = idx & 63, i = (idx >> 6) & 255, bh = idx >> 14;
    size_t base = (size_t)bh * SEQ * DH + (size_t)i * LG * DH + d;
    float qs = 0.f, ks = 0.f;
    #pragma unroll 8
    for (int j = 0; j < LG; j++) { qs += g_q[base + j * 64]; ks += g_k[base + j * 64]; }
    g_ql[idx] = qs * (1.f / LG);
    g_kl[idx] = ks * (1.f / LG);
}

// Row softmax (in place), COLS = CT*256. One block per row.
template<int CT>
__global__ void k_softmax(float* __restrict__ X) {
    const size_t base = (size_t)blockIdx.x * (CT * 256);
    const int tid = threadIdx.x, lane = tid & 31, wp = tid >> 5;
    __shared__ float red[8];
    float v[CT];
    float m = -1e30f;
    #pragma unroll
    for (int t = 0; t < CT; t++) { v[t] = X[base + t * 256 + tid]; m = fmaxf(m, v[t]); }
    #pragma unroll
    for (int off = 16; off; off >>= 1) m = fmaxf(m, __shfl_xor_sync(0xffffffffu, m, off));
    if (!lane) red[wp] = m;
    __syncthreads();
    float M = red[0];
    #pragma unroll
    for (int w = 1; w < 8; w++) M = fmaxf(M, red[w]);
    __syncthreads();
    float s = 0.f;
    #pragma unroll
    for (int t = 0; t < CT; t++) { v[t] = expf(v[t] - M); s += v[t]; }
    #pragma unroll
    for (int off = 16; off; off >>= 1) s += __shfl_xor_sync(0xffffffffu, s, off);
    if (!lane) red[wp] = s;
    __syncthreads();
    float S = 0.f;
    #pragma unroll
    for (int w = 0; w < 8; w++) S += red[w];
    float inv = 1.f / S;
    #pragma unroll
    for (int t = 0; t < CT; t++) X[base + t * 256 + tid] = v[t] * inv;
}

// sim3 row stats: one block per row of S (8192 cols): M = max, L = sum exp(s-M)
__global__ void k_stats() {
    const size_t base = (size_t)blockIdx.x * SEQ;
    const int tid = threadIdx.x, lane = tid & 31, wp = tid >> 5;
    __shared__ float red[8];
    float v[32];
    float m = -1e30f;
    #pragma unroll
    for (int t = 0; t < 32; t++) { v[t] = g_S[base + t * 256 + tid]; m = fmaxf(m, v[t]); }
    #pragma unroll
    for (int off = 16; off; off >>= 1) m = fmaxf(m, __shfl_xor_sync(0xffffffffu, m, off));
    if (!lane) red[wp] = m;
    __syncthreads();
    float M = red[0];
    #pragma unroll
    for (int w = 1; w < 8; w++) M = fmaxf(M, red[w]);
    __syncthreads();
    float s = 0.f;
    #pragma unroll
    for (int t = 0; t < 32; t++) s += expf(v[t] - M);
    #pragma unroll
    for (int off = 16; off; off >>= 1) s += __shfl_xor_sync(0xffffffffu, s, off);
    if (!lane) red[wp] = s;
    __syncthreads();
    if (tid == 0) {
        float S = 0.f;
        #pragma unroll
        for (int w = 0; w < 8; w++) S += red[w];
        g_M3[blockIdx.x] = M;
        g_L3[blockIdx.x] = S;
    }
}

// global max of row-sums (axis -1) and col-sums (axis -2) over ALL bh
__global__ void k_reset() { if (threadIdx.x < 2) g_mx[threadIdx.x] = 0u; }

__global__ void k_colrowmax() {
    const int bh = blockIdx.x, tid = threadIdx.x, lane = tid & 31, wp = tid >> 5;
    __shared__ float red[8];
    const float* Xb = g_X + (size_t)bh * NM * NM;
    float cs = 0.f;
    for (int i = 0; i < NM; i++) cs += Xb[i * NM + tid];
    float m = cs;
    #pragma unroll
    for (int off = 16; off; off >>= 1) m = fmaxf(m, __shfl_xor_sync(0xffffffffu, m, off));
    if (!lane) red[wp] = m;
    __syncthreads();
    if (tid == 0) {
        float M = red[0];
        #pragma unroll
        for (int w = 1; w < 8; w++) M = fmaxf(M, red[w]);
        atomicMax(&g_mx[1], __float_as_uint(M));
    }
    __syncthreads();
    float rs = 0.f;
    const float* Xr = Xb + (size_t)tid * NM;
    for (int j = 0; j < NM; j++) rs += Xr[j];
    m = rs;
    #pragma unroll
    for (int off = 16; off; off >>= 1) m = fmaxf(m, __shfl_xor_sync(0xffffffffu, m, off));
    if (!lane) red[wp] = m;
    __syncthreads();
    if (tid == 0) {
        float M = red[0];
        #pragma unroll
        for (int w = 1; w < 8; w++) M = fmaxf(M, red[w]);
        atomicMax(&g_mx[0], __float_as_uint(M));
    }
}

__global__ void k_zinit() {
    int idx = blockIdx.x * blockDim.x + threadIdx.x;   // BH*NM*NM
    float inv = 1.f / (__uint_as_float(g_mx[0]) * __uint_as_float(g_mx[1]));
    int j = idx & 255, i = (idx >> 8) & 255, bh = idx >> 16;
    g_Za[idx] = g_X[(size_t)bh * NM * NM + j * NM + i] * inv;
}

__global__ void k_combine() {
    int idx = blockIdx.x * blockDim.x + threadIdx.x;   // BH*NM*DH
    int bh = idx >> 14, r = idx & 16383;
    float s = 0.f;
    #pragma unroll
    for (int p = 0; p < 8; p++) s += g_C2p[(size_t)(bh * 8 + p) * 16384 + r];
    g_C2[idx] = s / g_L3[bh * NM + (r >> 6)];
}

// epilogue: O1 + depthwise conv(v, 33), transposed into Y[b*n][h*64+d]
__global__ __launch_bounds__(256)
void k_post(const float* __restrict__ wres) {
    __shared__ float vs[160][64];
    __shared__ float w[33];
    const int bh = blockIdx.y, b = bh >> 3, h = bh & 7;
    const int i0 = blockIdx.x * 128;
    const int tid = threadIdx.x;
    if (tid < 33) w[tid] = wres[h * 33 + tid];
    const float* vb = g_v + (size_t)bh * SEQ * DH;
    for (int p = tid; p < 2560; p += 256) {
        int row = p >> 4, q4 = (p & 15) << 2;
        int gi = i0 - 16 + row;
        float4 t = (gi >= 0 && gi < SEQ) ? *(const float4*)(vb + (size_t)gi * 64 + q4)
                                         : make_float4(0.f, 0.f, 0.f, 0.f);
        *(float4*)&vs[row][q4] = t;
    }
    __syncthreads();
    const int d = tid & 63, rg = tid >> 6;
    const float* o1 = g_O1 + (size_t)bh * SEQ * DH;
    for (int l = rg; l < 128; l += 4) {
        float acc = 0.f;
        #pragma unroll
        for (int t = 0; t < 33; t++) acc += w[t] * vs[l + t][d];
        int i = i0 + l;
        g_Y[(size_t)(b * SEQ + i) * DM + h * DH + d] = o1[(size_t)i * DH + d] + acc;
    }
}

// =====================================================================
extern "C" void kernel_launch(void* const* d_in, const int* in_sizes, int n_in,
                              void* d_out, int out_size) {
    const float* x     = (const float*)d_in[0];
    const float* w_qkv = (const float*)d_in[1];
    const float* w_out = (const float*)d_in[2];
    const float* b_out = (const float*)d_in[3];
    const float* w_res = (const float*)d_in[4];
    float* out = (float*)d_out;

    float *q, *k_, *v, *ql, *kl, *X, *Za, *Zb, *XZ, *T1, *T2, *S, *C2p, *C2, *Cm, *O1, *Y, *M3;
    cudaGetSymbolAddress((void**)&q,   g_q);
    cudaGetSymbolAddress((void**)&k_,  g_k);
    cudaGetSymbolAddress((void**)&v,   g_v);
    cudaGetSymbolAddress((void**)&ql,  g_ql);
    cudaGetSymbolAddress((void**)&kl,  g_kl);
    cudaGetSymbolAddress((void**)&X,   g_X);
    cudaGetSymbolAddress((void**)&Za,  g_Za);
    cudaGetSymbolAddress((void**)&Zb,  g_Zb);
    cudaGetSymbolAddress((void**)&XZ,  g_XZ);
    cudaGetSymbolAddress((void**)&T1,  g_T1);
    cudaGetSymbolAddress((void**)&T2,  g_T2);
    cudaGetSymbolAddress((void**)&S,   g_S);
    cudaGetSymbolAddress((void**)&C2p, g_C2p);
    cudaGetSymbolAddress((void**)&C2,  g_C2);
    cudaGetSymbolAddress((void**)&Cm,  g_Cm);
    cudaGetSymbolAddress((void**)&O1,  g_O1);
    cudaGetSymbolAddress((void**)&Y,   g_Y);
    cudaGetSymbolAddress((void**)&M3,  g_M3);

    cudaFuncSetAttribute(k_fattn1, cudaFuncAttributeMaxDynamicSharedMemorySize, FA1_SMEM);

    const float* NUL = (const float*)0;
    float* NULF = (float*)0;

    // 1. qkv = x @ w_qkv, scattered directly to packed q (scaled), k, v
    t_gemm<128, 2, false, 1><<<dim3(TRIPLE / 128, ROWS / 128, 1), 256>>>(
        x, DM, 0LL, w_qkv, TRIPLE, 0LL, NUL, 0LL, NUL, q, TRIPLE, 0LL,
        DM, 1.f, 0.f, 1, q, k_, v, NUL);
    // 2. landmarks
    k_land<<<(BH * NM * DH) / 256, 256>>>();
    // 3. attn2 = softmax(q_land @ k_land^T)
    t_gemm<128, 2, true, 0><<<dim3(2, 2, BH), 256>>>(
        ql, DH, 16384LL, kl, DH, 16384LL, NUL, 0LL, NUL, X, NM, 65536LL,
        DH, 1.f, 0.f, 1, NULF, NULF, NULF, NUL);
    k_softmax<1><<<BH * NM, 256>>>(X);
    // 4. pinv init
    k_reset<<<1, 32>>>();
    k_colrowmax<<<BH, 256>>>();
    k_zinit<<<(BH * NM * NM) / 256, 256>>>();
    // 5. 6 Newton iterations
    float* Zc = Za; float* Zn = Zb;
    for (int it = 0; it < 6; it++) {
        t_gemm<128, 2, false, 0><<<dim3(2, 2, BH), 256>>>(
            X, NM, 65536LL, Zc, NM, 65536LL, NUL, 0LL, NUL, XZ, NM, 65536LL,
            NM, 1.f, 0.f, 1, NULF, NULF, NULF, NUL);
        t_gemm<128, 2, false, 0><<<dim3(2, 2, BH), 256>>>(
            XZ, NM, 65536LL, XZ, NM, 65536LL, XZ, 65536LL, NUL, T1, NM, 65536LL,
            NM, -1.f, 7.f, 1, NULF, NULF, NULF, NUL);
        t_gemm<128, 2, false, 0><<<dim3(2, 2, BH), 256>>>(
            XZ, NM, 65536LL, T1, NM, 65536LL, XZ, 65536LL, NUL, T2, NM, 65536LL,
            NM, -1.f, 15.f, 1, NULF, NULF, NULF, NUL);
        t_gemm<128, 2, false, 0><<<dim3(2, 2, BH), 256>>>(
            Zc, NM, 65536LL, T2, NM, 65536LL, Zc, 65536LL, NUL, Zn, NM, 65536LL,
            NM, -0.25f, 3.25f, 1, NULF, NULF, NULF, NUL);
        float* tmp = Zc; Zc = Zn; Zn = tmp;
    }
    // 6. sim3 = q_land @ k^T (raw scores)
    t_gemm<128, 2, true, 0><<<dim3(SEQ / 128, 2, BH), 256>>>(
        ql, DH, 16384LL, k_, DH, 524288LL, NUL, 0LL, NUL, S, SEQ, 2097152LL,
        DH, 1.f, 0.f, 1, NULF, NULF, NULF, NUL);
    // 7. row stats for sim3
    k_stats<<<BH * NM, 256>>>();
    // 8. C2 = exp(sim3 - M) @ v  (split-K 8), /L in combine
    t_gemm<64, 1, false, 2><<<dim3(1, 2, BH * 8), 128>>>(
        S, SEQ, 2097152LL, v, DH, 524288LL, NUL, 0LL, NUL, C2p, DH, 16384LL,
        1024, 1.f, 0.f, 8, NULF, NULF, NULF, M3);
    k_combine<<<(BH * NM * DH) / 256, 256>>>();
    // 9. Cm = Z @ C2
    t_gemm<64, 1, false, 0><<<dim3(1, 2, BH), 128>>>(
        Zc, NM, 65536LL, C2, DH, 16384LL, NUL, 0LL, NUL, Cm, DH, 16384LL,
        NM, 1.f, 0.f, 1, NULF, NULF, NULF, NUL);
    // 10. fused: O1 = softmax(q @ kl^T) @ Cm
    k_fattn1<<<dim3(SEQ / 64, BH), 256, FA1_SMEM>>>(q, kl, Cm, O1);
    // 11. conv residual + transpose -> Y
    k_post<<<dim3(SEQ / 128, BH), 256>>>(w_res);
    // 12. out = Y @ w_out + b_out
    t_gemm<128, 2, false, 0><<<dim3(DM / 128, ROWS / 128, 1), 256>>>(
        Y, DM, 0LL, w_out, DM, 0LL, NUL, 0LL, b_out, out, DM, 0LL,
        DM, 1.f, 0.f, 1, NULF, NULF, NULF, NUL);
}

// round 7
// speedup vs baseline: 1.7166x; 1.1158x over previous
#include <cuda_runtime.h>
#include <cuda_bf16.h>
#include <math.h>

#define NB      4
#define SEQ     8192
#define DM      512
#define NH      8
#define DH      64
#define NM      256
#define LG      32
#define BH      32          // NB*NH
#define TRIPLE  1536
#define ROWS    32768       // NB*SEQ

// ---------------- scratch (device globals; no allocations allowed) -------
__device__ float g_q [(size_t)BH * SEQ * DH];         // packed, pre-scaled by dh^-0.5
__device__ float g_k [(size_t)BH * SEQ * DH];
__device__ float g_v [(size_t)BH * SEQ * DH];
__device__ float g_ql[BH * NM * DH];
__device__ float g_kl[BH * NM * DH];
__device__ float g_X [BH * NM * NM];                  // attn2
__device__ float g_Za[BH * NM * NM];
__device__ float g_Zb[BH * NM * NM];
__device__ float g_XZ[BH * NM * NM];
__device__ float g_T1[BH * NM * NM];
__device__ float g_T2[BH * NM * NM];
__device__ float g_C2[BH * NM * DH];                  // softmax(sim3) @ v
__device__ float g_Cm[BH * NM * DH];                  // Z @ C2
__device__ float g_O1[(size_t)BH * SEQ * DH];         // attn1 @ Cm
__device__ float g_Y [(size_t)ROWS * DM];             // pre-out-proj
__device__ unsigned int g_mx[2];

// ---------------- tf32 helpers ----------------
__device__ __forceinline__ float to_tf32(float x) {
    unsigned u; asm("cvt.rna.tf32.f32 %0, %1;" : "=r"(u) : "f"(x));
    return __uint_as_float(u);
}
__device__ __forceinline__ void mma8(float4& d, float a0, float a1, float a2, float a3,
                                     float b0, float b1) {
    asm volatile(
        "mma.sync.aligned.m16n8k8.row.col.f32.tf32.tf32.f32 "
        "{%0,%1,%2,%3}, {%4,%5,%6,%7}, {%8,%9}, {%0,%1,%2,%3};"
        : "+f"(d.x), "+f"(d.y), "+f"(d.z), "+f"(d.w)
        : "r"(__float_as_uint(a0)), "r"(__float_as_uint(a1)),
          "r"(__float_as_uint(a2)), "r"(__float_as_uint(a3)),
          "r"(__float_as_uint(b0)), "r"(__float_as_uint(b1)));
}
__device__ __forceinline__ void cpa16(void* s, const void* g) {
    unsigned sa = (unsigned)__cvta_generic_to_shared(s);
    asm volatile("cp.async.cg.shared.global [%0], [%1], 16;" :: "r"(sa), "l"(g));
}

// =====================================================================
// TF32 tensor-core GEMM. BM=128, BN in {128,64}. BK=16, double buffer.
// EPI==0: C = alpha*(A@B[^T]) + beta*D (+bias)
// EPI==1: qkv scatter epilogue into q/k/v (q scaled by 0.125)
// =====================================================================
template<int BN, int WARPS_N, bool TRANSB, int EPI>
__global__ __launch_bounds__(128 * WARPS_N)
void t_gemm(const float* __restrict__ A, int lda, long long sA,
            const float* __restrict__ B, int ldb, long long sB,
            const float* __restrict__ D, long long sD,
            const float* __restrict__ bias,
            float* __restrict__ C, int ldc, long long sC,
            int K, float alpha, float beta, int ksplit,
            float* __restrict__ qp, float* __restrict__ kp, float* __restrict__ vp)
{
    constexpr int NT = 128 * WARPS_N;
    constexpr int CA = 512 / NT;             // A float4 per thread per stage
    constexpr int CB = (16 * BN / 4) / NT;   // B float4 per thread per stage
    __shared__ __align__(16) float As[2][16][8][16];
    __shared__ __align__(16) float Bs[2][16][8][16];

    const int tid = threadIdx.x;
    const int z = blockIdx.z;
    const int bh = z / ksplit, sk = z - bh * ksplit;
    const float* Ab = A + (size_t)bh * sA + (size_t)blockIdx.y * 128 * lda + (size_t)sk * K;
    const float* Bb;
    if (TRANSB) Bb = B + (size_t)bh * sB + (size_t)blockIdx.x * BN * ldb + (size_t)sk * K;
    else        Bb = B + (size_t)bh * sB + (size_t)sk * K * ldb + blockIdx.x * BN;

    const int lane = tid & 31, g = lane >> 2, tg = lane & 3;
    const int wid = tid >> 5, wm = wid & 3, wn = wid >> 2;
    const int sw = tg << 2;

    float4 rA[CA], rB[CB];

    auto g2r = [&](int kb) {
        #pragma unroll
        for (int i = 0; i < CA; i++) {
            int t4 = tid + i * NT;
            int row = t4 >> 2, kq = (t4 & 3) << 2;
            rA[i] = *(const float4*)(Ab + (size_t)row * lda + kb * 16 + kq);
        }
        #pragma unroll
        for (int i = 0; i < CB; i++) {
            int t4 = tid + i * NT;
            if constexpr (TRANSB) {
                int row = t4 >> 2, kq = (t4 & 3) << 2;
                rB[i] = *(const float4*)(Bb + (size_t)row * ldb + kb * 16 + kq);
            } else {
                constexpr int B4 = BN / 4;
                int row = t4 / B4, cq = (t4 % B4) << 2;
                rB[i] = *(const float4*)(Bb + (size_t)(kb * 16 + row) * ldb + cq);
            }
        }
    };
    auto r2s = [&](int st) {
        #pragma unroll
        for (int i = 0; i < CA; i++) {
            int t4 = tid + i * NT;
            int row = t4 >> 2, kq = (t4 & 3) << 2;
            float v[4] = {rA[i].x, rA[i].y, rA[i].z, rA[i].w};
            #pragma unroll
            for (int j = 0; j < 4; j++) {
                int kk = kq + j;
                As[st][kk][row & 7][(row >> 3) ^ ((kk & 3) << 2)] = to_tf32(v[j]);
            }
        }
        #pragma unroll
        for (int i = 0; i < CB; i++) {
            int t4 = tid + i * NT;
            float v[4] = {rB[i].x, rB[i].y, rB[i].z, rB[i].w};
            if constexpr (TRANSB) {
                int row = t4 >> 2, kq = (t4 & 3) << 2;
                #pragma unroll
                for (int j = 0; j < 4; j++) {
                    int kk = kq + j;
                    Bs[st][kk][row & 7][(row >> 3) ^ ((kk & 3) << 2)] = to_tf32(v[j]);
                }
            } else {
                constexpr int B4 = BN / 4;
                int row = t4 / B4, cq = (t4 % B4) << 2;
                #pragma unroll
                for (int j = 0; j < 4; j++) {
                    int col = cq + j;
                    Bs[st][row][col & 7][(col >> 3) ^ ((row & 3) << 2)] = to_tf32(v[j]);
                }
            }
        }
    };

    float4 acc[2][8];
    #pragma unroll
    for (int i = 0; i < 2; i++)
        #pragma unroll
        for (int j = 0; j < 8; j++) acc[i][j] = make_float4(0.f, 0.f, 0.f, 0.f);

    const int kblocks = K >> 4;
    g2r(0); r2s(0); __syncthreads();
    for (int kb = 0; kb < kblocks; kb++) {
        const int cur = kb & 1;
        if (kb + 1 < kblocks) g2r(kb + 1);
        #pragma unroll
        for (int s8 = 0; s8 < 16; s8 += 8) {
            const int k0 = s8 + tg;
            float4 aLo = *(const float4*)&As[cur][k0    ][g][(wm * 4) ^ sw];
            float4 aHi = *(const float4*)&As[cur][k0 + 4][g][(wm * 4) ^ sw];
            float4 b0l = *(const float4*)&Bs[cur][k0    ][g][(wn * 8) ^ sw];
            float4 b0h = *(const float4*)&Bs[cur][k0    ][g][(wn * 8 + 4) ^ sw];
            float4 b1l = *(const float4*)&Bs[cur][k0 + 4][g][(wn * 8) ^ sw];
            float4 b1h = *(const float4*)&Bs[cur][k0 + 4][g][(wn * 8 + 4) ^ sw];
            float bb0[8] = {b0l.x, b0l.y, b0l.z, b0l.w, b0h.x, b0h.y, b0h.z, b0h.w};
            float bb1[8] = {b1l.x, b1l.y, b1l.z, b1l.w, b1h.x, b1h.y, b1h.z, b1h.w};
            float am[2][4] = {{aLo.x, aLo.y, aHi.x, aHi.y}, {aLo.z, aLo.w, aHi.z, aHi.w}};
            #pragma unroll
            for (int mt = 0; mt < 2; mt++)
                #pragma unroll
                for (int nt = 0; nt < 8; nt++)
                    mma8(acc[mt][nt], am[mt][0], am[mt][1], am[mt][2], am[mt][3],
                         bb0[nt], bb1[nt]);
        }
        if (kb + 1 < kblocks) { r2s(cur ^ 1); __syncthreads(); }
    }

    // epilogue
    const int r00 = blockIdx.y * 128 + wm * 32;
    #pragma unroll
    for (int mt = 0; mt < 2; mt++) {
        #pragma unroll
        for (int nt = 0; nt < 8; nt++) {
            const int r0 = r00 + mt * 16 + g;
            const int cb = blockIdx.x * BN + wn * 64 + nt * 8 + tg * 2;
            float4 v = acc[mt][nt];
            if constexpr (EPI == 1) {
                const int which = cb >> 9, rem = cb & 511;
                const int h = rem >> 6, d = rem & 63;
                const float s = (which == 0) ? 0.125f : 1.0f;
                float* dst = (which == 0) ? qp : ((which == 1) ? kp : vp);
                int b = r0 >> 13, ii = r0 & 8191;
                float2 lo; lo.x = v.x * s; lo.y = v.y * s;
                *(float2*)&dst[(((size_t)(b * 8 + h) * 8192 + ii) << 6) + d] = lo;
                const int r1 = r0 + 8; b = r1 >> 13; ii = r1 & 8191;
                float2 hi; hi.x = v.z * s; hi.y = v.w * s;
                *(float2*)&dst[(((size_t)(b * 8 + h) * 8192 + ii) << 6) + d] = hi;
            } else {
                float* Cb = C + (size_t)z * sC;
                const float* Db = D + (size_t)bh * sD;
                float2 lo, hi;
                lo.x = alpha * v.x; lo.y = alpha * v.y;
                hi.x = alpha * v.z; hi.y = alpha * v.w;
                if (beta != 0.f) {
                    float2 dlo = *(const float2*)&Db[(size_t)r0 * ldc + cb];
                    float2 dhi = *(const float2*)&Db[(size_t)(r0 + 8) * ldc + cb];
                    lo.x += beta * dlo.x; lo.y += beta * dlo.y;
                    hi.x += beta * dhi.x; hi.y += beta * dhi.y;
                }
                if (bias) {
                    float2 bv = *(const float2*)&bias[cb];
                    lo.x += bv.x; lo.y += bv.y; hi.x += bv.x; hi.y += bv.y;
                }
                *(float2*)&Cb[(size_t)r0 * ldc + cb] = lo;
                *(float2*)&Cb[(size_t)(r0 + 8) * ldc + cb] = hi;
            }
        }
    }
}

// =====================================================================
// Flash-style fused sim3 path: C2[64 landmark rows, 64] =
//   softmax_row(ql_tile @ k^T) @ v,  streaming k/v in 128-token tiles
//   with cp.async double buffering + online softmax.
// One CTA (256 thr) per (64-row tile, bh). grid (4, BH).
// smem floats: Qs 8192 | Ks[2] 2*8704 | Vs[2] 2*8704 | Ps 8448 | Mp 256 | Lp 256
// =====================================================================
#define FA3_SMEM (207872)
__global__ __launch_bounds__(256)
void k_fattn3(const float* __restrict__ qlg, const float* __restrict__ kg,
              const float* __restrict__ vg, float* __restrict__ c2)
{
    extern __shared__ float sm[];
    float* Qs = sm;                         // [kk<64][g<8][x<16]
    float* Ks = sm + 8192;                  // 2 stages, [c<128][68]
    float* Vs = sm + 8192 + 2 * 8704;       // 2 stages, [c<128][68]
    float* Ps = sm + 8192 + 4 * 8704;       // [row<64][132]
    float* Mp = Ps + 8448;                  // [4][64]
    float* Lp = Mp + 256;                   // [4][64]

    const int bh = blockIdx.y;
    const int i0 = blockIdx.x * 64;
    const int tid = threadIdx.x;
    const int lane = tid & 31, g = lane >> 2, tg = lane & 3;
    const int wid = tid >> 5, wm = wid & 1, wn = wid >> 1;
    const int sw = tg << 2;

    const float* kb = kg + (size_t)bh * SEQ * DH;
    const float* vb = vg + (size_t)bh * SEQ * DH;

    // issue K/V tile j into stage st
    auto issue = [&](int j, int st) {
        const int cb = j * 128;
        #pragma unroll
        for (int i = 0; i < 8; i++) {
            int t4 = tid + i * 256;
            int row = t4 >> 4, q4 = (t4 & 15) << 2;
            cpa16(&Ks[st * 8704 + row * 68 + q4], kb + (size_t)(cb + row) * 64 + q4);
        }
        #pragma unroll
        for (int i = 0; i < 8; i++) {
            int t4 = tid + i * 256;
            int row = t4 >> 4, q4 = (t4 & 15) << 2;
            cpa16(&Vs[st * 8704 + row * 68 + q4], vb + (size_t)(cb + row) * 64 + q4);
        }
        asm volatile("cp.async.commit_group;");
    };

    issue(0, 0);

    // load Q tile (64x64) into A-layout with cvt
    const float* qb = qlg + ((size_t)bh * NM + i0) * 64;
    #pragma unroll
    for (int i = 0; i < 4; i++) {
        int t4 = tid + i * 256; int row = t4 >> 4, kq = (t4 & 15) << 2;
        float4 v = *(const float4*)(qb + row * 64 + kq);
        float vv[4] = {v.x, v.y, v.z, v.w};
        #pragma unroll
        for (int j = 0; j < 4; j++) {
            int kk = kq + j;
            Qs[kk * 128 + (row & 7) * 16 + ((row >> 3) ^ ((kk & 3) << 2))] = to_tf32(vv[j]);
        }
    }

    float4 acc2[2][2];
    #pragma unroll
    for (int i = 0; i < 2; i++)
        #pragma unroll
        for (int j = 0; j < 2; j++) acc2[i][j] = make_float4(0.f, 0.f, 0.f, 0.f);
    float Mrun[4] = {-1e30f, -1e30f, -1e30f, -1e30f};
    float Lrun[4] = {0.f, 0.f, 0.f, 0.f};

    for (int jt = 0; jt < SEQ / 128; jt++) {
        const int cur = jt & 1;
        if (jt + 1 < SEQ / 128) {
            issue(jt + 1, cur ^ 1);
            asm volatile("cp.async.wait_group 1;");
        } else {
            asm volatile("cp.async.wait_group 0;");
        }
        __syncthreads();

        const float* Kc = Ks + cur * 8704;
        const float* Vc = Vs + cur * 8704;

        // stage A: S(64x128) = Q @ K^T
        float4 acc1[2][4];
        #pragma unroll
        for (int i = 0; i < 2; i++)
            #pragma unroll
            for (int j = 0; j < 4; j++) acc1[i][j] = make_float4(0.f, 0.f, 0.f, 0.f);
        #pragma unroll
        for (int s8 = 0; s8 < 64; s8 += 8) {
            const int k0 = s8 + tg;
            float4 aLo = *(const float4*)&Qs[k0 * 128 + g * 16 + ((wm * 4) ^ sw)];
            float4 aHi = *(const float4*)&Qs[(k0 + 4) * 128 + g * 16 + ((wm * 4) ^ sw)];
            float am[2][4] = {{aLo.x, aLo.y, aHi.x, aHi.y}, {aLo.z, aLo.w, aHi.z, aHi.w}};
            #pragma unroll
            for (int nt = 0; nt < 4; nt++) {
                const float* kr = Kc + (wn * 32 + nt * 8 + g) * 68;
                float b0 = kr[k0], b1 = kr[k0 + 4];
                #pragma unroll
                for (int mt = 0; mt < 2; mt++)
                    mma8(acc1[mt][nt], am[mt][0], am[mt][1], am[mt][2], am[mt][3], b0, b1);
            }
        }

        // tile row max -> Mp
        float tmax[4];
        #pragma unroll
        for (int t = 0; t < 4; t++) {
            const int mt = t >> 1; const bool hi = t & 1;
            float m = -1e30f;
            #pragma unroll
            for (int nt = 0; nt < 4; nt++) {
                float4 a = acc1[mt][nt];
                m = fmaxf(m, hi ? fmaxf(a.z, a.w) : fmaxf(a.x, a.y));
            }
            m = fmaxf(m, __shfl_xor_sync(0xffffffffu, m, 1));
            m = fmaxf(m, __shfl_xor_sync(0xffffffffu, m, 2));
            tmax[t] = m;
        }
        if (tg == 0) {
            #pragma unroll
            for (int t = 0; t < 4; t++) Mp[wn * 64 + wm * 32 + 8 * t + g] = tmax[t];
        }
        __syncthreads();

        float f[4];
        #pragma unroll
        for (int t = 0; t < 4; t++) {
            const int rl = wm * 32 + 8 * t + g;
            float tm = fmaxf(fmaxf(Mp[rl], Mp[64 + rl]),
                             fmaxf(Mp[128 + rl], Mp[192 + rl]));
            float Mn = fmaxf(Mrun[t], tm);
            f[t] = __expf(Mrun[t] - Mn);
            Mrun[t] = Mn;
        }
        // rescale O accumulators
        #pragma unroll
        for (int mt2 = 0; mt2 < 2; mt2++)
            #pragma unroll
            for (int nt2 = 0; nt2 < 2; nt2++) {
                acc2[mt2][nt2].x *= f[2 * mt2];     acc2[mt2][nt2].y *= f[2 * mt2];
                acc2[mt2][nt2].z *= f[2 * mt2 + 1]; acc2[mt2][nt2].w *= f[2 * mt2 + 1];
            }
        // P = exp(S - M), store + partial rowsum
        #pragma unroll
        for (int t = 0; t < 4; t++) {
            const int mt = t >> 1; const bool hi = t & 1;
            const int rl = wm * 32 + 8 * t + g;
            const float M = Mrun[t];
            float s = 0.f;
            #pragma unroll
            for (int nt = 0; nt < 4; nt++) {
                float4 a = acc1[mt][nt];
                float v0 = hi ? a.z : a.x, v1 = hi ? a.w : a.y;
                float e0 = __expf(v0 - M), e1 = __expf(v1 - M);
                s += e0 + e1;
                int c0 = wn * 32 + nt * 8 + 2 * tg;
                Ps[rl * 132 + c0] = e0;
                Ps[rl * 132 + c0 + 1] = e1;
            }
            s += __shfl_xor_sync(0xffffffffu, s, 1);
            s += __shfl_xor_sync(0xffffffffu, s, 2);
            if (tg == 0) Lp[wn * 64 + rl] = s;
        }
        __syncthreads();
        #pragma unroll
        for (int t = 0; t < 4; t++) {
            const int rl = wm * 32 + 8 * t + g;
            Lrun[t] = Lrun[t] * f[t] + (Lp[rl] + Lp[64 + rl] + Lp[128 + rl] + Lp[192 + rl]);
        }

        // stage B: O += P(64x128) @ V(128x64)
        #pragma unroll 4
        for (int s8 = 0; s8 < 128; s8 += 8) {
            const int k0 = s8 + tg, k1 = k0 + 4;
            float a_[2][4], b_[2][2];
            #pragma unroll
            for (int mt2 = 0; mt2 < 2; mt2++) {
                const int r0 = wm * 32 + 16 * mt2 + g;
                a_[mt2][0] = Ps[r0 * 132 + k0];
                a_[mt2][1] = Ps[(r0 + 8) * 132 + k0];
                a_[mt2][2] = Ps[r0 * 132 + k1];
                a_[mt2][3] = Ps[(r0 + 8) * 132 + k1];
            }
            #pragma unroll
            for (int nt2 = 0; nt2 < 2; nt2++) {
                const int c = wn * 16 + nt2 * 8 + g;
                b_[nt2][0] = Vc[k0 * 68 + c];
                b_[nt2][1] = Vc[k1 * 68 + c];
            }
            #pragma unroll
            for (int mt2 = 0; mt2 < 2; mt2++)
                #pragma unroll
                for (int nt2 = 0; nt2 < 2; nt2++)
                    mma8(acc2[mt2][nt2], a_[mt2][0], a_[mt2][1], a_[mt2][2], a_[mt2][3],
                         b_[nt2][0], b_[nt2][1]);
        }
        __syncthreads();
    }

    float invL[4];
    #pragma unroll
    for (int t = 0; t < 4; t++) invL[t] = 1.f / Lrun[t];
    float* ob = c2 + ((size_t)bh * NM + i0) * 64;
    #pragma unroll
    for (int mt2 = 0; mt2 < 2; mt2++) {
        #pragma unroll
        for (int nt2 = 0; nt2 < 2; nt2++) {
            const int c = wn * 16 + nt2 * 8 + 2 * tg;
            const int r0 = wm * 32 + 16 * mt2 + g;
            float4 v = acc2[mt2][nt2];
            float2 lo; lo.x = v.x * invL[2 * mt2];     lo.y = v.y * invL[2 * mt2];
            float2 hi; hi.x = v.z * invL[2 * mt2 + 1]; hi.y = v.w * invL[2 * mt2 + 1];
            *(float2*)&ob[(size_t)r0 * 64 + c] = lo;
            *(float2*)&ob[(size_t)(r0 + 8) * 64 + c] = hi;
        }
    }
}

// =====================================================================
// Fused attn1 path (unchanged from R5, expf -> __expf)
// =====================================================================
#define FA1_SMEM (169984)
__global__ __launch_bounds__(256)
void k_fattn1(const float* __restrict__ qg, const float* __restrict__ klg,
              const float* __restrict__ cmg, float* __restrict__ o1)
{
    extern __shared__ float sm[];
    float* Qs   = sm;                    // [kk<64][g<8][x<16]
    float* Ks   = sm + 8192;             // [kk<64][g<8][x<32]
    float* Ps   = sm + 8192;             // [k<256][g<8][x<8]   (aliases Ks)
    float* Cs   = sm + 24576;            // [k<256][c<68]
    float* Mred = sm + 24576 + 17408;    // [4][64]
    float* Lred = Mred + 256;            // [4][64]

    const int bh = blockIdx.y;
    const int i0 = blockIdx.x * 64;
    const int tid = threadIdx.x;
    const int lane = tid & 31, g = lane >> 2, tg = lane & 3;
    const int wid = tid >> 5, wm = wid & 1, wn = wid >> 1;
    const int sw = tg << 2;

    const float* qb = qg + ((size_t)bh * SEQ + i0) * 64;
    #pragma unroll
    for (int i = 0; i < 4; i++) {
        int t4 = tid + i * 256; int row = t4 >> 4, kq = (t4 & 15) << 2;
        float4 v = *(const float4*)(qb + row * 64 + kq);
        float vv[4] = {v.x, v.y, v.z, v.w};
        #pragma unroll
        for (int j = 0; j < 4; j++) {
            int kk = kq + j;
            Qs[kk * 128 + (row & 7) * 16 + ((row >> 3) ^ ((kk & 3) << 2))] = to_tf32(vv[j]);
        }
    }
    const float* kb = klg + (size_t)bh * NM * 64;
    #pragma unroll
    for (int i = 0; i < 16; i++) {
        int t4 = tid + i * 256; int l = t4 >> 4, kq = (t4 & 15) << 2;
        float4 v = *(const float4*)(kb + l * 64 + kq);
        float vv[4] = {v.x, v.y, v.z, v.w};
        #pragma unroll
        for (int j = 0; j < 4; j++) {
            int kk = kq + j;
            Ks[kk * 256 + (l & 7) * 32 + ((l >> 3) ^ ((kk & 3) << 2))] = to_tf32(vv[j]);
        }
    }
    const float* cb = cmg + (size_t)bh * NM * 64;
    #pragma unroll
    for (int i = 0; i < 16; i++) {
        int t4 = tid + i * 256; int k = t4 >> 4, nq = (t4 & 15) << 2;
        float4 v = *(const float4*)(cb + k * 64 + nq);
        float4 w; w.x = to_tf32(v.x); w.y = to_tf32(v.y);
        w.z = to_tf32(v.z); w.w = to_tf32(v.w);
        *(float4*)&Cs[k * 68 + nq] = w;
    }
    __syncthreads();

    float4 acc1[2][8];
    #pragma unroll
    for (int i = 0; i < 2; i++)
        #pragma unroll
        for (int j = 0; j < 8; j++) acc1[i][j] = make_float4(0.f, 0.f, 0.f, 0.f);

    #pragma unroll
    for (int s8 = 0; s8 < 64; s8 += 8) {
        const int k0 = s8 + tg;
        float4 aLo = *(const float4*)&Qs[k0 * 128 + g * 16 + ((wm * 4) ^ sw)];
        float4 aHi = *(const float4*)&Qs[(k0 + 4) * 128 + g * 16 + ((wm * 4) ^ sw)];
        float4 b0l = *(const float4*)&Ks[k0 * 256 + g * 32 + ((wn * 8) ^ sw)];
        float4 b0h = *(const float4*)&Ks[k0 * 256 + g * 32 + ((wn * 8 + 4) ^ sw)];
        float4 b1l = *(const float4*)&Ks[(k0 + 4) * 256 + g * 32 + ((wn * 8) ^ sw)];
        float4 b1h = *(const float4*)&Ks[(k0 + 4) * 256 + g * 32 + ((wn * 8 + 4) ^ sw)];
        float bb0[8] = {b0l.x, b0l.y, b0l.z, b0l.w, b0h.x, b0h.y, b0h.z, b0h.w};
        float bb1[8] = {b1l.x, b1l.y, b1l.z, b1l.w, b1h.x, b1h.y, b1h.z, b1h.w};
        float am[2][4] = {{aLo.x, aLo.y, aHi.x, aHi.y}, {aLo.z, aLo.w, aHi.z, aHi.w}};
        #pragma unroll
        for (int mt = 0; mt < 2; mt++)
            #pragma unroll
            for (int nt = 0; nt < 8; nt++)
                mma8(acc1[mt][nt], am[mt][0], am[mt][1], am[mt][2], am[mt][3],
                     bb0[nt], bb1[nt]);
    }

    float rmax[4];
    #pragma unroll
    for (int t = 0; t < 4; t++) {
        const int mt = t >> 1; const bool hi = t & 1;
        float m = -1e30f;
        #pragma unroll
        for (int nt = 0; nt < 8; nt++) {
            float4 a = acc1[mt][nt];
            m = fmaxf(m, hi ? fmaxf(a.z, a.w) : fmaxf(a.x, a.y));
        }
        m = fmaxf(m, __shfl_xor_sync(0xffffffffu, m, 1));
        m = fmaxf(m, __shfl_xor_sync(0xffffffffu, m, 2));
        rmax[t] = m;
    }
    if (tg == 0) {
        #pragma unroll
        for (int t = 0; t < 4; t++) Mred[wn * 64 + 32 * wm + 8 * t + g] = rmax[t];
    }
    __syncthreads();
    #pragma unroll
    for (int t = 0; t < 4; t++) {
        const int rl = 32 * wm + 8 * t + g;
        rmax[t] = fmaxf(fmaxf(Mred[rl], Mred[64 + rl]),
                        fmaxf(Mred[128 + rl], Mred[192 + rl]));
    }
    #pragma unroll
    for (int t = 0; t < 4; t++) {
        const int mt = t >> 1; const bool hi = t & 1;
        const int rl = 32 * wm + 8 * t + g;
        const int rh = rl >> 3;
        const float M = rmax[t];
        float s = 0.f;
        #pragma unroll
        for (int nt = 0; nt < 8; nt++) {
            float4 a = acc1[mt][nt];
            float v0 = hi ? a.z : a.x, v1 = hi ? a.w : a.y;
            float e0 = __expf(v0 - M), e1 = __expf(v1 - M);
            s += e0 + e1;
            int c0 = wn * 64 + nt * 8 + 2 * tg;
            Ps[c0 * 64 + g * 8 + (rh ^ (c0 & 7))] = e0;
            Ps[(c0 + 1) * 64 + g * 8 + (rh ^ ((c0 + 1) & 7))] = e1;
        }
        s += __shfl_xor_sync(0xffffffffu, s, 1);
        s += __shfl_xor_sync(0xffffffffu, s, 2);
        if (tg == 0) Lred[wn * 64 + rl] = s;
    }
    __syncthreads();

    float4 acc2[2][2];
    #pragma unroll
    for (int i = 0; i < 2; i++)
        #pragma unroll
        for (int j = 0; j < 2; j++) acc2[i][j] = make_float4(0.f, 0.f, 0.f, 0.f);

    #pragma unroll 4
    for (int s8 = 0; s8 < 256; s8 += 8) {
        const int k0 = s8 + tg, k1 = k0 + 4;
        float a_[2][4], b_[2][2];
        #pragma unroll
        for (int mt = 0; mt < 2; mt++) {
            const int rh = 4 * wm + 2 * mt;
            a_[mt][0] = Ps[k0 * 64 + g * 8 + (rh ^ (k0 & 7))];
            a_[mt][1] = Ps[k0 * 64 + g * 8 + ((rh + 1) ^ (k0 & 7))];
            a_[mt][2] = Ps[k1 * 64 + g * 8 + (rh ^ (k1 & 7))];
            a_[mt][3] = Ps[k1 * 64 + g * 8 + ((rh + 1) ^ (k1 & 7))];
        }
        #pragma unroll
        for (int nt = 0; nt < 2; nt++) {
            const int c = wn * 16 + nt * 8 + g;
            b_[nt][0] = Cs[k0 * 68 + c];
            b_[nt][1] = Cs[k1 * 68 + c];
        }
        #pragma unroll
        for (int mt = 0; mt < 2; mt++)
            #pragma unroll
            for (int nt = 0; nt < 2; nt++)
                mma8(acc2[mt][nt], a_[mt][0], a_[mt][1], a_[mt][2], a_[mt][3],
                     b_[nt][0], b_[nt][1]);
    }

    float invL[4];
    #pragma unroll
    for (int t = 0; t < 4; t++) {
        const int rl = 32 * wm + 8 * t + g;
        float L = Lred[rl] + Lred[64 + rl] + Lred[128 + rl] + Lred[192 + rl];
        invL[t] = 1.f / L;
    }
    float* ob = o1 + ((size_t)bh * SEQ + i0) * 64;
    #pragma unroll
    for (int mt = 0; mt < 2; mt++) {
        #pragma unroll
        for (int nt = 0; nt < 2; nt++) {
            const int c = wn * 16 + nt * 8 + 2 * tg;
            const int r0 = 32 * wm + 16 * mt + g;
            float4 v = acc2[mt][nt];
            float2 lo; lo.x = v.x * invL[2 * mt]; lo.y = v.y * invL[2 * mt];
            float2 hi; hi.x = v.z * invL[2 * mt + 1]; hi.y = v.w * invL[2 * mt + 1];
            *(float2*)&ob[(size_t)r0 * 64 + c] = lo;
            *(float2*)&ob[(size_t)(r0 + 8) * 64 + c] = hi;
        }
    }
}

// landmarks: mean over 32 consecutive tokens
__global__ void k_land() {
    int idx = blockIdx.x * blockDim.x + threadIdx.x;   // BH*NM*DH
    int d = idx & 63, i = (idx >> 6) & 255, bh = idx >> 14;
    size_t base = (size_t)bh * SEQ * DH + (size_t)i * LG * DH + d;
    float qs = 0.f, ks = 0.f;
    #pragma unroll 8
    for (int j = 0; j < LG; j++) { qs += g_q[base + j * 64]; ks += g_k[base + j * 64]; }
    g_ql[idx] = qs * (1.f / LG);
    g_kl[idx] = ks * (1.f / LG);
}

// Row softmax (in place), 256 cols, one block per row.
__global__ void k_softmax(float* __restrict__ X) {
    const size_t base = (size_t)blockIdx.x * 256;
    const int tid = threadIdx.x, lane = tid & 31, wp = tid >> 5;
    __shared__ float red[8];
    float v = X[base + tid];
    float m = v;
    #pragma unroll
    for (int off = 16; off; off >>= 1) m = fmaxf(m, __shfl_xor_sync(0xffffffffu, m, off));
    if (!lane) red[wp] = m;
    __syncthreads();
    float M = red[0];
    #pragma unroll
    for (int w = 1; w < 8; w++) M = fmaxf(M, red[w]);
    __syncthreads();
    float e = __expf(v - M);
    float s = e;
    #pragma unroll
    for (int off = 16; off; off >>= 1) s += __shfl_xor_sync(0xffffffffu, s, off);
    if (!lane) red[wp] = s;
    __syncthreads();
    float S = 0.f;
    #pragma unroll
    for (int w = 0; w < 8; w++) S += red[w];
    X[base + tid] = e / S;
}

// global max of row-sums (axis -1) and col-sums (axis -2) over ALL bh
__global__ void k_reset() { if (threadIdx.x < 2) g_mx[threadIdx.x] = 0u; }

__global__ void k_colrowmax() {
    const int bh = blockIdx.x, tid = threadIdx.x, lane = tid & 31, wp = tid >> 5;
    __shared__ float red[8];
    const float* Xb = g_X + (size_t)bh * NM * NM;
    float cs = 0.f;
    for (int i = 0; i < NM; i++) cs += Xb[i * NM + tid];
    float m = cs;
    #pragma unroll
    for (int off = 16; off; off >>= 1) m = fmaxf(m, __shfl_xor_sync(0xffffffffu, m, off));
    if (!lane) red[wp] = m;
    __syncthreads();
    if (tid == 0) {
        float M = red[0];
        #pragma unroll
        for (int w = 1; w < 8; w++) M = fmaxf(M, red[w]);
        atomicMax(&g_mx[1], __float_as_uint(M));
    }
    __syncthreads();
    float rs = 0.f;
    const float* Xr = Xb + (size_t)tid * NM;
    for (int j = 0; j < NM; j++) rs += Xr[j];
    m = rs;
    #pragma unroll
    for (int off = 16; off; off >>= 1) m = fmaxf(m, __shfl_xor_sync(0xffffffffu, m, off));
    if (!lane) red[wp] = m;
    __syncthreads();
    if (tid == 0) {
        float M = red[0];
        #pragma unroll
        for (int w = 1; w < 8; w++) M = fmaxf(M, red[w]);
        atomicMax(&g_mx[0], __float_as_uint(M));
    }
}

__global__ void k_zinit() {
    int idx = blockIdx.x * blockDim.x + threadIdx.x;   // BH*NM*NM
    float inv = 1.f / (__uint_as_float(g_mx[0]) * __uint_as_float(g_mx[1]));
    int j = idx & 255, i = (idx >> 8) & 255, bh = idx >> 16;
    g_Za[idx] = g_X[(size_t)bh * NM * NM + j * NM + i] * inv;
}

// epilogue: O1 + depthwise conv(v, 33), transposed into Y[b*n][h*64+d]
__global__ __launch_bounds__(256)
void k_post(const float* __restrict__ wres) {
    __shared__ float vs[160][64];
    __shared__ float w[33];
    const int bh = blockIdx.y, b = bh >> 3, h = bh & 7;
    const int i0 = blockIdx.x * 128;
    const int tid = threadIdx.x;
    if (tid < 33) w[tid] = wres[h * 33 + tid];
    const float* vb = g_v + (size_t)bh * SEQ * DH;
    for (int p = tid; p < 2560; p += 256) {
        int row = p >> 4, q4 = (p & 15) << 2;
        int gi = i0 - 16 + row;
        float4 t = (gi >= 0 && gi < SEQ) ? *(const float4*)(vb + (size_t)gi * 64 + q4)
                                         : make_float4(0.f, 0.f, 0.f, 0.f);
        *(float4*)&vs[row][q4] = t;
    }
    __syncthreads();
    const int d = tid & 63, rg = tid >> 6;
    const float* o1 = g_O1 + (size_t)bh * SEQ * DH;
    for (int l = rg; l < 128; l += 4) {
        float acc = 0.f;
        #pragma unroll
        for (int t = 0; t < 33; t++) acc += w[t] * vs[l + t][d];
        int i = i0 + l;
        g_Y[(size_t)(b * SEQ + i) * DM + h * DH + d] = o1[(size_t)i * DH + d] + acc;
    }
}

// =====================================================================
extern "C" void kernel_launch(void* const* d_in, const int* in_sizes, int n_in,
                              void* d_out, int out_size) {
    const float* x     = (const float*)d_in[0];
    const float* w_qkv = (const float*)d_in[1];
    const float* w_out = (const float*)d_in[2];
    const float* b_out = (const float*)d_in[3];
    const float* w_res = (const float*)d_in[4];
    float* out = (float*)d_out;

    float *q, *k_, *v, *ql, *kl, *X, *Za, *Zb, *XZ, *T1, *T2, *C2, *Cm, *O1, *Y;
    cudaGetSymbolAddress((void**)&q,   g_q);
    cudaGetSymbolAddress((void**)&k_,  g_k);
    cudaGetSymbolAddress((void**)&v,   g_v);
    cudaGetSymbolAddress((void**)&ql,  g_ql);
    cudaGetSymbolAddress((void**)&kl,  g_kl);
    cudaGetSymbolAddress((void**)&X,   g_X);
    cudaGetSymbolAddress((void**)&Za,  g_Za);
    cudaGetSymbolAddress((void**)&Zb,  g_Zb);
    cudaGetSymbolAddress((void**)&XZ,  g_XZ);
    cudaGetSymbolAddress((void**)&T1,  g_T1);
    cudaGetSymbolAddress((void**)&T2,  g_T2);
    cudaGetSymbolAddress((void**)&C2,  g_C2);
    cudaGetSymbolAddress((void**)&Cm,  g_Cm);
    cudaGetSymbolAddress((void**)&O1,  g_O1);
    cudaGetSymbolAddress((void**)&Y,   g_Y);

    cudaFuncSetAttribute(k_fattn1, cudaFuncAttributeMaxDynamicSharedMemorySize, FA1_SMEM);
    cudaFuncSetAttribute(k_fattn3, cudaFuncAttributeMaxDynamicSharedMemorySize, FA3_SMEM);

    const float* NUL = (const float*)0;
    float* NULF = (float*)0;

    // 1. qkv = x @ w_qkv, scattered directly to packed q (scaled), k, v
    t_gemm<128, 2, false, 1><<<dim3(TRIPLE / 128, ROWS / 128, 1), 256>>>(
        x, DM, 0LL, w_qkv, TRIPLE, 0LL, NUL, 0LL, NUL, q, TRIPLE, 0LL,
        DM, 1.f, 0.f, 1, q, k_, v);
    // 2. landmarks
    k_land<<<(BH * NM * DH) / 256, 256>>>();
    // 3. attn2 = softmax(q_land @ k_land^T)
    t_gemm<128, 2, true, 0><<<dim3(2, 2, BH), 256>>>(
        ql, DH, 16384LL, kl, DH, 16384LL, NUL, 0LL, NUL, X, NM, 65536LL,
        DH, 1.f, 0.f, 1, NULF, NULF, NULF);
    k_softmax<<<BH * NM, 256>>>(X);
    // 4. pinv init
    k_reset<<<1, 32>>>();
    k_colrowmax<<<BH, 256>>>();
    k_zinit<<<(BH * NM * NM) / 256, 256>>>();
    // 5. 6 Newton iterations
    float* Zc = Za; float* Zn = Zb;
    for (int it = 0; it < 6; it++) {
        t_gemm<128, 2, false, 0><<<dim3(2, 2, BH), 256>>>(
            X, NM, 65536LL, Zc, NM, 65536LL, NUL, 0LL, NUL, XZ, NM, 65536LL,
            NM, 1.f, 0.f, 1, NULF, NULF, NULF);
        t_gemm<128, 2, false, 0><<<dim3(2, 2, BH), 256>>>(
            XZ, NM, 65536LL, XZ, NM, 65536LL, XZ, 65536LL, NUL, T1, NM, 65536LL,
            NM, -1.f, 7.f, 1, NULF, NULF, NULF);
        t_gemm<128, 2, false, 0><<<dim3(2, 2, BH), 256>>>(
            XZ, NM, 65536LL, T1, NM, 65536LL, XZ, 65536LL, NUL, T2, NM, 65536LL,
            NM, -1.f, 15.f, 1, NULF, NULF, NULF);
        t_gemm<128, 2, false, 0><<<dim3(2, 2, BH), 256>>>(
            Zc, NM, 65536LL, T2, NM, 65536LL, Zc, 65536LL, NUL, Zn, NM, 65536LL,
            NM, -0.25f, 3.25f, 1, NULF, NULF, NULF);
        float* tmp = Zc; Zc = Zn; Zn = tmp;
    }
    // 6. fused flash sim3 path: C2 = softmax(ql @ k^T) @ v
    k_fattn3<<<dim3(4, BH), 256, FA3_SMEM>>>(ql, k_, v, C2);
    // 7. Cm = Z @ C2
    t_gemm<64, 1, false, 0><<<dim3(1, 2, BH), 128>>>(
        Zc, NM, 65536LL, C2, DH, 16384LL, NUL, 0LL, NUL, Cm, DH, 16384LL,
        NM, 1.f, 0.f, 1, NULF, NULF, NULF);
    // 8. fused: O1 = softmax(q @ kl^T) @ Cm
    k_fattn1<<<dim3(SEQ / 64, BH), 256, FA1_SMEM>>>(q, kl, Cm, O1);
    // 9. conv residual + transpose -> Y
    k_post<<<dim3(SEQ / 128, BH), 256>>>(w_res);
    // 10. out = Y @ w_out + b_out
    t_gemm<128, 2, false, 0><<<dim3(DM / 128, ROWS / 128, 1), 256>>>(
        Y, DM, 0LL, w_out, DM, 0LL, NUL, 0LL, b_out, out, DM, 0LL,
        DM, 1.f, 0.f, 1, NULF, NULF, NULF);
}

// round 10
// speedup vs baseline: 2.3676x; 1.3792x over previous
#include <cuda_runtime.h>
#include <cuda_bf16.h>
#include <math.h>

#define NB      4
#define SEQ     8192
#define DM      512
#define NH      8
#define DH      64
#define NM      256
#define LG      32
#define BH      32          // NB*NH
#define TRIPLE  1536
#define ROWS    32768       // NB*SEQ

// ---------------- scratch (device globals; no allocations allowed) -------
__device__ float g_q [(size_t)BH * SEQ * DH];         // packed, pre-scaled by dh^-0.5
__device__ float g_k [(size_t)BH * SEQ * DH];
__device__ float g_v [(size_t)BH * SEQ * DH];
__device__ float g_ql[BH * NM * DH];
__device__ float g_kl[BH * NM * DH];
__device__ float g_X [BH * NM * NM];                  // attn2
__device__ float g_Za[BH * NM * NM];
__device__ float g_Zb[BH * NM * NM];
__device__ float g_XZ[BH * NM * NM];
__device__ float g_T1[BH * NM * NM];
__device__ float g_T2[BH * NM * NM];
__device__ float g_C2[BH * NM * DH];                  // softmax(sim3) @ v
__device__ float g_Cm[BH * NM * DH];                  // Z @ C2
__device__ float g_Y [(size_t)ROWS * DM];             // pre-out-proj
__device__ unsigned int g_mx[2];

// ---------------- helpers ----------------
__device__ __forceinline__ float to_tf32(float x) {
    unsigned u; asm("cvt.rna.tf32.f32 %0, %1;" : "=r"(u) : "f"(x));
    return __uint_as_float(u);
}
__device__ __forceinline__ void mma8(float4& d, float a0, float a1, float a2, float a3,
                                     float b0, float b1) {
    asm volatile(
        "mma.sync.aligned.m16n8k8.row.col.f32.tf32.tf32.f32 "
        "{%0,%1,%2,%3}, {%4,%5,%6,%7}, {%8,%9}, {%0,%1,%2,%3};"
        : "+f"(d.x), "+f"(d.y), "+f"(d.z), "+f"(d.w)
        : "r"(__float_as_uint(a0)), "r"(__float_as_uint(a1)),
          "r"(__float_as_uint(a2)), "r"(__float_as_uint(a3)),
          "r"(__float_as_uint(b0)), "r"(__float_as_uint(b1)));
}
__device__ __forceinline__ void cpa16(void* s, const void* g) {
    unsigned sa = (unsigned)__cvta_generic_to_shared(s);
    asm volatile("cp.async.cg.shared.global [%0], [%1], 16;" :: "r"(sa), "l"(g));
}
__device__ __forceinline__ void cpa16z(void* s, const void* g, bool ok) {
    unsigned sa = (unsigned)__cvta_generic_to_shared(s);
    int sz = ok ? 16 : 0;
    asm volatile("cp.async.cg.shared.global [%0], [%1], 16, %2;" :: "r"(sa), "l"(g), "r"(sz));
}
__device__ __forceinline__ void cvt4(float* p) {
    float4 v = *(float4*)p;
    v.x = to_tf32(v.x); v.y = to_tf32(v.y); v.z = to_tf32(v.z); v.w = to_tf32(v.w);
    *(float4*)p = v;
}

// =====================================================================
// TF32 tensor-core GEMM, cp.async 3-stage pipeline + in-smem RNA cvt pass.
// BM=128, BN in {128,64}. BK=16.
// smem: As[3][128][20]; TN B: Bs[3][BN][20]; NN B: Bs[3][16][BN+8].
// EPI==0: C = alpha*(A@B[^T]) + beta*D (+bias)
// EPI==1: qkv scatter epilogue into q/k/v (q scaled by 0.125)
// =====================================================================
template<int BN, int WARPS_N, bool TRANSB, int EPI>
__global__ __launch_bounds__(128 * WARPS_N)
void t_gemm(const float* __restrict__ A, int lda, long long sA,
            const float* __restrict__ B, int ldb, long long sB,
            const float* __restrict__ D, long long sD,
            const float* __restrict__ bias,
            float* __restrict__ C, int ldc, long long sC,
            int K, float alpha, float beta, int ksplit,
            float* __restrict__ qp, float* __restrict__ kp, float* __restrict__ vp)
{
    constexpr int NT   = 128 * WARPS_N;
    constexpr int ASTG = 128 * 20;
    constexpr int BSTG = TRANSB ? BN * 20 : 16 * (BN + 8);
    constexpr int ACH  = 512 / NT;        // 16B chunks per thread per stage
    constexpr int BCH  = 4 * BN / NT;
    extern __shared__ float smp[];
    float* As = smp;
    float* Bs = smp + 3 * ASTG;

    const int tid = threadIdx.x;
    const int z = blockIdx.z;
    const int bh = z / ksplit, sk = z - bh * ksplit;
    const float* Ab = A + (size_t)bh * sA + (size_t)blockIdx.y * 128 * lda + (size_t)sk * K;
    const float* Bb;
    if (TRANSB) Bb = B + (size_t)bh * sB + (size_t)blockIdx.x * BN * ldb + (size_t)sk * K;
    else        Bb = B + (size_t)bh * sB + (size_t)sk * K * ldb + blockIdx.x * BN;

    const int lane = tid & 31, g = lane >> 2, tg = lane & 3;
    const int wid = tid >> 5, wm = wid & 3, wn = wid >> 2;

    auto issue = [&](int kb, int st) {
        #pragma unroll
        for (int i = 0; i < ACH; i++) {
            int id = tid + i * NT;
            int row = id >> 2, c4 = id & 3;
            cpa16(&As[st * ASTG + row * 20 + c4 * 4],
                  Ab + (size_t)row * lda + kb * 16 + c4 * 4);
        }
        #pragma unroll
        for (int i = 0; i < BCH; i++) {
            int id = tid + i * NT;
            if constexpr (TRANSB) {
                int row = id >> 2, c4 = id & 3;
                cpa16(&Bs[st * BSTG + row * 20 + c4 * 4],
                      Bb + (size_t)row * ldb + kb * 16 + c4 * 4);
            } else {
                int kr = id / (BN / 4), n4 = id % (BN / 4);
                cpa16(&Bs[st * BSTG + kr * (BN + 8) + n4 * 4],
                      Bb + (size_t)(kb * 16 + kr) * ldb + n4 * 4);
            }
        }
        asm volatile("cp.async.commit_group;");
    };

    // re-round this thread's own chunks of stage st to tf32 (RNA)
    auto cvt_stage = [&](int st) {
        #pragma unroll
        for (int i = 0; i < ACH; i++) {
            int id = tid + i * NT;
            int row = id >> 2, c4 = id & 3;
            cvt4(&As[st * ASTG + row * 20 + c4 * 4]);
        }
        #pragma unroll
        for (int i = 0; i < BCH; i++) {
            int id = tid + i * NT;
            if constexpr (TRANSB) {
                int row = id >> 2, c4 = id & 3;
                cvt4(&Bs[st * BSTG + row * 20 + c4 * 4]);
            } else {
                int kr = id / (BN / 4), n4 = id % (BN / 4);
                cvt4(&Bs[st * BSTG + kr * (BN + 8) + n4 * 4]);
            }
        }
    };

    float4 acc[2][8];
    #pragma unroll
    for (int i = 0; i < 2; i++)
        #pragma unroll
        for (int j = 0; j < 8; j++) acc[i][j] = make_float4(0.f, 0.f, 0.f, 0.f);

    const int kblocks = K >> 4;
    issue(0, 0); issue(1, 1);
    for (int kb = 0; kb < kblocks; kb++) {
        if (kb + 1 < kblocks) { asm volatile("cp.async.wait_group 1;"); }
        else                  { asm volatile("cp.async.wait_group 0;"); }
        __syncthreads();
        cvt_stage(kb % 3);
        if (kb + 2 < kblocks) issue(kb + 2, (kb + 2) % 3);
        __syncthreads();
        const float* Ac = As + (kb % 3) * ASTG;
        const float* Bc = Bs + (kb % 3) * BSTG;
        #pragma unroll
        for (int s8 = 0; s8 < 16; s8 += 8) {
            float a[2][4];
            #pragma unroll
            for (int mt = 0; mt < 2; mt++) {
                const int Rm = wm * 32 + mt * 16 + g;
                a[mt][0] = Ac[Rm * 20 + s8 + tg];
                a[mt][1] = Ac[(Rm + 8) * 20 + s8 + tg];
                a[mt][2] = Ac[Rm * 20 + s8 + tg + 4];
                a[mt][3] = Ac[(Rm + 8) * 20 + s8 + tg + 4];
            }
            #pragma unroll
            for (int nt = 0; nt < 8; nt++) {
                const int c = wn * 64 + nt * 8 + g;
                float b0, b1;
                if constexpr (TRANSB) {
                    b0 = Bc[c * 20 + s8 + tg];
                    b1 = Bc[c * 20 + s8 + tg + 4];
                } else {
                    b0 = Bc[(s8 + tg) * (BN + 8) + c];
                    b1 = Bc[(s8 + tg + 4) * (BN + 8) + c];
                }
                #pragma unroll
                for (int mt = 0; mt < 2; mt++)
                    mma8(acc[mt][nt], a[mt][0], a[mt][1], a[mt][2], a[mt][3], b0, b1);
            }
        }
    }

    // epilogue
    const int r00 = blockIdx.y * 128 + wm * 32;
    #pragma unroll
    for (int mt = 0; mt < 2; mt++) {
        #pragma unroll
        for (int nt = 0; nt < 8; nt++) {
            const int r0 = r00 + mt * 16 + g;
            const int cb = blockIdx.x * BN + wn * 64 + nt * 8 + tg * 2;
            float4 v = acc[mt][nt];
            if constexpr (EPI == 1) {
                const int which = cb >> 9, rem = cb & 511;
                const int h = rem >> 6, d = rem & 63;
                const float s = (which == 0) ? 0.125f : 1.0f;
                float* dst = (which == 0) ? qp : ((which == 1) ? kp : vp);
                int b = r0 >> 13, ii = r0 & 8191;
                float2 lo; lo.x = v.x * s; lo.y = v.y * s;
                *(float2*)&dst[(((size_t)(b * 8 + h) * 8192 + ii) << 6) + d] = lo;
                const int r1 = r0 + 8; b = r1 >> 13; ii = r1 & 8191;
                float2 hi; hi.x = v.z * s; hi.y = v.w * s;
                *(float2*)&dst[(((size_t)(b * 8 + h) * 8192 + ii) << 6) + d] = hi;
            } else {
                float* Cb = C + (size_t)z * sC;
                const float* Db = D + (size_t)bh * sD;
                float2 lo, hi;
                lo.x = alpha * v.x; lo.y = alpha * v.y;
                hi.x = alpha * v.z; hi.y = alpha * v.w;
                if (beta != 0.f) {
                    float2 dlo = *(const float2*)&Db[(size_t)r0 * ldc + cb];
                    float2 dhi = *(const float2*)&Db[(size_t)(r0 + 8) * ldc + cb];
                    lo.x += beta * dlo.x; lo.y += beta * dlo.y;
                    hi.x += beta * dhi.x; hi.y += beta * dhi.y;
                }
                if (bias) {
                    float2 bv = *(const float2*)&bias[cb];
                    lo.x += bv.x; lo.y += bv.y; hi.x += bv.x; hi.y += bv.y;
                }
                *(float2*)&Cb[(size_t)r0 * ldc + cb] = lo;
                *(float2*)&Cb[(size_t)(r0 + 8) * ldc + cb] = hi;
            }
        }
    }
}

// =====================================================================
// Flash-style fused sim3 path (R6 config — passed at 4.148e-4)
// =====================================================================
#define FA3_SMEM (207872)
__global__ __launch_bounds__(256)
void k_fattn3(const float* __restrict__ qlg, const float* __restrict__ kg,
              const float* __restrict__ vg, float* __restrict__ c2)
{
    extern __shared__ float sm[];
    float* Qs = sm;                         // [kk<64][g<8][x<16]
    float* Ks = sm + 8192;                  // 2 stages, [c<128][68]
    float* Vs = sm + 8192 + 2 * 8704;       // 2 stages, [c<128][68]
    float* Ps = sm + 8192 + 4 * 8704;       // [row<64][132]
    float* Mp = Ps + 8448;                  // [4][64]
    float* Lp = Mp + 256;                   // [4][64]

    const int bh = blockIdx.y;
    const int i0 = blockIdx.x * 64;
    const int tid = threadIdx.x;
    const int lane = tid & 31, g = lane >> 2, tg = lane & 3;
    const int wid = tid >> 5, wm = wid & 1, wn = wid >> 1;
    const int sw = tg << 2;

    const float* kb = kg + (size_t)bh * SEQ * DH;
    const float* vb = vg + (size_t)bh * SEQ * DH;

    auto issue = [&](int j, int st) {
        const int cb = j * 128;
        #pragma unroll
        for (int i = 0; i < 8; i++) {
            int t4 = tid + i * 256;
            int row = t4 >> 4, q4 = (t4 & 15) << 2;
            cpa16(&Ks[st * 8704 + row * 68 + q4], kb + (size_t)(cb + row) * 64 + q4);
        }
        #pragma unroll
        for (int i = 0; i < 8; i++) {
            int t4 = tid + i * 256;
            int row = t4 >> 4, q4 = (t4 & 15) << 2;
            cpa16(&Vs[st * 8704 + row * 68 + q4], vb + (size_t)(cb + row) * 64 + q4);
        }
        asm volatile("cp.async.commit_group;");
    };

    issue(0, 0);

    const float* qb = qlg + ((size_t)bh * NM + i0) * 64;
    #pragma unroll
    for (int i = 0; i < 4; i++) {
        int t4 = tid + i * 256; int row = t4 >> 4, kq = (t4 & 15) << 2;
        float4 v = *(const float4*)(qb + row * 64 + kq);
        float vv[4] = {v.x, v.y, v.z, v.w};
        #pragma unroll
        for (int j = 0; j < 4; j++) {
            int kk = kq + j;
            Qs[kk * 128 + (row & 7) * 16 + ((row >> 3) ^ ((kk & 3) << 2))] = to_tf32(vv[j]);
        }
    }

    float4 acc2[2][2];
    #pragma unroll
    for (int i = 0; i < 2; i++)
        #pragma unroll
        for (int j = 0; j < 2; j++) acc2[i][j] = make_float4(0.f, 0.f, 0.f, 0.f);
    float Mrun[4] = {-1e30f, -1e30f, -1e30f, -1e30f};
    float Lrun[4] = {0.f, 0.f, 0.f, 0.f};

    for (int jt = 0; jt < SEQ / 128; jt++) {
        const int cur = jt & 1;
        if (jt + 1 < SEQ / 128) {
            issue(jt + 1, cur ^ 1);
            asm volatile("cp.async.wait_group 1;");
        } else {
            asm volatile("cp.async.wait_group 0;");
        }
        __syncthreads();

        const float* Kc = Ks + cur * 8704;
        const float* Vc = Vs + cur * 8704;

        float4 acc1[2][4];
        #pragma unroll
        for (int i = 0; i < 2; i++)
            #pragma unroll
            for (int j = 0; j < 4; j++) acc1[i][j] = make_float4(0.f, 0.f, 0.f, 0.f);
        #pragma unroll
        for (int s8 = 0; s8 < 64; s8 += 8) {
            const int k0 = s8 + tg;
            float4 aLo = *(const float4*)&Qs[k0 * 128 + g * 16 + ((wm * 4) ^ sw)];
            float4 aHi = *(const float4*)&Qs[(k0 + 4) * 128 + g * 16 + ((wm * 4) ^ sw)];
            float am[2][4] = {{aLo.x, aLo.y, aHi.x, aHi.y}, {aLo.z, aLo.w, aHi.z, aHi.w}};
            #pragma unroll
            for (int nt = 0; nt < 4; nt++) {
                const float* kr = Kc + (wn * 32 + nt * 8 + g) * 68;
                float b0 = kr[k0], b1 = kr[k0 + 4];
                #pragma unroll
                for (int mt = 0; mt < 2; mt++)
                    mma8(acc1[mt][nt], am[mt][0], am[mt][1], am[mt][2], am[mt][3], b0, b1);
            }
        }

        float tmax[4];
        #pragma unroll
        for (int t = 0; t < 4; t++) {
            const int mt = t >> 1; const bool hi = t & 1;
            float m = -1e30f;
            #pragma unroll
            for (int nt = 0; nt < 4; nt++) {
                float4 a = acc1[mt][nt];
                m = fmaxf(m, hi ? fmaxf(a.z, a.w) : fmaxf(a.x, a.y));
            }
            m = fmaxf(m, __shfl_xor_sync(0xffffffffu, m, 1));
            m = fmaxf(m, __shfl_xor_sync(0xffffffffu, m, 2));
            tmax[t] = m;
        }
        if (tg == 0) {
            #pragma unroll
            for (int t = 0; t < 4; t++) Mp[wn * 64 + wm * 32 + 8 * t + g] = tmax[t];
        }
        __syncthreads();

        float f[4];
        #pragma unroll
        for (int t = 0; t < 4; t++) {
            const int rl = wm * 32 + 8 * t + g;
            float tm = fmaxf(fmaxf(Mp[rl], Mp[64 + rl]),
                             fmaxf(Mp[128 + rl], Mp[192 + rl]));
            float Mn = fmaxf(Mrun[t], tm);
            f[t] = __expf(Mrun[t] - Mn);
            Mrun[t] = Mn;
        }
        #pragma unroll
        for (int mt2 = 0; mt2 < 2; mt2++)
            #pragma unroll
            for (int nt2 = 0; nt2 < 2; nt2++) {
                acc2[mt2][nt2].x *= f[2 * mt2];     acc2[mt2][nt2].y *= f[2 * mt2];
                acc2[mt2][nt2].z *= f[2 * mt2 + 1]; acc2[mt2][nt2].w *= f[2 * mt2 + 1];
            }
        #pragma unroll
        for (int t = 0; t < 4; t++) {
            const int mt = t >> 1; const bool hi = t & 1;
            const int rl = wm * 32 + 8 * t + g;
            const float M = Mrun[t];
            float s = 0.f;
            #pragma unroll
            for (int nt = 0; nt < 4; nt++) {
                float4 a = acc1[mt][nt];
                float v0 = hi ? a.z : a.x, v1 = hi ? a.w : a.y;
                float e0 = __expf(v0 - M), e1 = __expf(v1 - M);
                s += e0 + e1;
                int c0 = wn * 32 + nt * 8 + 2 * tg;
                Ps[rl * 132 + c0] = e0;
                Ps[rl * 132 + c0 + 1] = e1;
            }
            s += __shfl_xor_sync(0xffffffffu, s, 1);
            s += __shfl_xor_sync(0xffffffffu, s, 2);
            if (tg == 0) Lp[wn * 64 + rl] = s;
        }
        __syncthreads();
        #pragma unroll
        for (int t = 0; t < 4; t++) {
            const int rl = wm * 32 + 8 * t + g;
            Lrun[t] = Lrun[t] * f[t] + (Lp[rl] + Lp[64 + rl] + Lp[128 + rl] + Lp[192 + rl]);
        }

        #pragma unroll 4
        for (int s8 = 0; s8 < 128; s8 += 8) {
            const int k0 = s8 + tg, k1 = k0 + 4;
            float a_[2][4], b_[2][2];
            #pragma unroll
            for (int mt2 = 0; mt2 < 2; mt2++) {
                const int r0 = wm * 32 + 16 * mt2 + g;
                a_[mt2][0] = Ps[r0 * 132 + k0];
                a_[mt2][1] = Ps[(r0 + 8) * 132 + k0];
                a_[mt2][2] = Ps[r0 * 132 + k1];
                a_[mt2][3] = Ps[(r0 + 8) * 132 + k1];
            }
            #pragma unroll
            for (int nt2 = 0; nt2 < 2; nt2++) {
                const int c = wn * 16 + nt2 * 8 + g;
                b_[nt2][0] = Vc[k0 * 68 + c];
                b_[nt2][1] = Vc[k1 * 68 + c];
            }
            #pragma unroll
            for (int mt2 = 0; mt2 < 2; mt2++)
                #pragma unroll
                for (int nt2 = 0; nt2 < 2; nt2++)
                    mma8(acc2[mt2][nt2], a_[mt2][0], a_[mt2][1], a_[mt2][2], a_[mt2][3],
                         b_[nt2][0], b_[nt2][1]);
        }
        __syncthreads();
    }

    float invL[4];
    #pragma unroll
    for (int t = 0; t < 4; t++) invL[t] = 1.f / Lrun[t];
    float* ob = c2 + ((size_t)bh * NM + i0) * 64;
    #pragma unroll
    for (int mt2 = 0; mt2 < 2; mt2++) {
        #pragma unroll
        for (int nt2 = 0; nt2 < 2; nt2++) {
            const int c = wn * 16 + nt2 * 8 + 2 * tg;
            const int r0 = wm * 32 + 16 * mt2 + g;
            float4 v = acc2[mt2][nt2];
            float2 lo; lo.x = v.x * invL[2 * mt2];     lo.y = v.y * invL[2 * mt2];
            float2 hi; hi.x = v.z * invL[2 * mt2 + 1]; hi.y = v.w * invL[2 * mt2 + 1];
            *(float2*)&ob[(size_t)r0 * 64 + c] = lo;
            *(float2*)&ob[(size_t)(r0 + 8) * 64 + c] = hi;
        }
    }
}

// =====================================================================
// Fused attn1 path + depthwise-conv residual + transpose into Y.
// O(64x64) = softmax(q_tile @ kl^T) @ Cm ; Y[b*n][h*64+d] = O + conv33(v)
// =====================================================================
#define FA1_SMEM (169984)
__global__ __launch_bounds__(256)
void k_fattn1(const float* __restrict__ qg, const float* __restrict__ klg,
              const float* __restrict__ cmg, const float* __restrict__ vg,
              const float* __restrict__ wres, float* __restrict__ Yg)
{
    extern __shared__ float sm[];
    float* Qs   = sm;                    // stage1: A-layout Q; later: Vw[96][64] + w[33]
    float* Ks   = sm + 8192;             // [kk<64][g<8][x<32]
    float* Ps   = sm + 8192;             // [k<256][g<8][x<8]   (aliases Ks)
    float* Cs   = sm + 24576;            // [k<256][c<68]; later Osm[64][68]
    float* Mred = sm + 24576 + 17408;    // [4][64]
    float* Lred = Mred + 256;            // [4][64]

    const int bh = blockIdx.y, b = bh >> 3, h = bh & 7;
    const int i0 = blockIdx.x * 64;
    const int tid = threadIdx.x;
    const int lane = tid & 31, g = lane >> 2, tg = lane & 3;
    const int wid = tid >> 5, wm = wid & 1, wn = wid >> 1;
    const int sw = tg << 2;

    const float* qb = qg + ((size_t)bh * SEQ + i0) * 64;
    #pragma unroll
    for (int i = 0; i < 4; i++) {
        int t4 = tid + i * 256; int row = t4 >> 4, kq = (t4 & 15) << 2;
        float4 v = *(const float4*)(qb + row * 64 + kq);
        float vv[4] = {v.x, v.y, v.z, v.w};
        #pragma unroll
        for (int j = 0; j < 4; j++) {
            int kk = kq + j;
            Qs[kk * 128 + (row & 7) * 16 + ((row >> 3) ^ ((kk & 3) << 2))] = to_tf32(vv[j]);
        }
    }
    const float* kb = klg + (size_t)bh * NM * 64;
    #pragma unroll
    for (int i = 0; i < 16; i++) {
        int t4 = tid + i * 256; int l = t4 >> 4, kq = (t4 & 15) << 2;
        float4 v = *(const float4*)(kb + l * 64 + kq);
        float vv[4] = {v.x, v.y, v.z, v.w};
        #pragma unroll
        for (int j = 0; j < 4; j++) {
            int kk = kq + j;
            Ks[kk * 256 + (l & 7) * 32 + ((l >> 3) ^ ((kk & 3) << 2))] = to_tf32(vv[j]);
        }
    }
    const float* cb = cmg + (size_t)bh * NM * 64;
    #pragma unroll
    for (int i = 0; i < 16; i++) {
        int t4 = tid + i * 256; int k = t4 >> 4, nq = (t4 & 15) << 2;
        float4 v = *(const float4*)(cb + k * 64 + nq);
        float4 w; w.x = to_tf32(v.x); w.y = to_tf32(v.y);
        w.z = to_tf32(v.z); w.w = to_tf32(v.w);
        *(float4*)&Cs[k * 68 + nq] = w;
    }
    __syncthreads();

    // stage 1: scores 64x256
    float4 acc1[2][8];
    #pragma unroll
    for (int i = 0; i < 2; i++)
        #pragma unroll
        for (int j = 0; j < 8; j++) acc1[i][j] = make_float4(0.f, 0.f, 0.f, 0.f);

    #pragma unroll
    for (int s8 = 0; s8 < 64; s8 += 8) {
        const int k0 = s8 + tg;
        float4 aLo = *(const float4*)&Qs[k0 * 128 + g * 16 + ((wm * 4) ^ sw)];
        float4 aHi = *(const float4*)&Qs[(k0 + 4) * 128 + g * 16 + ((wm * 4) ^ sw)];
        float4 b0l = *(const float4*)&Ks[k0 * 256 + g * 32 + ((wn * 8) ^ sw)];
        float4 b0h = *(const float4*)&Ks[k0 * 256 + g * 32 + ((wn * 8 + 4) ^ sw)];
        float4 b1l = *(const float4*)&Ks[(k0 + 4) * 256 + g * 32 + ((wn * 8) ^ sw)];
        float4 b1h = *(const float4*)&Ks[(k0 + 4) * 256 + g * 32 + ((wn * 8 + 4) ^ sw)];
        float bb0[8] = {b0l.x, b0l.y, b0l.z, b0l.w, b0h.x, b0h.y, b0h.z, b0h.w};
        float bb1[8] = {b1l.x, b1l.y, b1l.z, b1l.w, b1h.x, b1h.y, b1h.z, b1h.w};
        float am[2][4] = {{aLo.x, aLo.y, aHi.x, aHi.y}, {aLo.z, aLo.w, aHi.z, aHi.w}};
        #pragma unroll
        for (int mt = 0; mt < 2; mt++)
            #pragma unroll
            for (int nt = 0; nt < 8; nt++)
                mma8(acc1[mt][nt], am[mt][0], am[mt][1], am[mt][2], am[mt][3],
                     bb0[nt], bb1[nt]);
    }

    float rmax[4];
    #pragma unroll
    for (int t = 0; t < 4; t++) {
        const int mt = t >> 1; const bool hi = t & 1;
        float m = -1e30f;
        #pragma unroll
        for (int nt = 0; nt < 8; nt++) {
            float4 a = acc1[mt][nt];
            m = fmaxf(m, hi ? fmaxf(a.z, a.w) : fmaxf(a.x, a.y));
        }
        m = fmaxf(m, __shfl_xor_sync(0xffffffffu, m, 1));
        m = fmaxf(m, __shfl_xor_sync(0xffffffffu, m, 2));
        rmax[t] = m;
    }
    if (tg == 0) {
        #pragma unroll
        for (int t = 0; t < 4; t++) Mred[wn * 64 + 32 * wm + 8 * t + g] = rmax[t];
    }
    __syncthreads();   // guards Qs reuse + Ks -> Ps reuse

    // prefetch v window for conv (Qs region dead) + conv weights
    {
        const float* vb = vg + (size_t)bh * SEQ * DH;
        #pragma unroll
        for (int i2 = 0; i2 < 6; i2++) {
            int id = tid + i2 * 256;                 // 1536 chunks = 96 rows x 16
            int j = id >> 4, d4 = (id & 15) << 2;
            int gi = i0 - 16 + j;
            bool ok = (gi >= 0 && gi < SEQ);
            cpa16z(&Qs[j * 64 + d4], vb + (size_t)(ok ? gi : 0) * 64 + d4, ok);
        }
        if (tid < 33) Qs[6144 + tid] = wres[h * 33 + tid];
        asm volatile("cp.async.commit_group;");
    }

    #pragma unroll
    for (int t = 0; t < 4; t++) {
        const int rl = 32 * wm + 8 * t + g;
        rmax[t] = fmaxf(fmaxf(Mred[rl], Mred[64 + rl]),
                        fmaxf(Mred[128 + rl], Mred[192 + rl]));
    }
    #pragma unroll
    for (int t = 0; t < 4; t++) {
        const int mt = t >> 1; const bool hi = t & 1;
        const int rl = 32 * wm + 8 * t + g;
        const int rh = rl >> 3;
        const float M = rmax[t];
        float s = 0.f;
        #pragma unroll
        for (int nt = 0; nt < 8; nt++) {
            float4 a = acc1[mt][nt];
            float v0 = hi ? a.z : a.x, v1 = hi ? a.w : a.y;
            float e0 = __expf(v0 - M), e1 = __expf(v1 - M);
            s += e0 + e1;
            int c0 = wn * 64 + nt * 8 + 2 * tg;
            Ps[c0 * 64 + g * 8 + (rh ^ (c0 & 7))] = to_tf32(e0);
            Ps[(c0 + 1) * 64 + g * 8 + (rh ^ ((c0 + 1) & 7))] = to_tf32(e1);
        }
        s += __shfl_xor_sync(0xffffffffu, s, 1);
        s += __shfl_xor_sync(0xffffffffu, s, 2);
        if (tg == 0) Lred[wn * 64 + rl] = s;
    }
    __syncthreads();

    // stage 2: O = P(64x256) @ Cm(256x64)
    float4 acc2[2][2];
    #pragma unroll
    for (int i = 0; i < 2; i++)
        #pragma unroll
        for (int j = 0; j < 2; j++) acc2[i][j] = make_float4(0.f, 0.f, 0.f, 0.f);

    #pragma unroll 4
    for (int s8 = 0; s8 < 256; s8 += 8) {
        const int k0 = s8 + tg, k1 = k0 + 4;
        float a_[2][4], b_[2][2];
        #pragma unroll
        for (int mt = 0; mt < 2; mt++) {
            const int rh = 4 * wm + 2 * mt;
            a_[mt][0] = Ps[k0 * 64 + g * 8 + (rh ^ (k0 & 7))];
            a_[mt][1] = Ps[k0 * 64 + g * 8 + ((rh + 1) ^ (k0 & 7))];
            a_[mt][2] = Ps[k1 * 64 + g * 8 + (rh ^ (k1 & 7))];
            a_[mt][3] = Ps[k1 * 64 + g * 8 + ((rh + 1) ^ (k1 & 7))];
        }
        #pragma unroll
        for (int nt = 0; nt < 2; nt++) {
            const int c = wn * 16 + nt * 8 + g;
            b_[nt][0] = Cs[k0 * 68 + c];
            b_[nt][1] = Cs[k1 * 68 + c];
        }
        #pragma unroll
        for (int mt = 0; mt < 2; mt++)
            #pragma unroll
            for (int nt = 0; nt < 2; nt++)
                mma8(acc2[mt][nt], a_[mt][0], a_[mt][1], a_[mt][2], a_[mt][3],
                     b_[nt][0], b_[nt][1]);
    }

    float invL[4];
    #pragma unroll
    for (int t = 0; t < 4; t++) {
        const int rl = 32 * wm + 8 * t + g;
        float L = Lred[rl] + Lred[64 + rl] + Lred[128 + rl] + Lred[192 + rl];
        invL[t] = 1.f / L;
    }

    asm volatile("cp.async.wait_group 0;");
    __syncthreads();    // stage2 reads of Cs done; Vw ready

    // stage scaled O into Osm (= Cs region, [64][68])
    #pragma unroll
    for (int mt = 0; mt < 2; mt++) {
        #pragma unroll
        for (int nt = 0; nt < 2; nt++) {
            const int c = wn * 16 + nt * 8 + 2 * tg;
            const int r0 = 32 * wm + 16 * mt + g;
            float4 v = acc2[mt][nt];
            float2 lo; lo.x = v.x * invL[2 * mt]; lo.y = v.y * invL[2 * mt];
            float2 hi; hi.x = v.z * invL[2 * mt + 1]; hi.y = v.w * invL[2 * mt + 1];
            *(float2*)&Cs[r0 * 68 + c] = lo;
            *(float2*)&Cs[(r0 + 8) * 68 + c] = hi;
        }
    }
    __syncthreads();

    // conv + write to Y (transposed layout)
    const float* wv = Qs + 6144;
    #pragma unroll
    for (int i2 = 0; i2 < 4; i2++) {
        int l4 = tid + i2 * 256;            // 1024 float4s = 64 rows x 16
        int i = l4 >> 4, d4 = (l4 & 15) << 2;
        float4 o = *(float4*)&Cs[i * 68 + d4];
        #pragma unroll
        for (int t = 0; t < 33; t++) {
            float wt = wv[t];
            float4 vv = *(float4*)&Qs[(i + t) * 64 + d4];
            o.x += wt * vv.x; o.y += wt * vv.y; o.z += wt * vv.z; o.w += wt * vv.w;
        }
        *(float4*)&Yg[(size_t)(b * SEQ + i0 + i) * DM + h * 64 + d4] = o;
    }
}

// landmarks: mean over 32 consecutive tokens
__global__ void k_land() {
    int idx = blockIdx.x * blockDim.x + threadIdx.x;   // BH*NM*DH
    int d = idx & 63, i = (idx >> 6) & 255, bh = idx >> 14;
    size_t base = (size_t)bh * SEQ * DH + (size_t)i * LG * DH + d;
    float qs = 0.f, ks = 0.f;
    #pragma unroll 8
    for (int j = 0; j < LG; j++) { qs += g_q[base + j * 64]; ks += g_k[base + j * 64]; }
    g_ql[idx] = qs * (1.f / LG);
    g_kl[idx] = ks * (1.f / LG);
}

// Row softmax (in place), 256 cols, one block per row.
__global__ void k_softmax(float* __restrict__ X) {
    const size_t base = (size_t)blockIdx.x * 256;
    const int tid = threadIdx.x, lane = tid & 31, wp = tid >> 5;
    __shared__ float red[8];
    float v = X[base + tid];
    float m = v;
    #pragma unroll
    for (int off = 16; off; off >>= 1) m = fmaxf(m, __shfl_xor_sync(0xffffffffu, m, off));
    if (!lane) red[wp] = m;
    __syncthreads();
    float M = red[0];
    #pragma unroll
    for (int w = 1; w < 8; w++) M = fmaxf(M, red[w]);
    __syncthreads();
    float e = __expf(v - M);
    float s = e;
    #pragma unroll
    for (int off = 16; off; off >>= 1) s += __shfl_xor_sync(0xffffffffu, s, off);
    if (!lane) red[wp] = s;
    __syncthreads();
    float S = 0.f;
    #pragma unroll
    for (int w = 0; w < 8; w++) S += red[w];
    X[base + tid] = e / S;
}

// global max of row-sums (axis -1) and col-sums (axis -2) over ALL bh
__global__ void k_reset() { if (threadIdx.x < 2) g_mx[threadIdx.x] = 0u; }

__global__ void k_colrowmax() {
    const int bh = blockIdx.x, tid = threadIdx.x, lane = tid & 31, wp = tid >> 5;
    __shared__ float red[8];
    const float* Xb = g_X + (size_t)bh * NM * NM;
    float cs = 0.f;
    for (int i = 0; i < NM; i++) cs += Xb[i * NM + tid];
    float m = cs;
    #pragma unroll
    for (int off = 16; off; off >>= 1) m = fmaxf(m, __shfl_xor_sync(0xffffffffu, m, off));
    if (!lane) red[wp] = m;
    __syncthreads();
    if (tid == 0) {
        float M = red[0];
        #pragma unroll
        for (int w = 1; w < 8; w++) M = fmaxf(M, red[w]);
        atomicMax(&g_mx[1], __float_as_uint(M));
    }
    __syncthreads();
    float rs = 0.f;
    const float* Xr = Xb + (size_t)tid * NM;
    for (int j = 0; j < NM; j++) rs += Xr[j];
    m = rs;
    #pragma unroll
    for (int off = 16; off; off >>= 1) m = fmaxf(m, __shfl_xor_sync(0xffffffffu, m, off));
    if (!lane) red[wp] = m;
    __syncthreads();
    if (tid == 0) {
        float M = red[0];
        #pragma unroll
        for (int w = 1; w < 8; w++) M = fmaxf(M, red[w]);
        atomicMax(&g_mx[0], __float_as_uint(M));
    }
}

__global__ void k_zinit() {
    int idx = blockIdx.x * blockDim.x + threadIdx.x;   // BH*NM*NM
    float inv = 1.f / (__uint_as_float(g_mx[0]) * __uint_as_float(g_mx[1]));
    int j = idx & 255, i = (idx >> 8) & 255, bh = idx >> 16;
    g_Za[idx] = g_X[(size_t)bh * NM * NM + j * NM + i] * inv;
}

// =====================================================================
extern "C" void kernel_launch(void* const* d_in, const int* in_sizes, int n_in,
                              void* d_out, int out_size) {
    const float* x     = (const float*)d_in[0];
    const float* w_qkv = (const float*)d_in[1];
    const float* w_out = (const float*)d_in[2];
    const float* b_out = (const float*)d_in[3];
    const float* w_res = (const float*)d_in[4];
    float* out = (float*)d_out;

    float *q, *k_, *v, *ql, *kl, *X, *Za, *Zb, *XZ, *T1, *T2, *C2, *Cm, *Y;
    cudaGetSymbolAddress((void**)&q,   g_q);
    cudaGetSymbolAddress((void**)&k_,  g_k);
    cudaGetSymbolAddress((void**)&v,   g_v);
    cudaGetSymbolAddress((void**)&ql,  g_ql);
    cudaGetSymbolAddress((void**)&kl,  g_kl);
    cudaGetSymbolAddress((void**)&X,   g_X);
    cudaGetSymbolAddress((void**)&Za,  g_Za);
    cudaGetSymbolAddress((void**)&Zb,  g_Zb);
    cudaGetSymbolAddress((void**)&XZ,  g_XZ);
    cudaGetSymbolAddress((void**)&T1,  g_T1);
    cudaGetSymbolAddress((void**)&T2,  g_T2);
    cudaGetSymbolAddress((void**)&C2,  g_C2);
    cudaGetSymbolAddress((void**)&Cm,  g_Cm);
    cudaGetSymbolAddress((void**)&Y,   g_Y);

    // dynamic smem opt-in (floats: A 3*2560; B per layout)
    const int SM_NN128 = (3 * 2560 + 3 * 16 * 136) * 4;   // 56832
    const int SM_TN128 = (3 * 2560 + 3 * 128 * 20) * 4;   // 61440
    const int SM_NN64  = (3 * 2560 + 3 * 16 * 72) * 4;    // 44544
    cudaFuncSetAttribute(t_gemm<128, 2, false, 1>, cudaFuncAttributeMaxDynamicSharedMemorySize, SM_NN128);
    cudaFuncSetAttribute(t_gemm<128, 2, false, 0>, cudaFuncAttributeMaxDynamicSharedMemorySize, SM_NN128);
    cudaFuncSetAttribute(t_gemm<128, 2, true, 0>,  cudaFuncAttributeMaxDynamicSharedMemorySize, SM_TN128);
    cudaFuncSetAttribute(t_gemm<64, 1, false, 0>,  cudaFuncAttributeMaxDynamicSharedMemorySize, SM_NN64);
    cudaFuncSetAttribute(k_fattn1, cudaFuncAttributeMaxDynamicSharedMemorySize, FA1_SMEM);
    cudaFuncSetAttribute(k_fattn3, cudaFuncAttributeMaxDynamicSharedMemorySize, FA3_SMEM);

    const float* NUL = (const float*)0;
    float* NULF = (float*)0;

    // 1. qkv = x @ w_qkv, scattered directly to packed q (scaled), k, v
    t_gemm<128, 2, false, 1><<<dim3(TRIPLE / 128, ROWS / 128, 1), 256, SM_NN128>>>(
        x, DM, 0LL, w_qkv, TRIPLE, 0LL, NUL, 0LL, NUL, q, TRIPLE, 0LL,
        DM, 1.f, 0.f, 1, q, k_, v);
    // 2. landmarks
    k_land<<<(BH * NM * DH) / 256, 256>>>();
    // 3. attn2 = softmax(q_land @ k_land^T)
    t_gemm<128, 2, true, 0><<<dim3(2, 2, BH), 256, SM_TN128>>>(
        ql, DH, 16384LL, kl, DH, 16384LL, NUL, 0LL, NUL, X, NM, 65536LL,
        DH, 1.f, 0.f, 1, NULF, NULF, NULF);
    k_softmax<<<BH * NM, 256>>>(X);
    // 4. pinv init
    k_reset<<<1, 32>>>();
    k_colrowmax<<<BH, 256>>>();
    k_zinit<<<(BH * NM * NM) / 256, 256>>>();
    // 5. 6 Newton iterations
    float* Zc = Za; float* Zn = Zb;
    for (int it = 0; it < 6; it++) {
        t_gemm<128, 2, false, 0><<<dim3(2, 2, BH), 256, SM_NN128>>>(
            X, NM, 65536LL, Zc, NM, 65536LL, NUL, 0LL, NUL, XZ, NM, 65536LL,
            NM, 1.f, 0.f, 1, NULF, NULF, NULF);
        t_gemm<128, 2, false, 0><<<dim3(2, 2, BH), 256, SM_NN128>>>(
            XZ, NM, 65536LL, XZ, NM, 65536LL, XZ, 65536LL, NUL, T1, NM, 65536LL,
            NM, -1.f, 7.f, 1, NULF, NULF, NULF);
        t_gemm<128, 2, false, 0><<<dim3(2, 2, BH), 256, SM_NN128>>>(
            XZ, NM, 65536LL, T1, NM, 65536LL, XZ, 65536LL, NUL, T2, NM, 65536LL,
            NM, -1.f, 15.f, 1, NULF, NULF, NULF);
        t_gemm<128, 2, false, 0><<<dim3(2, 2, BH), 256, SM_NN128>>>(
            Zc, NM, 65536LL, T2, NM, 65536LL, Zc, 65536LL, NUL, Zn, NM, 65536LL,
            NM, -0.25f, 3.25f, 1, NULF, NULF, NULF);
        float* tmp = Zc; Zc = Zn; Zn = tmp;
    }
    // 6. fused flash sim3 path: C2 = softmax(ql @ k^T) @ v
    k_fattn3<<<dim3(4, BH), 256, FA3_SMEM>>>(ql, k_, v, C2);
    // 7. Cm = Z @ C2
    t_gemm<64, 1, false, 0><<<dim3(1, 2, BH), 128, SM_NN64>>>(
        Zc, NM, 65536LL, C2, DH, 16384LL, NUL, 0LL, NUL, Cm, DH, 16384LL,
        NM, 1.f, 0.f, 1, NULF, NULF, NULF);
    // 8. fused: Y = softmax(q @ kl^T) @ Cm + conv33(v), transposed
    k_fattn1<<<dim3(SEQ / 64, BH), 256, FA1_SMEM>>>(q, kl, Cm, v, w_res, Y);
    // 9. out = Y @ w_out + b_out
    t_gemm<128, 2, false, 0><<<dim3(DM / 128, ROWS / 128, 1), 256, SM_NN128>>>(
        Y, DM, 0LL, w_out, DM, 0LL, NUL, 0LL, b_out, out, DM, 0LL,
        DM, 1.f, 0.f, 1, NULF, NULF, NULF);
}

// round 12
// speedup vs baseline: 2.4922x; 1.0526x over previous
#include <cuda_runtime.h>
#include <cuda_bf16.h>
#include <math.h>

#define NB      4
#define SEQ     8192
#define DM      512
#define NH      8
#define DH      64
#define NM      256
#define LG      32
#define BH      32          // NB*NH
#define TRIPLE  1536
#define ROWS    32768       // NB*SEQ

// ---------------- scratch (device globals; no allocations allowed) -------
__device__ float g_q [(size_t)BH * SEQ * DH];         // packed, pre-scaled by dh^-0.5
__device__ float g_k [(size_t)BH * SEQ * DH];
__device__ float g_v [(size_t)BH * SEQ * DH];
__device__ float g_ql[BH * NM * DH];
__device__ float g_kl[BH * NM * DH];
__device__ float g_X [BH * NM * NM];                  // attn2
__device__ float g_Za[BH * NM * NM];
__device__ float g_Zb[BH * NM * NM];
__device__ float g_XZ[BH * NM * NM];
__device__ float g_T1[BH * NM * NM];
__device__ float g_T2[BH * NM * NM];
__device__ float g_C2[BH * NM * DH];                  // softmax(sim3) @ v
__device__ float g_Cm[BH * NM * DH];                  // Z @ C2
__device__ float g_Y [(size_t)ROWS * DM];             // pre-out-proj
__device__ unsigned int g_mx[2];
__device__ unsigned int g_bar[BH];                    // pinv inter-CTA barrier

// ---------------- helpers ----------------
__device__ __forceinline__ float to_tf32(float x) {
    unsigned u; asm("cvt.rna.tf32.f32 %0, %1;" : "=r"(u) : "f"(x));
    return __uint_as_float(u);
}
__device__ __forceinline__ void mma8(float4& d, float a0, float a1, float a2, float a3,
                                     float b0, float b1) {
    asm volatile(
        "mma.sync.aligned.m16n8k8.row.col.f32.tf32.tf32.f32 "
        "{%0,%1,%2,%3}, {%4,%5,%6,%7}, {%8,%9}, {%0,%1,%2,%3};"
        : "+f"(d.x), "+f"(d.y), "+f"(d.z), "+f"(d.w)
        : "r"(__float_as_uint(a0)), "r"(__float_as_uint(a1)),
          "r"(__float_as_uint(a2)), "r"(__float_as_uint(a3)),
          "r"(__float_as_uint(b0)), "r"(__float_as_uint(b1)));
}
__device__ __forceinline__ void cpa16(void* s, const void* g) {
    unsigned sa = (unsigned)__cvta_generic_to_shared(s);
    asm volatile("cp.async.cg.shared.global [%0], [%1], 16;" :: "r"(sa), "l"(g));
}
__device__ __forceinline__ void cpa16z(void* s, const void* g, bool ok) {
    unsigned sa = (unsigned)__cvta_generic_to_shared(s);
    int sz = ok ? 16 : 0;
    asm volatile("cp.async.cg.shared.global [%0], [%1], 16, %2;" :: "r"(sa), "l"(g), "r"(sz));
}

// =====================================================================
// TF32 tensor-core GEMM, cp.async 3-stage pipeline, register-side RNA cvt.
// BM=128, BN in {128,64}. BK=16.
// smem: As[3][128][20]; TN B: Bs[3][BN][20]; NN B: Bs[3][16][BN+8].
// EPI==0: C = alpha*(A@B[^T]) + beta*D (+bias)
// EPI==1: qkv scatter epilogue into q/k/v (q scaled by 0.125)
// =====================================================================
template<int BN, int WARPS_N, bool TRANSB, int EPI>
__global__ __launch_bounds__(128 * WARPS_N)
void t_gemm(const float* __restrict__ A, int lda, long long sA,
            const float* __restrict__ B, int ldb, long long sB,
            const float* __restrict__ D, long long sD,
            const float* __restrict__ bias,
            float* __restrict__ C, int ldc, long long sC,
            int K, float alpha, float beta, int ksplit,
            float* __restrict__ qp, float* __restrict__ kp, float* __restrict__ vp)
{
    constexpr int NT   = 128 * WARPS_N;
    constexpr int ASTG = 128 * 20;
    constexpr int BSTG = TRANSB ? BN * 20 : 16 * (BN + 8);
    constexpr int ACH  = 512 / NT;        // 16B chunks per thread per stage
    constexpr int BCH  = 4 * BN / NT;
    extern __shared__ float smp[];
    float* As = smp;
    float* Bs = smp + 3 * ASTG;

    const int tid = threadIdx.x;
    const int z = blockIdx.z;
    const int bh = z / ksplit, sk = z - bh * ksplit;
    const float* Ab = A + (size_t)bh * sA + (size_t)blockIdx.y * 128 * lda + (size_t)sk * K;
    const float* Bb;
    if (TRANSB) Bb = B + (size_t)bh * sB + (size_t)blockIdx.x * BN * ldb + (size_t)sk * K;
    else        Bb = B + (size_t)bh * sB + (size_t)sk * K * ldb + blockIdx.x * BN;

    const int lane = tid & 31, g = lane >> 2, tg = lane & 3;
    const int wid = tid >> 5, wm = wid & 3, wn = wid >> 2;

    auto issue = [&](int kb, int st) {
        #pragma unroll
        for (int i = 0; i < ACH; i++) {
            int id = tid + i * NT;
            int row = id >> 2, c4 = id & 3;
            cpa16(&As[st * ASTG + row * 20 + c4 * 4],
                  Ab + (size_t)row * lda + kb * 16 + c4 * 4);
        }
        #pragma unroll
        for (int i = 0; i < BCH; i++) {
            int id = tid + i * NT;
            if constexpr (TRANSB) {
                int row = id >> 2, c4 = id & 3;
                cpa16(&Bs[st * BSTG + row * 20 + c4 * 4],
                      Bb + (size_t)row * ldb + kb * 16 + c4 * 4);
            } else {
                int kr = id / (BN / 4), n4 = id % (BN / 4);
                cpa16(&Bs[st * BSTG + kr * (BN + 8) + n4 * 4],
                      Bb + (size_t)(kb * 16 + kr) * ldb + n4 * 4);
            }
        }
        asm volatile("cp.async.commit_group;");
    };

    float4 acc[2][8];
    #pragma unroll
    for (int i = 0; i < 2; i++)
        #pragma unroll
        for (int j = 0; j < 8; j++) acc[i][j] = make_float4(0.f, 0.f, 0.f, 0.f);

    const int kblocks = K >> 4;
    issue(0, 0); issue(1, 1);
    for (int kb = 0; kb < kblocks; kb++) {
        if (kb + 1 < kblocks) { asm volatile("cp.async.wait_group 1;"); }
        else                  { asm volatile("cp.async.wait_group 0;"); }
        __syncthreads();
        if (kb + 2 < kblocks) issue(kb + 2, (kb + 2) % 3);
        const float* Ac = As + (kb % 3) * ASTG;
        const float* Bc = Bs + (kb % 3) * BSTG;
        #pragma unroll
        for (int s8 = 0; s8 < 16; s8 += 8) {
            float a[2][4];
            #pragma unroll
            for (int mt = 0; mt < 2; mt++) {
                const int Rm = wm * 32 + mt * 16 + g;
                a[mt][0] = to_tf32(Ac[Rm * 20 + s8 + tg]);
                a[mt][1] = to_tf32(Ac[(Rm + 8) * 20 + s8 + tg]);
                a[mt][2] = to_tf32(Ac[Rm * 20 + s8 + tg + 4]);
                a[mt][3] = to_tf32(Ac[(Rm + 8) * 20 + s8 + tg + 4]);
            }
            #pragma unroll
            for (int nt = 0; nt < 8; nt++) {
                const int c = wn * 64 + nt * 8 + g;
                float b0, b1;
                if constexpr (TRANSB) {
                    b0 = to_tf32(Bc[c * 20 + s8 + tg]);
                    b1 = to_tf32(Bc[c * 20 + s8 + tg + 4]);
                } else {
                    b0 = to_tf32(Bc[(s8 + tg) * (BN + 8) + c]);
                    b1 = to_tf32(Bc[(s8 + tg + 4) * (BN + 8) + c]);
                }
                #pragma unroll
                for (int mt = 0; mt < 2; mt++)
                    mma8(acc[mt][nt], a[mt][0], a[mt][1], a[mt][2], a[mt][3], b0, b1);
            }
        }
    }

    // epilogue
    const int r00 = blockIdx.y * 128 + wm * 32;
    #pragma unroll
    for (int mt = 0; mt < 2; mt++) {
        #pragma unroll
        for (int nt = 0; nt < 8; nt++) {
            const int r0 = r00 + mt * 16 + g;
            const int cb = blockIdx.x * BN + wn * 64 + nt * 8 + tg * 2;
            float4 v = acc[mt][nt];
            if constexpr (EPI == 1) {
                const int which = cb >> 9, rem = cb & 511;
                const int h = rem >> 6, d = rem & 63;
                const float s = (which == 0) ? 0.125f : 1.0f;
                float* dst = (which == 0) ? qp : ((which == 1) ? kp : vp);
                int b = r0 >> 13, ii = r0 & 8191;
                float2 lo; lo.x = v.x * s; lo.y = v.y * s;
                *(float2*)&dst[(((size_t)(b * 8 + h) * 8192 + ii) << 6) + d] = lo;
                const int r1 = r0 + 8; b = r1 >> 13; ii = r1 & 8191;
                float2 hi; hi.x = v.z * s; hi.y = v.w * s;
                *(float2*)&dst[(((size_t)(b * 8 + h) * 8192 + ii) << 6) + d] = hi;
            } else {
                float* Cb = C + (size_t)z * sC;
                const float* Db = D + (size_t)bh * sD;
                float2 lo, hi;
                lo.x = alpha * v.x; lo.y = alpha * v.y;
                hi.x = alpha * v.z; hi.y = alpha * v.w;
                if (beta != 0.f) {
                    float2 dlo = *(const float2*)&Db[(size_t)r0 * ldc + cb];
                    float2 dhi = *(const float2*)&Db[(size_t)(r0 + 8) * ldc + cb];
                    lo.x += beta * dlo.x; lo.y += beta * dlo.y;
                    hi.x += beta * dhi.x; hi.y += beta * dhi.y;
                }
                if (bias) {
                    float2 bv = *(const float2*)&bias[cb];
                    lo.x += bv.x; lo.y += bv.y; hi.x += bv.x; hi.y += bv.y;
                }
                *(float2*)&Cb[(size_t)r0 * ldc + cb] = lo;
                *(float2*)&Cb[(size_t)(r0 + 8) * ldc + cb] = hi;
            }
        }
    }
}

// =====================================================================
// Persistent pinv: 24 chained 256x256x256 GEMM steps, one launch.
// 128 CTAs, 4 per bh (by=quad>>1, bx=quad&1), inter-step per-bh barrier.
// All global reads via cp.async.cg / __ldcg (L2, L1-bypassing).
// =====================================================================
__global__ __launch_bounds__(256)
void k_pinv() {
    constexpr int ASTG = 128 * 20;
    constexpr int BSTG = 16 * 136;
    extern __shared__ float smp[];
    float* As = smp;
    float* Bs = smp + 3 * ASTG;

    const int bh = blockIdx.x >> 2;
    const int qd = blockIdx.x & 3;
    const int by = qd >> 1, bx = qd & 1;
    const int tid = threadIdx.x;
    const int lane = tid & 31, g = lane >> 2, tg = lane & 3;
    const int wid = tid >> 5, wm = wid & 3, wn = wid >> 2;

    float* Xp  = g_X  + (size_t)bh * 65536;
    float* XZp = g_XZ + (size_t)bh * 65536;
    float* T1p = g_T1 + (size_t)bh * 65536;
    float* T2p = g_T2 + (size_t)bh * 65536;
    float* Zc  = g_Za + (size_t)bh * 65536;
    float* Zn  = g_Zb + (size_t)bh * 65536;
    unsigned int* bar = &g_bar[bh];

    for (int s = 0; s < 24; s++) {
        const int sub = s & 3;
        const float *Asrc, *Bsrc, *Dsrc; float* Cdst; float alpha, beta;
        if (sub == 0)      { Asrc = Xp;  Bsrc = Zc;  Dsrc = 0;   Cdst = XZp; alpha = 1.f;    beta = 0.f;   }
        else if (sub == 1) { Asrc = XZp; Bsrc = XZp; Dsrc = XZp; Cdst = T1p; alpha = -1.f;   beta = 7.f;   }
        else if (sub == 2) { Asrc = XZp; Bsrc = T1p; Dsrc = XZp; Cdst = T2p; alpha = -1.f;   beta = 15.f;  }
        else               { Asrc = Zc;  Bsrc = T2p; Dsrc = Zc;  Cdst = Zn;  alpha = -0.25f; beta = 3.25f; }

        const float* Ab = Asrc + (size_t)by * 128 * 256;
        const float* Bb = Bsrc + bx * 128;

        auto issue = [&](int kb, int st) {
            #pragma unroll
            for (int i = 0; i < 2; i++) {
                int id = tid + i * 256;
                int row = id >> 2, c4 = id & 3;
                cpa16(&As[st * ASTG + row * 20 + c4 * 4],
                      Ab + (size_t)row * 256 + kb * 16 + c4 * 4);
            }
            #pragma unroll
            for (int i = 0; i < 2; i++) {
                int id = tid + i * 256;
                int kr = id >> 5, n4 = id & 31;
                cpa16(&Bs[st * BSTG + kr * 136 + n4 * 4],
                      Bb + (size_t)(kb * 16 + kr) * 256 + n4 * 4);
            }
            asm volatile("cp.async.commit_group;");
        };

        float4 acc[2][8];
        #pragma unroll
        for (int i = 0; i < 2; i++)
            #pragma unroll
            for (int j = 0; j < 8; j++) acc[i][j] = make_float4(0.f, 0.f, 0.f, 0.f);

        issue(0, 0); issue(1, 1);
        for (int kb = 0; kb < 16; kb++) {
            if (kb + 1 < 16) { asm volatile("cp.async.wait_group 1;"); }
            else             { asm volatile("cp.async.wait_group 0;"); }
            __syncthreads();
            if (kb + 2 < 16) issue(kb + 2, (kb + 2) % 3);
            const float* Ac = As + (kb % 3) * ASTG;
            const float* Bc = Bs + (kb % 3) * BSTG;
            #pragma unroll
            for (int s8 = 0; s8 < 16; s8 += 8) {
                float a[2][4];
                #pragma unroll
                for (int mt = 0; mt < 2; mt++) {
                    const int Rm = wm * 32 + mt * 16 + g;
                    a[mt][0] = to_tf32(Ac[Rm * 20 + s8 + tg]);
                    a[mt][1] = to_tf32(Ac[(Rm + 8) * 20 + s8 + tg]);
                    a[mt][2] = to_tf32(Ac[Rm * 20 + s8 + tg + 4]);
                    a[mt][3] = to_tf32(Ac[(Rm + 8) * 20 + s8 + tg + 4]);
                }
                #pragma unroll
                for (int nt = 0; nt < 8; nt++) {
                    const int c = wn * 64 + nt * 8 + g;
                    float b0 = to_tf32(Bc[(s8 + tg) * 136 + c]);
                    float b1 = to_tf32(Bc[(s8 + tg + 4) * 136 + c]);
                    #pragma unroll
                    for (int mt = 0; mt < 2; mt++)
                        mma8(acc[mt][nt], a[mt][0], a[mt][1], a[mt][2], a[mt][3], b0, b1);
                }
            }
        }

        // epilogue (D via __ldcg to bypass possibly-stale L1)
        #pragma unroll
        for (int mt = 0; mt < 2; mt++) {
            #pragma unroll
            for (int nt = 0; nt < 8; nt++) {
                const int r0 = by * 128 + wm * 32 + mt * 16 + g;
                const int cb = bx * 128 + wn * 64 + nt * 8 + tg * 2;
                float4 v = acc[mt][nt];
                float2 lo, hi;
                lo.x = alpha * v.x; lo.y = alpha * v.y;
                hi.x = alpha * v.z; hi.y = alpha * v.w;
                if (beta != 0.f) {
                    float2 dlo = __ldcg((const float2*)&Dsrc[(size_t)r0 * 256 + cb]);
                    float2 dhi = __ldcg((const float2*)&Dsrc[(size_t)(r0 + 8) * 256 + cb]);
                    lo.x += beta * dlo.x; lo.y += beta * dlo.y;
                    hi.x += beta * dhi.x; hi.y += beta * dhi.y;
                }
                *(float2*)&Cdst[(size_t)r0 * 256 + cb] = lo;
                *(float2*)&Cdst[(size_t)(r0 + 8) * 256 + cb] = hi;
            }
        }

        // per-bh barrier: all 4 CTAs finish step s before anyone starts s+1
        __threadfence();
        __syncthreads();
        if (tid == 0) {
            asm volatile("red.release.gpu.global.add.u32 [%0], %1;"
                         :: "l"(bar), "r"(1u) : "memory");
            const unsigned target = 4u * (unsigned)(s + 1);
            unsigned cur;
            do {
                asm volatile("ld.acquire.gpu.global.u32 %0, [%1];" : "=r"(cur) : "l"(bar));
            } while (cur < target);
        }
        __syncthreads();

        if (sub == 3) { float* t = Zc; Zc = Zn; Zn = t; }
    }
}

// =====================================================================
// Flash-style fused sim3 path
// =====================================================================
#define FA3_SMEM (207872)
__global__ __launch_bounds__(256)
void k_fattn3(const float* __restrict__ qlg, const float* __restrict__ kg,
              const float* __restrict__ vg, float* __restrict__ c2)
{
    extern __shared__ float sm[];
    float* Qs = sm;                         // [kk<64][g<8][x<16]
    float* Ks = sm + 8192;                  // 2 stages, [c<128][68]
    float* Vs = sm + 8192 + 2 * 8704;       // 2 stages, [c<128][68]
    float* Ps = sm + 8192 + 4 * 8704;       // [row<64][132]
    float* Mp = Ps + 8448;                  // [4][64]
    float* Lp = Mp + 256;                   // [4][64]

    const int bh = blockIdx.y;
    const int i0 = blockIdx.x * 64;
    const int tid = threadIdx.x;
    const int lane = tid & 31, g = lane >> 2, tg = lane & 3;
    const int wid = tid >> 5, wm = wid & 1, wn = wid >> 1;
    const int sw = tg << 2;

    const float* kb = kg + (size_t)bh * SEQ * DH;
    const float* vb = vg + (size_t)bh * SEQ * DH;

    auto issue = [&](int j, int st) {
        const int cb = j * 128;
        #pragma unroll
        for (int i = 0; i < 8; i++) {
            int t4 = tid + i * 256;
            int row = t4 >> 4, q4 = (t4 & 15) << 2;
            cpa16(&Ks[st * 8704 + row * 68 + q4], kb + (size_t)(cb + row) * 64 + q4);
        }
        #pragma unroll
        for (int i = 0; i < 8; i++) {
            int t4 = tid + i * 256;
            int row = t4 >> 4, q4 = (t4 & 15) << 2;
            cpa16(&Vs[st * 8704 + row * 68 + q4], vb + (size_t)(cb + row) * 64 + q4);
        }
        asm volatile("cp.async.commit_group;");
    };

    issue(0, 0);

    const float* qb = qlg + ((size_t)bh * NM + i0) * 64;
    #pragma unroll
    for (int i = 0; i < 4; i++) {
        int t4 = tid + i * 256; int row = t4 >> 4, kq = (t4 & 15) << 2;
        float4 v = *(const float4*)(qb + row * 64 + kq);
        float vv[4] = {v.x, v.y, v.z, v.w};
        #pragma unroll
        for (int j = 0; j < 4; j++) {
            int kk = kq + j;
            Qs[kk * 128 + (row & 7) * 16 + ((row >> 3) ^ ((kk & 3) << 2))] = to_tf32(vv[j]);
        }
    }

    float4 acc2[2][2];
    #pragma unroll
    for (int i = 0; i < 2; i++)
        #pragma unroll
        for (int j = 0; j < 2; j++) acc2[i][j] = make_float4(0.f, 0.f, 0.f, 0.f);
    float Mrun[4] = {-1e30f, -1e30f, -1e30f, -1e30f};
    float Lrun[4] = {0.f, 0.f, 0.f, 0.f};

    for (int jt = 0; jt < SEQ / 128; jt++) {
        const int cur = jt & 1;
        if (jt + 1 < SEQ / 128) {
            issue(jt + 1, cur ^ 1);
            asm volatile("cp.async.wait_group 1;");
        } else {
            asm volatile("cp.async.wait_group 0;");
        }
        __syncthreads();

        const float* Kc = Ks + cur * 8704;
        const float* Vc = Vs + cur * 8704;

        float4 acc1[2][4];
        #pragma unroll
        for (int i = 0; i < 2; i++)
            #pragma unroll
            for (int j = 0; j < 4; j++) acc1[i][j] = make_float4(0.f, 0.f, 0.f, 0.f);
        #pragma unroll
        for (int s8 = 0; s8 < 64; s8 += 8) {
            const int k0 = s8 + tg;
            float4 aLo = *(const float4*)&Qs[k0 * 128 + g * 16 + ((wm * 4) ^ sw)];
            float4 aHi = *(const float4*)&Qs[(k0 + 4) * 128 + g * 16 + ((wm * 4) ^ sw)];
            float am[2][4] = {{aLo.x, aLo.y, aHi.x, aHi.y}, {aLo.z, aLo.w, aHi.z, aHi.w}};
            #pragma unroll
            for (int nt = 0; nt < 4; nt++) {
                const float* kr = Kc + (wn * 32 + nt * 8 + g) * 68;
                float b0 = kr[k0], b1 = kr[k0 + 4];
                #pragma unroll
                for (int mt = 0; mt < 2; mt++)
                    mma8(acc1[mt][nt], am[mt][0], am[mt][1], am[mt][2], am[mt][3], b0, b1);
            }
        }

        float tmax[4];
        #pragma unroll
        for (int t = 0; t < 4; t++) {
            const int mt = t >> 1; const bool hi = t & 1;
            float m = -1e30f;
            #pragma unroll
            for (int nt = 0; nt < 4; nt++) {
                float4 a = acc1[mt][nt];
                m = fmaxf(m, hi ? fmaxf(a.z, a.w) : fmaxf(a.x, a.y));
            }
            m = fmaxf(m, __shfl_xor_sync(0xffffffffu, m, 1));
            m = fmaxf(m, __shfl_xor_sync(0xffffffffu, m, 2));
            tmax[t] = m;
        }
        if (tg == 0) {
            #pragma unroll
            for (int t = 0; t < 4; t++) Mp[wn * 64 + wm * 32 + 8 * t + g] = tmax[t];
        }
        __syncthreads();

        float f[4];
        #pragma unroll
        for (int t = 0; t < 4; t++) {
            const int rl = wm * 32 + 8 * t + g;
            float tm = fmaxf(fmaxf(Mp[rl], Mp[64 + rl]),
                             fmaxf(Mp[128 + rl], Mp[192 + rl]));
            float Mn = fmaxf(Mrun[t], tm);
            f[t] = __expf(Mrun[t] - Mn);
            Mrun[t] = Mn;
        }
        #pragma unroll
        for (int mt2 = 0; mt2 < 2; mt2++)
            #pragma unroll
            for (int nt2 = 0; nt2 < 2; nt2++) {
                acc2[mt2][nt2].x *= f[2 * mt2];     acc2[mt2][nt2].y *= f[2 * mt2];
                acc2[mt2][nt2].z *= f[2 * mt2 + 1]; acc2[mt2][nt2].w *= f[2 * mt2 + 1];
            }
        #pragma unroll
        for (int t = 0; t < 4; t++) {
            const int mt = t >> 1; const bool hi = t & 1;
            const int rl = wm * 32 + 8 * t + g;
            const float M = Mrun[t];
            float s = 0.f;
            #pragma unroll
            for (int nt = 0; nt < 4; nt++) {
                float4 a = acc1[mt][nt];
                float v0 = hi ? a.z : a.x, v1 = hi ? a.w : a.y;
                float e0 = __expf(v0 - M), e1 = __expf(v1 - M);
                s += e0 + e1;
                int c0 = wn * 32 + nt * 8 + 2 * tg;
                Ps[rl * 132 + c0] = e0;
                Ps[rl * 132 + c0 + 1] = e1;
            }
            s += __shfl_xor_sync(0xffffffffu, s, 1);
            s += __shfl_xor_sync(0xffffffffu, s, 2);
            if (tg == 0) Lp[wn * 64 + rl] = s;
        }
        __syncthreads();
        #pragma unroll
        for (int t = 0; t < 4; t++) {
            const int rl = wm * 32 + 8 * t + g;
            Lrun[t] = Lrun[t] * f[t] + (Lp[rl] + Lp[64 + rl] + Lp[128 + rl] + Lp[192 + rl]);
        }

        #pragma unroll 4
        for (int s8 = 0; s8 < 128; s8 += 8) {
            const int k0 = s8 + tg, k1 = k0 + 4;
            float a_[2][4], b_[2][2];
            #pragma unroll
            for (int mt2 = 0; mt2 < 2; mt2++) {
                const int r0 = wm * 32 + 16 * mt2 + g;
                a_[mt2][0] = Ps[r0 * 132 + k0];
                a_[mt2][1] = Ps[(r0 + 8) * 132 + k0];
                a_[mt2][2] = Ps[r0 * 132 + k1];
                a_[mt2][3] = Ps[(r0 + 8) * 132 + k1];
            }
            #pragma unroll
            for (int nt2 = 0; nt2 < 2; nt2++) {
                const int c = wn * 16 + nt2 * 8 + g;
                b_[nt2][0] = Vc[k0 * 68 + c];
                b_[nt2][1] = Vc[k1 * 68 + c];
            }
            #pragma unroll
            for (int mt2 = 0; mt2 < 2; mt2++)
                #pragma unroll
                for (int nt2 = 0; nt2 < 2; nt2++)
                    mma8(acc2[mt2][nt2], a_[mt2][0], a_[mt2][1], a_[mt2][2], a_[mt2][3],
                         b_[nt2][0], b_[nt2][1]);
        }
        __syncthreads();
    }

    float invL[4];
    #pragma unroll
    for (int t = 0; t < 4; t++) invL[t] = 1.f / Lrun[t];
    float* ob = c2 + ((size_t)bh * NM + i0) * 64;
    #pragma unroll
    for (int mt2 = 0; mt2 < 2; mt2++) {
        #pragma unroll
        for (int nt2 = 0; nt2 < 2; nt2++) {
            const int c = wn * 16 + nt2 * 8 + 2 * tg;
            const int r0 = wm * 32 + 16 * mt2 + g;
            float4 v = acc2[mt2][nt2];
            float2 lo; lo.x = v.x * invL[2 * mt2];     lo.y = v.y * invL[2 * mt2];
            float2 hi; hi.x = v.z * invL[2 * mt2 + 1]; hi.y = v.w * invL[2 * mt2 + 1];
            *(float2*)&ob[(size_t)r0 * 64 + c] = lo;
            *(float2*)&ob[(size_t)(r0 + 8) * 64 + c] = hi;
        }
    }
}

// =====================================================================
// Fused attn1 path + depthwise-conv residual + transpose into Y.
// =====================================================================
#define FA1_SMEM (169984)
__global__ __launch_bounds__(256)
void k_fattn1(const float* __restrict__ qg, const float* __restrict__ klg,
              const float* __restrict__ cmg, const float* __restrict__ vg,
              const float* __restrict__ wres, float* __restrict__ Yg)
{
    extern __shared__ float sm[];
    float* Qs   = sm;                    // stage1: A-layout Q; later: Vw[96][64] + w[33]
    float* Ks   = sm + 8192;             // [kk<64][g<8][x<32]
    float* Ps   = sm + 8192;             // [k<256][g<8][x<8]   (aliases Ks)
    float* Cs   = sm + 24576;            // [k<256][c<68]; later Osm[64][68]
    float* Mred = sm + 24576 + 17408;    // [4][64]
    float* Lred = Mred + 256;            // [4][64]

    const int bh = blockIdx.y, b = bh >> 3, h = bh & 7;
    const int i0 = blockIdx.x * 64;
    const int tid = threadIdx.x;
    const int lane = tid & 31, g = lane >> 2, tg = lane & 3;
    const int wid = tid >> 5, wm = wid & 1, wn = wid >> 1;
    const int sw = tg << 2;

    const float* qb = qg + ((size_t)bh * SEQ + i0) * 64;
    #pragma unroll
    for (int i = 0; i < 4; i++) {
        int t4 = tid + i * 256; int row = t4 >> 4, kq = (t4 & 15) << 2;
        float4 v = *(const float4*)(qb + row * 64 + kq);
        float vv[4] = {v.x, v.y, v.z, v.w};
        #pragma unroll
        for (int j = 0; j < 4; j++) {
            int kk = kq + j;
            Qs[kk * 128 + (row & 7) * 16 + ((row >> 3) ^ ((kk & 3) << 2))] = to_tf32(vv[j]);
        }
    }
    const float* kb = klg + (size_t)bh * NM * 64;
    #pragma unroll
    for (int i = 0; i < 16; i++) {
        int t4 = tid + i * 256; int l = t4 >> 4, kq = (t4 & 15) << 2;
        float4 v = *(const float4*)(kb + l * 64 + kq);
        float vv[4] = {v.x, v.y, v.z, v.w};
        #pragma unroll
        for (int j = 0; j < 4; j++) {
            int kk = kq + j;
            Ks[kk * 256 + (l & 7) * 32 + ((l >> 3) ^ ((kk & 3) << 2))] = to_tf32(vv[j]);
        }
    }
    const float* cb = cmg + (size_t)bh * NM * 64;
    #pragma unroll
    for (int i = 0; i < 16; i++) {
        int t4 = tid + i * 256; int k = t4 >> 4, nq = (t4 & 15) << 2;
        float4 v = *(const float4*)(cb + k * 64 + nq);
        float4 w; w.x = to_tf32(v.x); w.y = to_tf32(v.y);
        w.z = to_tf32(v.z); w.w = to_tf32(v.w);
        *(float4*)&Cs[k * 68 + nq] = w;
    }
    __syncthreads();

    // stage 1: scores 64x256
    float4 acc1[2][8];
    #pragma unroll
    for (int i = 0; i < 2; i++)
        #pragma unroll
        for (int j = 0; j < 8; j++) acc1[i][j] = make_float4(0.f, 0.f, 0.f, 0.f);

    #pragma unroll
    for (int s8 = 0; s8 < 64; s8 += 8) {
        const int k0 = s8 + tg;
        float4 aLo = *(const float4*)&Qs[k0 * 128 + g * 16 + ((wm * 4) ^ sw)];
        float4 aHi = *(const float4*)&Qs[(k0 + 4) * 128 + g * 16 + ((wm * 4) ^ sw)];
        float4 b0l = *(const float4*)&Ks[k0 * 256 + g * 32 + ((wn * 8) ^ sw)];
        float4 b0h = *(const float4*)&Ks[k0 * 256 + g * 32 + ((wn * 8 + 4) ^ sw)];
        float4 b1l = *(const float4*)&Ks[(k0 + 4) * 256 + g * 32 + ((wn * 8) ^ sw)];
        float4 b1h = *(const float4*)&Ks[(k0 + 4) * 256 + g * 32 + ((wn * 8 + 4) ^ sw)];
        float bb0[8] = {b0l.x, b0l.y, b0l.z, b0l.w, b0h.x, b0h.y, b0h.z, b0h.w};
        float bb1[8] = {b1l.x, b1l.y, b1l.z, b1l.w, b1h.x, b1h.y, b1h.z, b1h.w};
        float am[2][4] = {{aLo.x, aLo.y, aHi.x, aHi.y}, {aLo.z, aLo.w, aHi.z, aHi.w}};
        #pragma unroll
        for (int mt = 0; mt < 2; mt++)
            #pragma unroll
            for (int nt = 0; nt < 8; nt++)
                mma8(acc1[mt][nt], am[mt][0], am[mt][1], am[mt][2], am[mt][3],
                     bb0[nt], bb1[nt]);
    }

    float rmax[4];
    #pragma unroll
    for (int t = 0; t < 4; t++) {
        const int mt = t >> 1; const bool hi = t & 1;
        float m = -1e30f;
        #pragma unroll
        for (int nt = 0; nt < 8; nt++) {
            float4 a = acc1[mt][nt];
            m = fmaxf(m, hi ? fmaxf(a.z, a.w) : fmaxf(a.x, a.y));
        }
        m = fmaxf(m, __shfl_xor_sync(0xffffffffu, m, 1));
        m = fmaxf(m, __shfl_xor_sync(0xffffffffu, m, 2));
        rmax[t] = m;
    }
    if (tg == 0) {
        #pragma unroll
        for (int t = 0; t < 4; t++) Mred[wn * 64 + 32 * wm + 8 * t + g] = rmax[t];
    }
    __syncthreads();   // guards Qs reuse + Ks -> Ps reuse

    // prefetch v window for conv (Qs region dead) + conv weights
    {
        const float* vb = vg + (size_t)bh * SEQ * DH;
        #pragma unroll
        for (int i2 = 0; i2 < 6; i2++) {
            int id = tid + i2 * 256;                 // 1536 chunks = 96 rows x 16
            int j = id >> 4, d4 = (id & 15) << 2;
            int gi = i0 - 16 + j;
            bool ok = (gi >= 0 && gi < SEQ);
            cpa16z(&Qs[j * 64 + d4], vb + (size_t)(ok ? gi : 0) * 64 + d4, ok);
        }
        if (tid < 33) Qs[6144 + tid] = wres[h * 33 + tid];
        asm volatile("cp.async.commit_group;");
    }

    #pragma unroll
    for (int t = 0; t < 4; t++) {
        const int rl = 32 * wm + 8 * t + g;
        rmax[t] = fmaxf(fmaxf(Mred[rl], Mred[64 + rl]),
                        fmaxf(Mred[128 + rl], Mred[192 + rl]));
    }
    #pragma unroll
    for (int t = 0; t < 4; t++) {
        const int mt = t >> 1; const bool hi = t & 1;
        const int rl = 32 * wm + 8 * t + g;
        const int rh = rl >> 3;
        const float M = rmax[t];
        float s = 0.f;
        #pragma unroll
        for (int nt = 0; nt < 8; nt++) {
            float4 a = acc1[mt][nt];
            float v0 = hi ? a.z : a.x, v1 = hi ? a.w : a.y;
            float e0 = __expf(v0 - M), e1 = __expf(v1 - M);
            s += e0 + e1;
            int c0 = wn * 64 + nt * 8 + 2 * tg;
            Ps[c0 * 64 + g * 8 + (rh ^ (c0 & 7))] = to_tf32(e0);
            Ps[(c0 + 1) * 64 + g * 8 + (rh ^ ((c0 + 1) & 7))] = to_tf32(e1);
        }
        s += __shfl_xor_sync(0xffffffffu, s, 1);
        s += __shfl_xor_sync(0xffffffffu, s, 2);
        if (tg == 0) Lred[wn * 64 + rl] = s;
    }
    __syncthreads();

    // stage 2: O = P(64x256) @ Cm(256x64)
    float4 acc2[2][2];
    #pragma unroll
    for (int i = 0; i < 2; i++)
        #pragma unroll
        for (int j = 0; j < 2; j++) acc2[i][j] = make_float4(0.f, 0.f, 0.f, 0.f);

    #pragma unroll 4
    for (int s8 = 0; s8 < 256; s8 += 8) {
        const int k0 = s8 + tg, k1 = k0 + 4;
        float a_[2][4], b_[2][2];
        #pragma unroll
        for (int mt = 0; mt < 2; mt++) {
            const int rh = 4 * wm + 2 * mt;
            a_[mt][0] = Ps[k0 * 64 + g * 8 + (rh ^ (k0 & 7))];
            a_[mt][1] = Ps[k0 * 64 + g * 8 + ((rh + 1) ^ (k0 & 7))];
            a_[mt][2] = Ps[k1 * 64 + g * 8 + (rh ^ (k1 & 7))];
            a_[mt][3] = Ps[k1 * 64 + g * 8 + ((rh + 1) ^ (k1 & 7))];
        }
        #pragma unroll
        for (int nt = 0; nt < 2; nt++) {
            const int c = wn * 16 + nt * 8 + g;
            b_[nt][0] = Cs[k0 * 68 + c];
            b_[nt][1] = Cs[k1 * 68 + c];
        }
        #pragma unroll
        for (int mt = 0; mt < 2; mt++)
            #pragma unroll
            for (int nt = 0; nt < 2; nt++)
                mma8(acc2[mt][nt], a_[mt][0], a_[mt][1], a_[mt][2], a_[mt][3],
                     b_[nt][0], b_[nt][1]);
    }

    float invL[4];
    #pragma unroll
    for (int t = 0; t < 4; t++) {
        const int rl = 32 * wm + 8 * t + g;
        float L = Lred[rl] + Lred[64 + rl] + Lred[128 + rl] + Lred[192 + rl];
        invL[t] = 1.f / L;
    }

    asm volatile("cp.async.wait_group 0;");
    __syncthreads();    // stage2 reads of Cs done; Vw ready

    // stage scaled O into Osm (= Cs region, [64][68])
    #pragma unroll
    for (int mt = 0; mt < 2; mt++) {
        #pragma unroll
        for (int nt = 0; nt < 2; nt++) {
            const int c = wn * 16 + nt * 8 + 2 * tg;
            const int r0 = 32 * wm + 16 * mt + g;
            float4 v = acc2[mt][nt];
            float2 lo; lo.x = v.x * invL[2 * mt]; lo.y = v.y * invL[2 * mt];
            float2 hi; hi.x = v.z * invL[2 * mt + 1]; hi.y = v.w * invL[2 * mt + 1];
            *(float2*)&Cs[r0 * 68 + c] = lo;
            *(float2*)&Cs[(r0 + 8) * 68 + c] = hi;
        }
    }
    __syncthreads();

    // conv + write to Y (transposed layout)
    const float* wv = Qs + 6144;
    #pragma unroll
    for (int i2 = 0; i2 < 4; i2++) {
        int l4 = tid + i2 * 256;            // 1024 float4s = 64 rows x 16
        int i = l4 >> 4, d4 = (l4 & 15) << 2;
        float4 o = *(float4*)&Cs[i * 68 + d4];
        #pragma unroll
        for (int t = 0; t < 33; t++) {
            float wt = wv[t];
            float4 vv = *(float4*)&Qs[(i + t) * 64 + d4];
            o.x += wt * vv.x; o.y += wt * vv.y; o.z += wt * vv.z; o.w += wt * vv.w;
        }
        *(float4*)&Yg[(size_t)(b * SEQ + i0 + i) * DM + h * 64 + d4] = o;
    }
}

// landmarks: mean over 32 consecutive tokens
__global__ void k_land() {
    int idx = blockIdx.x * blockDim.x + threadIdx.x;   // BH*NM*DH
    int d = idx & 63, i = (idx >> 6) & 255, bh = idx >> 14;
    size_t base = (size_t)bh * SEQ * DH + (size_t)i * LG * DH + d;
    float qs = 0.f, ks = 0.f;
    #pragma unroll 8
    for (int j = 0; j < LG; j++) { qs += g_q[base + j * 64]; ks += g_k[base + j * 64]; }
    g_ql[idx] = qs * (1.f / LG);
    g_kl[idx] = ks * (1.f / LG);
}

// Row softmax (in place), 256 cols, one block per row.
__global__ void k_softmax(float* __restrict__ X) {
    const size_t base = (size_t)blockIdx.x * 256;
    const int tid = threadIdx.x, lane = tid & 31, wp = tid >> 5;
    __shared__ float red[8];
    float v = X[base + tid];
    float m = v;
    #pragma unroll
    for (int off = 16; off; off >>= 1) m = fmaxf(m, __shfl_xor_sync(0xffffffffu, m, off));
    if (!lane) red[wp] = m;
    __syncthreads();
    float M = red[0];
    #pragma unroll
    for (int w = 1; w < 8; w++) M = fmaxf(M, red[w]);
    __syncthreads();
    float e = __expf(v - M);
    float s = e;
    #pragma unroll
    for (int off = 16; off; off >>= 1) s += __shfl_xor_sync(0xffffffffu, s, off);
    if (!lane) red[wp] = s;
    __syncthreads();
    float S = 0.f;
    #pragma unroll
    for (int w = 0; w < 8; w++) S += red[w];
    X[base + tid] = e / S;
}

// reset: g_mx and pinv barrier counters
__global__ void k_reset() {
    if (threadIdx.x < 2) g_mx[threadIdx.x] = 0u;
    if (threadIdx.x < BH) g_bar[threadIdx.x] = 0u;
}

__global__ void k_colrowmax() {
    const int bh = blockIdx.x, tid = threadIdx.x, lane = tid & 31, wp = tid >> 5;
    __shared__ float red[8];
    const float* Xb = g_X + (size_t)bh * NM * NM;
    float cs = 0.f;
    for (int i = 0; i < NM; i++) cs += Xb[i * NM + tid];
    float m = cs;
    #pragma unroll
    for (int off = 16; off; off >>= 1) m = fmaxf(m, __shfl_xor_sync(0xffffffffu, m, off));
    if (!lane) red[wp] = m;
    __syncthreads();
    if (tid == 0) {
        float M = red[0];
        #pragma unroll
        for (int w = 1; w < 8; w++) M = fmaxf(M, red[w]);
        atomicMax(&g_mx[1], __float_as_uint(M));
    }
    __syncthreads();
    float rs = 0.f;
    const float* Xr = Xb + (size_t)tid * NM;
    for (int j = 0; j < NM; j++) rs += Xr[j];
    m = rs;
    #pragma unroll
    for (int off = 16; off; off >>= 1) m = fmaxf(m, __shfl_xor_sync(0xffffffffu, m, off));
    if (!lane) red[wp] = m;
    __syncthreads();
    if (tid == 0) {
        float M = red[0];
        #pragma unroll
        for (int w = 1; w < 8; w++) M = fmaxf(M, red[w]);
        atomicMax(&g_mx[0], __float_as_uint(M));
    }
}

__global__ void k_zinit() {
    int idx = blockIdx.x * blockDim.x + threadIdx.x;   // BH*NM*NM
    float inv = 1.f / (__uint_as_float(g_mx[0]) * __uint_as_float(g_mx[1]));
    int j = idx & 255, i = (idx >> 8) & 255, bh = idx >> 16;
    g_Za[idx] = g_X[(size_t)bh * NM * NM + j * NM + i] * inv;
}

// =====================================================================
extern "C" void kernel_launch(void* const* d_in, const int* in_sizes, int n_in,
                              void* d_out, int out_size) {
    const float* x     = (const float*)d_in[0];
    const float* w_qkv = (const float*)d_in[1];
    const float* w_out = (const float*)d_in[2];
    const float* b_out = (const float*)d_in[3];
    const float* w_res = (const float*)d_in[4];
    float* out = (float*)d_out;

    float *q, *k_, *v, *ql, *kl, *X, *Za, *C2, *Cm, *Y;
    cudaGetSymbolAddress((void**)&q,   g_q);
    cudaGetSymbolAddress((void**)&k_,  g_k);
    cudaGetSymbolAddress((void**)&v,   g_v);
    cudaGetSymbolAddress((void**)&ql,  g_ql);
    cudaGetSymbolAddress((void**)&kl,  g_kl);
    cudaGetSymbolAddress((void**)&X,   g_X);
    cudaGetSymbolAddress((void**)&Za,  g_Za);
    cudaGetSymbolAddress((void**)&C2,  g_C2);
    cudaGetSymbolAddress((void**)&Cm,  g_Cm);
    cudaGetSymbolAddress((void**)&Y,   g_Y);

    // dynamic smem opt-in (floats: A 3*2560; B per layout)
    const int SM_NN128 = (3 * 2560 + 3 * 16 * 136) * 4;   // 56832
    const int SM_TN128 = (3 * 2560 + 3 * 128 * 20) * 4;   // 61440
    const int SM_NN64  = (3 * 2560 + 3 * 16 * 72) * 4;    // 44544
    cudaFuncSetAttribute(t_gemm<128, 2, false, 1>, cudaFuncAttributeMaxDynamicSharedMemorySize, SM_NN128);
    cudaFuncSetAttribute(t_gemm<128, 2, false, 0>, cudaFuncAttributeMaxDynamicSharedMemorySize, SM_NN128);
    cudaFuncSetAttribute(t_gemm<128, 2, true, 0>,  cudaFuncAttributeMaxDynamicSharedMemorySize, SM_TN128);
    cudaFuncSetAttribute(t_gemm<64, 1, false, 0>,  cudaFuncAttributeMaxDynamicSharedMemorySize, SM_NN64);
    cudaFuncSetAttribute(k_pinv,   cudaFuncAttributeMaxDynamicSharedMemorySize, SM_NN128);
    cudaFuncSetAttribute(k_fattn1, cudaFuncAttributeMaxDynamicSharedMemorySize, FA1_SMEM);
    cudaFuncSetAttribute(k_fattn3, cudaFuncAttributeMaxDynamicSharedMemorySize, FA3_SMEM);

    const float* NUL = (const float*)0;
    float* NULF = (float*)0;

    // 1. qkv = x @ w_qkv, scattered directly to packed q (scaled), k, v
    t_gemm<128, 2, false, 1><<<dim3(TRIPLE / 128, ROWS / 128, 1), 256, SM_NN128>>>(
        x, DM, 0LL, w_qkv, TRIPLE, 0LL, NUL, 0LL, NUL, q, TRIPLE, 0LL,
        DM, 1.f, 0.f, 1, q, k_, v);
    // 2. landmarks
    k_land<<<(BH * NM * DH) / 256, 256>>>();
    // 3. attn2 = softmax(q_land @ k_land^T)
    t_gemm<128, 2, true, 0><<<dim3(2, 2, BH), 256, SM_TN128>>>(
        ql, DH, 16384LL, kl, DH, 16384LL, NUL, 0LL, NUL, X, NM, 65536LL,
        DH, 1.f, 0.f, 1, NULF, NULF, NULF);
    k_softmax<<<BH * NM, 256>>>(X);
    // 4. pinv init
    k_reset<<<1, 32>>>();
    k_colrowmax<<<BH, 256>>>();
    k_zinit<<<(BH * NM * NM) / 256, 256>>>();
    // 5. 6 Newton iterations, one persistent launch (result in g_Za)
    k_pinv<<<128, 256, SM_NN128>>>();
    // 6. fused flash sim3 path: C2 = softmax(ql @ k^T) @ v
    k_fattn3<<<dim3(4, BH), 256, FA3_SMEM>>>(ql, k_, v, C2);
    // 7. Cm = Z @ C2
    t_gemm<64, 1, false, 0><<<dim3(1, 2, BH), 128, SM_NN64>>>(
        Za, NM, 65536LL, C2, DH, 16384LL, NUL, 0LL, NUL, Cm, DH, 16384LL,
        NM, 1.f, 0.f, 1, NULF, NULF, NULF);
    // 8. fused: Y = softmax(q @ kl^T) @ Cm + conv33(v), transposed
    k_fattn1<<<dim3(SEQ / 64, BH), 256, FA1_SMEM>>>(q, kl, Cm, v, w_res, Y);
    // 9. out = Y @ w_out + b_out
    t_gemm<128, 2, false, 0><<<dim3(DM / 128, ROWS / 128, 1), 256, SM_NN128>>>(
        Y, DM, 0LL, w_out, DM, 0LL, NUL, 0LL, b_out, out, DM, 0LL,
        DM, 1.f, 0.f, 1, NULF, NULF, NULF);
}

// round 15
// speedup vs baseline: 2.6071x; 1.0461x over previous
#include <cuda_runtime.h>
#include <cuda_bf16.h>
#include <math.h>

#define NB      4
#define SEQ     8192
#define DM      512
#define NH      8
#define DH      64
#define NM      256
#define LG      32
#define BH      32          // NB*NH
#define TRIPLE  1536
#define ROWS    32768       // NB*SEQ

// ---------------- scratch (device globals; no allocations allowed) -------
__device__ float g_q [(size_t)BH * SEQ * DH];         // packed tf32, pre-scaled by dh^-0.5
__device__ float g_k [(size_t)BH * SEQ * DH];
__device__ float g_v [(size_t)BH * SEQ * DH];
__device__ float g_ql[BH * NM * DH];
__device__ float g_kl[BH * NM * DH];
__device__ float g_X [BH * NM * NM];                  // attn2 (tf32 after softmax)
__device__ float g_Za[BH * NM * NM];
__device__ float g_Zb[BH * NM * NM];
__device__ float g_XZ[BH * NM * NM];
__device__ float g_T1[BH * NM * NM];
__device__ float g_T2[BH * NM * NM];
__device__ float g_C2[BH * NM * DH];                  // softmax(sim3) @ v
__device__ float g_Cm[BH * NM * DH];                  // Z @ C2
__device__ float g_Y [(size_t)ROWS * DM];             // step0: x_r; step8+: pre-out-proj
__device__ float g_wr[TRIPLE * DM + DM * DM];         // rounded w_qkv | w_out
__device__ unsigned int g_mx[2];
__device__ unsigned int g_bar[BH];                    // pinv inter-CTA barrier

// ---------------- helpers ----------------
__device__ __forceinline__ float to_tf32(float x) {
    unsigned u; asm("cvt.rna.tf32.f32 %0, %1;" : "=r"(u) : "f"(x));
    return __uint_as_float(u);
}
__device__ __forceinline__ void mma8(float4& d, float a0, float a1, float a2, float a3,
                                     float b0, float b1) {
    asm volatile(
        "mma.sync.aligned.m16n8k8.row.col.f32.tf32.tf32.f32 "
        "{%0,%1,%2,%3}, {%4,%5,%6,%7}, {%8,%9}, {%0,%1,%2,%3};"
        : "+f"(d.x), "+f"(d.y), "+f"(d.z), "+f"(d.w)
        : "r"(__float_as_uint(a0)), "r"(__float_as_uint(a1)),
          "r"(__float_as_uint(a2)), "r"(__float_as_uint(a3)),
          "r"(__float_as_uint(b0)), "r"(__float_as_uint(b1)));
}
__device__ __forceinline__ void cpa16(void* s, const void* g) {
    unsigned sa = (unsigned)__cvta_generic_to_shared(s);
    asm volatile("cp.async.cg.shared.global [%0], [%1], 16;" :: "r"(sa), "l"(g));
}
__device__ __forceinline__ void cpa16z(void* s, const void* g, bool ok) {
    unsigned sa = (unsigned)__cvta_generic_to_shared(s);
    int sz = ok ? 16 : 0;
    asm volatile("cp.async.cg.shared.global [%0], [%1], 16, %2;" :: "r"(sa), "l"(g), "r"(sz));
}

// pre-round true inputs: x -> g_Y, w_qkv|w_out -> g_wr
__global__ void k_round3(const float* __restrict__ x, const float* __restrict__ wq,
                         const float* __restrict__ wo) {
    int i = blockIdx.x * 256 + threadIdx.x;
    const int NX = (ROWS * DM) >> 2;        // 4194304
    const int NW = (TRIPLE * DM) >> 2;      // 196608
    float4 v; float4* dst;
    if (i < NX)            { v = ((const float4*)x)[i];            dst = (float4*)g_Y + i; }
    else if (i < NX + NW)  { int j = i - NX;      v = ((const float4*)wq)[j]; dst = (float4*)g_wr + j; }
    else                   { int j = i - NX - NW; v = ((const float4*)wo)[j];
                             dst = (float4*)(g_wr + TRIPLE * DM) + j; }
    float4 r; r.x = to_tf32(v.x); r.y = to_tf32(v.y); r.z = to_tf32(v.z); r.w = to_tf32(v.w);
    *dst = r;
}

// =====================================================================
// TF32 tensor-core GEMM, cp.async 3-stage pipeline. Operands in memory are
// already exactly-tf32 (producer-rounded), so fragments feed MMA raw.
// BM=128, BN in {128,64}. BK=16.
// EPI==0: C = alpha*(A@B[^T]) + beta*D (+bias); RC rounds stores to tf32.
// EPI==1: qkv scatter epilogue into q/k/v (q scaled by 0.125), rounded.
// =====================================================================
template<int BN, int WARPS_N, bool TRANSB, int EPI, int RC>
__global__ __launch_bounds__(128 * WARPS_N)
void t_gemm(const float* __restrict__ A, int lda, long long sA,
            const float* __restrict__ B, int ldb, long long sB,
            const float* __restrict__ D, long long sD,
            const float* __restrict__ bias,
            float* __restrict__ C, int ldc, long long sC,
            int K, float alpha, float beta, int ksplit,
            float* __restrict__ qp, float* __restrict__ kp, float* __restrict__ vp)
{
    constexpr int NT   = 128 * WARPS_N;
    constexpr int ASTG = 128 * 20;
    constexpr int BSTG = TRANSB ? BN * 20 : 16 * (BN + 8);
    constexpr int ACH  = 512 / NT;        // 16B chunks per thread per stage
    constexpr int BCH  = 4 * BN / NT;
    extern __shared__ float smp[];
    float* As = smp;
    float* Bs = smp + 3 * ASTG;

    const int tid = threadIdx.x;
    const int z = blockIdx.z;
    const int bh = z / ksplit, sk = z - bh * ksplit;
    const float* Ab = A + (size_t)bh * sA + (size_t)blockIdx.y * 128 * lda + (size_t)sk * K;
    const float* Bb;
    if (TRANSB) Bb = B + (size_t)bh * sB + (size_t)blockIdx.x * BN * ldb + (size_t)sk * K;
    else        Bb = B + (size_t)bh * sB + (size_t)sk * K * ldb + blockIdx.x * BN;

    const int lane = tid & 31, g = lane >> 2, tg = lane & 3;
    const int wid = tid >> 5, wm = wid & 3, wn = wid >> 2;

    auto issue = [&](int kb, int st) {
        #pragma unroll
        for (int i = 0; i < ACH; i++) {
            int id = tid + i * NT;
            int row = id >> 2, c4 = id & 3;
            cpa16(&As[st * ASTG + row * 20 + c4 * 4],
                  Ab + (size_t)row * lda + kb * 16 + c4 * 4);
        }
        #pragma unroll
        for (int i = 0; i < BCH; i++) {
            int id = tid + i * NT;
            if constexpr (TRANSB) {
                int row = id >> 2, c4 = id & 3;
                cpa16(&Bs[st * BSTG + row * 20 + c4 * 4],
                      Bb + (size_t)row * ldb + kb * 16 + c4 * 4);
            } else {
                int kr = id / (BN / 4), n4 = id % (BN / 4);
                cpa16(&Bs[st * BSTG + kr * (BN + 8) + n4 * 4],
                      Bb + (size_t)(kb * 16 + kr) * ldb + n4 * 4);
            }
        }
        asm volatile("cp.async.commit_group;");
    };

    float4 acc[2][8];
    #pragma unroll
    for (int i = 0; i < 2; i++)
        #pragma unroll
        for (int j = 0; j < 8; j++) acc[i][j] = make_float4(0.f, 0.f, 0.f, 0.f);

    const int kblocks = K >> 4;
    issue(0, 0); issue(1, 1);
    for (int kb = 0; kb < kblocks; kb++) {
        if (kb + 1 < kblocks) { asm volatile("cp.async.wait_group 1;"); }
        else                  { asm volatile("cp.async.wait_group 0;"); }
        __syncthreads();
        if (kb + 2 < kblocks) issue(kb + 2, (kb + 2) % 3);
        const float* Ac = As + (kb % 3) * ASTG;
        const float* Bc = Bs + (kb % 3) * BSTG;
        #pragma unroll
        for (int s8 = 0; s8 < 16; s8 += 8) {
            float a[2][4];
            #pragma unroll
            for (int mt = 0; mt < 2; mt++) {
                const int Rm = wm * 32 + mt * 16 + g;
                a[mt][0] = Ac[Rm * 20 + s8 + tg];
                a[mt][1] = Ac[(Rm + 8) * 20 + s8 + tg];
                a[mt][2] = Ac[Rm * 20 + s8 + tg + 4];
                a[mt][3] = Ac[(Rm + 8) * 20 + s8 + tg + 4];
            }
            #pragma unroll
            for (int nt = 0; nt < 8; nt++) {
                const int c = wn * 64 + nt * 8 + g;
                float b0, b1;
                if constexpr (TRANSB) {
                    b0 = Bc[c * 20 + s8 + tg];
                    b1 = Bc[c * 20 + s8 + tg + 4];
                } else {
                    b0 = Bc[(s8 + tg) * (BN + 8) + c];
                    b1 = Bc[(s8 + tg + 4) * (BN + 8) + c];
                }
                #pragma unroll
                for (int mt = 0; mt < 2; mt++)
                    mma8(acc[mt][nt], a[mt][0], a[mt][1], a[mt][2], a[mt][3], b0, b1);
            }
        }
    }

    // epilogue
    const int r00 = blockIdx.y * 128 + wm * 32;
    #pragma unroll
    for (int mt = 0; mt < 2; mt++) {
        #pragma unroll
        for (int nt = 0; nt < 8; nt++) {
            const int r0 = r00 + mt * 16 + g;
            const int cb = blockIdx.x * BN + wn * 64 + nt * 8 + tg * 2;
            float4 v = acc[mt][nt];
            if constexpr (EPI == 1) {
                const int which = cb >> 9, rem = cb & 511;
                const int h = rem >> 6, d = rem & 63;
                const float s = (which == 0) ? 0.125f : 1.0f;
                float* dst = (which == 0) ? qp : ((which == 1) ? kp : vp);
                int b = r0 >> 13, ii = r0 & 8191;
                float2 lo; lo.x = to_tf32(v.x * s); lo.y = to_tf32(v.y * s);
                *(float2*)&dst[(((size_t)(b * 8 + h) * 8192 + ii) << 6) + d] = lo;
                const int r1 = r0 + 8; b = r1 >> 13; ii = r1 & 8191;
                float2 hi; hi.x = to_tf32(v.z * s); hi.y = to_tf32(v.w * s);
                *(float2*)&dst[(((size_t)(b * 8 + h) * 8192 + ii) << 6) + d] = hi;
            } else {
                float* Cb = C + (size_t)z * sC;
                const float* Db = D + (size_t)bh * sD;
                float2 lo, hi;
                lo.x = alpha * v.x; lo.y = alpha * v.y;
                hi.x = alpha * v.z; hi.y = alpha * v.w;
                if (beta != 0.f) {
                    float2 dlo = *(const float2*)&Db[(size_t)r0 * ldc + cb];
                    float2 dhi = *(const float2*)&Db[(size_t)(r0 + 8) * ldc + cb];
                    lo.x += beta * dlo.x; lo.y += beta * dlo.y;
                    hi.x += beta * dhi.x; hi.y += beta * dhi.y;
                }
                if (bias) {
                    float2 bv = *(const float2*)&bias[cb];
                    lo.x += bv.x; lo.y += bv.y; hi.x += bv.x; hi.y += bv.y;
                }
                if constexpr (RC) {
                    lo.x = to_tf32(lo.x); lo.y = to_tf32(lo.y);
                    hi.x = to_tf32(hi.x); hi.y = to_tf32(hi.y);
                }
                *(float2*)&Cb[(size_t)r0 * ldc + cb] = lo;
                *(float2*)&Cb[(size_t)(r0 + 8) * ldc + cb] = hi;
            }
        }
    }
}

// =====================================================================
// Persistent pinv: 24 chained 256x256x256 GEMM steps, one launch.
// Operands producer-rounded; outputs rounded at store.
// =====================================================================
__global__ __launch_bounds__(256)
void k_pinv() {
    constexpr int ASTG = 128 * 20;
    constexpr int BSTG = 16 * 136;
    extern __shared__ float smp[];
    float* As = smp;
    float* Bs = smp + 3 * ASTG;

    const int bh = blockIdx.x >> 2;
    const int qd = blockIdx.x & 3;
    const int by = qd >> 1, bx = qd & 1;
    const int tid = threadIdx.x;
    const int lane = tid & 31, g = lane >> 2, tg = lane & 3;
    const int wid = tid >> 5, wm = wid & 3, wn = wid >> 2;

    float* Xp  = g_X  + (size_t)bh * 65536;
    float* XZp = g_XZ + (size_t)bh * 65536;
    float* T1p = g_T1 + (size_t)bh * 65536;
    float* T2p = g_T2 + (size_t)bh * 65536;
    float* Zc  = g_Za + (size_t)bh * 65536;
    float* Zn  = g_Zb + (size_t)bh * 65536;
    unsigned int* bar = &g_bar[bh];

    for (int s = 0; s < 24; s++) {
        const int sub = s & 3;
        const float *Asrc, *Bsrc, *Dsrc; float* Cdst; float alpha, beta;
        if (sub == 0)      { Asrc = Xp;  Bsrc = Zc;  Dsrc = 0;   Cdst = XZp; alpha = 1.f;    beta = 0.f;   }
        else if (sub == 1) { Asrc = XZp; Bsrc = XZp; Dsrc = XZp; Cdst = T1p; alpha = -1.f;   beta = 7.f;   }
        else if (sub == 2) { Asrc = XZp; Bsrc = T1p; Dsrc = XZp; Cdst = T2p; alpha = -1.f;   beta = 15.f;  }
        else               { Asrc = Zc;  Bsrc = T2p; Dsrc = Zc;  Cdst = Zn;  alpha = -0.25f; beta = 3.25f; }

        const float* Ab = Asrc + (size_t)by * 128 * 256;
        const float* Bb = Bsrc + bx * 128;

        auto issue = [&](int kb, int st) {
            #pragma unroll
            for (int i = 0; i < 2; i++) {
                int id = tid + i * 256;
                int row = id >> 2, c4 = id & 3;
                cpa16(&As[st * ASTG + row * 20 + c4 * 4],
                      Ab + (size_t)row * 256 + kb * 16 + c4 * 4);
            }
            #pragma unroll
            for (int i = 0; i < 2; i++) {
                int id = tid + i * 256;
                int kr = id >> 5, n4 = id & 31;
                cpa16(&Bs[st * BSTG + kr * 136 + n4 * 4],
                      Bb + (size_t)(kb * 16 + kr) * 256 + n4 * 4);
            }
            asm volatile("cp.async.commit_group;");
        };

        float4 acc[2][8];
        #pragma unroll
        for (int i = 0; i < 2; i++)
            #pragma unroll
            for (int j = 0; j < 8; j++) acc[i][j] = make_float4(0.f, 0.f, 0.f, 0.f);

        issue(0, 0); issue(1, 1);
        for (int kb = 0; kb < 16; kb++) {
            if (kb + 1 < 16) { asm volatile("cp.async.wait_group 1;"); }
            else             { asm volatile("cp.async.wait_group 0;"); }
            __syncthreads();
            if (kb + 2 < 16) issue(kb + 2, (kb + 2) % 3);
            const float* Ac = As + (kb % 3) * ASTG;
            const float* Bc = Bs + (kb % 3) * BSTG;
            #pragma unroll
            for (int s8 = 0; s8 < 16; s8 += 8) {
                float a[2][4];
                #pragma unroll
                for (int mt = 0; mt < 2; mt++) {
                    const int Rm = wm * 32 + mt * 16 + g;
                    a[mt][0] = Ac[Rm * 20 + s8 + tg];
                    a[mt][1] = Ac[(Rm + 8) * 20 + s8 + tg];
                    a[mt][2] = Ac[Rm * 20 + s8 + tg + 4];
                    a[mt][3] = Ac[(Rm + 8) * 20 + s8 + tg + 4];
                }
                #pragma unroll
                for (int nt = 0; nt < 8; nt++) {
                    const int c = wn * 64 + nt * 8 + g;
                    float b0 = Bc[(s8 + tg) * 136 + c];
                    float b1 = Bc[(s8 + tg + 4) * 136 + c];
                    #pragma unroll
                    for (int mt = 0; mt < 2; mt++)
                        mma8(acc[mt][nt], a[mt][0], a[mt][1], a[mt][2], a[mt][3], b0, b1);
                }
            }
        }

        // epilogue (D via __ldcg; store rounded)
        #pragma unroll
        for (int mt = 0; mt < 2; mt++) {
            #pragma unroll
            for (int nt = 0; nt < 8; nt++) {
                const int r0 = by * 128 + wm * 32 + mt * 16 + g;
                const int cb = bx * 128 + wn * 64 + nt * 8 + tg * 2;
                float4 v = acc[mt][nt];
                float2 lo, hi;
                lo.x = alpha * v.x; lo.y = alpha * v.y;
                hi.x = alpha * v.z; hi.y = alpha * v.w;
                if (beta != 0.f) {
                    float2 dlo = __ldcg((const float2*)&Dsrc[(size_t)r0 * 256 + cb]);
                    float2 dhi = __ldcg((const float2*)&Dsrc[(size_t)(r0 + 8) * 256 + cb]);
                    lo.x += beta * dlo.x; lo.y += beta * dlo.y;
                    hi.x += beta * dhi.x; hi.y += beta * dhi.y;
                }
                lo.x = to_tf32(lo.x); lo.y = to_tf32(lo.y);
                hi.x = to_tf32(hi.x); hi.y = to_tf32(hi.y);
                *(float2*)&Cdst[(size_t)r0 * 256 + cb] = lo;
                *(float2*)&Cdst[(size_t)(r0 + 8) * 256 + cb] = hi;
            }
        }

        // per-bh barrier: all 4 CTAs finish step s before anyone starts s+1
        __threadfence();
        __syncthreads();
        if (tid == 0) {
            asm volatile("red.release.gpu.global.add.u32 [%0], %1;"
                         :: "l"(bar), "r"(1u) : "memory");
            const unsigned target = 4u * (unsigned)(s + 1);
            unsigned cur;
            do {
                __nanosleep(64);
                asm volatile("ld.acquire.gpu.global.u32 %0, [%1];" : "=r"(cur) : "l"(bar));
            } while (cur < target);
        }
        __syncthreads();

        if (sub == 3) { float* t = Zc; Zc = Zn; Zn = t; }
    }
}

// =====================================================================
// Flash-style fused sim3 path (ql/k/v producer-rounded; no fill cvt)
// =====================================================================
#define FA3_SMEM (207872)
__global__ __launch_bounds__(256)
void k_fattn3(const float* __restrict__ qlg, const float* __restrict__ kg,
              const float* __restrict__ vg, float* __restrict__ c2)
{
    extern __shared__ float sm[];
    float* Qs = sm;                         // [kk<64][g<8][x<16]
    float* Ks = sm + 8192;                  // 2 stages, [c<128][68]
    float* Vs = sm + 8192 + 2 * 8704;       // 2 stages, [c<128][68]
    float* Ps = sm + 8192 + 4 * 8704;       // [row<64][132]
    float* Mp = Ps + 8448;                  // [4][64]
    float* Lp = Mp + 256;                   // [4][64]

    const int bh = blockIdx.y;
    const int i0 = blockIdx.x * 64;
    const int tid = threadIdx.x;
    const int lane = tid & 31, g = lane >> 2, tg = lane & 3;
    const int wid = tid >> 5, wm = wid & 1, wn = wid >> 1;
    const int sw = tg << 2;

    const float* kb = kg + (size_t)bh * SEQ * DH;
    const float* vb = vg + (size_t)bh * SEQ * DH;

    auto issue = [&](int j, int st) {
        const int cb = j * 128;
        #pragma unroll
        for (int i = 0; i < 8; i++) {
            int t4 = tid + i * 256;
            int row = t4 >> 4, q4 = (t4 & 15) << 2;
            cpa16(&Ks[st * 8704 + row * 68 + q4], kb + (size_t)(cb + row) * 64 + q4);
        }
        #pragma unroll
        for (int i = 0; i < 8; i++) {
            int t4 = tid + i * 256;
            int row = t4 >> 4, q4 = (t4 & 15) << 2;
            cpa16(&Vs[st * 8704 + row * 68 + q4], vb + (size_t)(cb + row) * 64 + q4);
        }
        asm volatile("cp.async.commit_group;");
    };

    issue(0, 0);

    const float* qb = qlg + ((size_t)bh * NM + i0) * 64;
    #pragma unroll
    for (int i = 0; i < 4; i++) {
        int t4 = tid + i * 256; int row = t4 >> 4, kq = (t4 & 15) << 2;
        float4 v = *(const float4*)(qb + row * 64 + kq);
        float vv[4] = {v.x, v.y, v.z, v.w};
        #pragma unroll
        for (int j = 0; j < 4; j++) {
            int kk = kq + j;
            Qs[kk * 128 + (row & 7) * 16 + ((row >> 3) ^ ((kk & 3) << 2))] = vv[j];
        }
    }

    float4 acc2[2][2];
    #pragma unroll
    for (int i = 0; i < 2; i++)
        #pragma unroll
        for (int j = 0; j < 2; j++) acc2[i][j] = make_float4(0.f, 0.f, 0.f, 0.f);
    float Mrun[4] = {-1e30f, -1e30f, -1e30f, -1e30f};
    float Lrun[4] = {0.f, 0.f, 0.f, 0.f};

    for (int jt = 0; jt < SEQ / 128; jt++) {
        const int cur = jt & 1;
        if (jt + 1 < SEQ / 128) {
            issue(jt + 1, cur ^ 1);
            asm volatile("cp.async.wait_group 1;");
        } else {
            asm volatile("cp.async.wait_group 0;");
        }
        __syncthreads();

        const float* Kc = Ks + cur * 8704;
        const float* Vc = Vs + cur * 8704;

        float4 acc1[2][4];
        #pragma unroll
        for (int i = 0; i < 2; i++)
            #pragma unroll
            for (int j = 0; j < 4; j++) acc1[i][j] = make_float4(0.f, 0.f, 0.f, 0.f);
        #pragma unroll
        for (int s8 = 0; s8 < 64; s8 += 8) {
            const int k0 = s8 + tg;
            float4 aLo = *(const float4*)&Qs[k0 * 128 + g * 16 + ((wm * 4) ^ sw)];
            float4 aHi = *(const float4*)&Qs[(k0 + 4) * 128 + g * 16 + ((wm * 4) ^ sw)];
            float am[2][4] = {{aLo.x, aLo.y, aHi.x, aHi.y}, {aLo.z, aLo.w, aHi.z, aHi.w}};
            #pragma unroll
            for (int nt = 0; nt < 4; nt++) {
                const float* kr = Kc + (wn * 32 + nt * 8 + g) * 68;
                float b0 = kr[k0], b1 = kr[k0 + 4];
                #pragma unroll
                for (int mt = 0; mt < 2; mt++)
                    mma8(acc1[mt][nt], am[mt][0], am[mt][1], am[mt][2], am[mt][3], b0, b1);
            }
        }

        float tmax[4];
        #pragma unroll
        for (int t = 0; t < 4; t++) {
            const int mt = t >> 1; const bool hi = t & 1;
            float m = -1e30f;
            #pragma unroll
            for (int nt = 0; nt < 4; nt++) {
                float4 a = acc1[mt][nt];
                m = fmaxf(m, hi ? fmaxf(a.z, a.w) : fmaxf(a.x, a.y));
            }
            m = fmaxf(m, __shfl_xor_sync(0xffffffffu, m, 1));
            m = fmaxf(m, __shfl_xor_sync(0xffffffffu, m, 2));
            tmax[t] = m;
        }
        if (tg == 0) {
            #pragma unroll
            for (int t = 0; t < 4; t++) Mp[wn * 64 + wm * 32 + 8 * t + g] = tmax[t];
        }
        __syncthreads();

        float f[4];
        #pragma unroll
        for (int t = 0; t < 4; t++) {
            const int rl = wm * 32 + 8 * t + g;
            float tm = fmaxf(fmaxf(Mp[rl], Mp[64 + rl]),
                             fmaxf(Mp[128 + rl], Mp[192 + rl]));
            float Mn = fmaxf(Mrun[t], tm);
            f[t] = __expf(Mrun[t] - Mn);
            Mrun[t] = Mn;
        }
        #pragma unroll
        for (int mt2 = 0; mt2 < 2; mt2++)
            #pragma unroll
            for (int nt2 = 0; nt2 < 2; nt2++) {
                acc2[mt2][nt2].x *= f[2 * mt2];     acc2[mt2][nt2].y *= f[2 * mt2];
                acc2[mt2][nt2].z *= f[2 * mt2 + 1]; acc2[mt2][nt2].w *= f[2 * mt2 + 1];
            }
        #pragma unroll
        for (int t = 0; t < 4; t++) {
            const int mt = t >> 1; const bool hi = t & 1;
            const int rl = wm * 32 + 8 * t + g;
            const float M = Mrun[t];
            float s = 0.f;
            #pragma unroll
            for (int nt = 0; nt < 4; nt++) {
                float4 a = acc1[mt][nt];
                float v0 = hi ? a.z : a.x, v1 = hi ? a.w : a.y;
                float e0 = __expf(v0 - M), e1 = __expf(v1 - M);
                s += e0 + e1;
                int c0 = wn * 32 + nt * 8 + 2 * tg;
                Ps[rl * 132 + c0] = e0;
                Ps[rl * 132 + c0 + 1] = e1;
            }
            s += __shfl_xor_sync(0xffffffffu, s, 1);
            s += __shfl_xor_sync(0xffffffffu, s, 2);
            if (tg == 0) Lp[wn * 64 + rl] = s;
        }
        __syncthreads();
        #pragma unroll
        for (int t = 0; t < 4; t++) {
            const int rl = wm * 32 + 8 * t + g;
            Lrun[t] = Lrun[t] * f[t] + (Lp[rl] + Lp[64 + rl] + Lp[128 + rl] + Lp[192 + rl]);
        }

        #pragma unroll 4
        for (int s8 = 0; s8 < 128; s8 += 8) {
            const int k0 = s8 + tg, k1 = k0 + 4;
            float a_[2][4], b_[2][2];
            #pragma unroll
            for (int mt2 = 0; mt2 < 2; mt2++) {
                const int r0 = wm * 32 + 16 * mt2 + g;
                a_[mt2][0] = Ps[r0 * 132 + k0];
                a_[mt2][1] = Ps[(r0 + 8) * 132 + k0];
                a_[mt2][2] = Ps[r0 * 132 + k1];
                a_[mt2][3] = Ps[(r0 + 8) * 132 + k1];
            }
            #pragma unroll
            for (int nt2 = 0; nt2 < 2; nt2++) {
                const int c = wn * 16 + nt2 * 8 + g;
                b_[nt2][0] = Vc[k0 * 68 + c];
                b_[nt2][1] = Vc[k1 * 68 + c];
            }
            #pragma unroll
            for (int mt2 = 0; mt2 < 2; mt2++)
                #pragma unroll
                for (int nt2 = 0; nt2 < 2; nt2++)
                    mma8(acc2[mt2][nt2], a_[mt2][0], a_[mt2][1], a_[mt2][2], a_[mt2][3],
                         b_[nt2][0], b_[nt2][1]);
        }
        __syncthreads();
    }

    float invL[4];
    #pragma unroll
    for (int t = 0; t < 4; t++) invL[t] = 1.f / Lrun[t];
    float* ob = c2 + ((size_t)bh * NM + i0) * 64;
    #pragma unroll
    for (int mt2 = 0; mt2 < 2; mt2++) {
        #pragma unroll
        for (int nt2 = 0; nt2 < 2; nt2++) {
            const int c = wn * 16 + nt2 * 8 + 2 * tg;
            const int r0 = wm * 32 + 16 * mt2 + g;
            float4 v = acc2[mt2][nt2];
            float2 lo; lo.x = to_tf32(v.x * invL[2 * mt2]);     lo.y = to_tf32(v.y * invL[2 * mt2]);
            float2 hi; hi.x = to_tf32(v.z * invL[2 * mt2 + 1]); hi.y = to_tf32(v.w * invL[2 * mt2 + 1]);
            *(float2*)&ob[(size_t)r0 * 64 + c] = lo;
            *(float2*)&ob[(size_t)(r0 + 8) * 64 + c] = hi;
        }
    }
}

// =====================================================================
// Fused attn1 path + depthwise-conv residual + transpose into Y (rounded).
// =====================================================================
#define FA1_SMEM (169984)
__global__ __launch_bounds__(256)
void k_fattn1(const float* __restrict__ qg, const float* __restrict__ klg,
              const float* __restrict__ cmg, const float* __restrict__ vg,
              const float* __restrict__ wres, float* __restrict__ Yg)
{
    extern __shared__ float sm[];
    float* Qs   = sm;                    // stage1: A-layout Q; later: Vw[96][64] + w[33]
    float* Ks   = sm + 8192;             // [kk<64][g<8][x<32]
    float* Ps   = sm + 8192;             // [k<256][g<8][x<8]   (aliases Ks)
    float* Cs   = sm + 24576;            // [k<256][c<68]; later Osm[64][68]
    float* Mred = sm + 24576 + 17408;    // [4][64]
    float* Lred = Mred + 256;            // [4][64]

    const int bh = blockIdx.y, b = bh >> 3, h = bh & 7;
    const int i0 = blockIdx.x * 64;
    const int tid = threadIdx.x;
    const int lane = tid & 31, g = lane >> 2, tg = lane & 3;
    const int wid = tid >> 5, wm = wid & 1, wn = wid >> 1;
    const int sw = tg << 2;

    const float* qb = qg + ((size_t)bh * SEQ + i0) * 64;
    #pragma unroll
    for (int i = 0; i < 4; i++) {
        int t4 = tid + i * 256; int row = t4 >> 4, kq = (t4 & 15) << 2;
        float4 v = *(const float4*)(qb + row * 64 + kq);
        float vv[4] = {v.x, v.y, v.z, v.w};
        #pragma unroll
        for (int j = 0; j < 4; j++) {
            int kk = kq + j;
            Qs[kk * 128 + (row & 7) * 16 + ((row >> 3) ^ ((kk & 3) << 2))] = vv[j];
        }
    }
    const float* kb = klg + (size_t)bh * NM * 64;
    #pragma unroll
    for (int i = 0; i < 16; i++) {
        int t4 = tid + i * 256; int l = t4 >> 4, kq = (t4 & 15) << 2;
        float4 v = *(const float4*)(kb + l * 64 + kq);
        float vv[4] = {v.x, v.y, v.z, v.w};
        #pragma unroll
        for (int j = 0; j < 4; j++) {
            int kk = kq + j;
            Ks[kk * 256 + (l & 7) * 32 + ((l >> 3) ^ ((kk & 3) << 2))] = vv[j];
        }
    }
    const float* cb = cmg + (size_t)bh * NM * 64;
    #pragma unroll
    for (int i = 0; i < 16; i++) {
        int t4 = tid + i * 256; int k = t4 >> 4, nq = (t4 & 15) << 2;
        float4 v = *(const float4*)(cb + k * 64 + nq);
        *(float4*)&Cs[k * 68 + nq] = v;
    }
    __syncthreads();

    // stage 1: scores 64x256
    float4 acc1[2][8];
    #pragma unroll
    for (int i = 0; i < 2; i++)
        #pragma unroll
        for (int j = 0; j < 8; j++) acc1[i][j] = make_float4(0.f, 0.f, 0.f, 0.f);

    #pragma unroll
    for (int s8 = 0; s8 < 64; s8 += 8) {
        const int k0 = s8 + tg;
        float4 aLo = *(const float4*)&Qs[k0 * 128 + g * 16 + ((wm * 4) ^ sw)];
        float4 aHi = *(const float4*)&Qs[(k0 + 4) * 128 + g * 16 + ((wm * 4) ^ sw)];
        float4 b0l = *(const float4*)&Ks[k0 * 256 + g * 32 + ((wn * 8) ^ sw)];
        float4 b0h = *(const float4*)&Ks[k0 * 256 + g * 32 + ((wn * 8 + 4) ^ sw)];
        float4 b1l = *(const float4*)&Ks[(k0 + 4) * 256 + g * 32 + ((wn * 8) ^ sw)];
        float4 b1h = *(const float4*)&Ks[(k0 + 4) * 256 + g * 32 + ((wn * 8 + 4) ^ sw)];
        float bb0[8] = {b0l.x, b0l.y, b0l.z, b0l.w, b0h.x, b0h.y, b0h.z, b0h.w};
        float bb1[8] = {b1l.x, b1l.y, b1l.z, b1l.w, b1h.x, b1h.y, b1h.z, b1h.w};
        float am[2][4] = {{aLo.x, aLo.y, aHi.x, aHi.y}, {aLo.z, aLo.w, aHi.z, aHi.w}};
        #pragma unroll
        for (int mt = 0; mt < 2; mt++)
            #pragma unroll
            for (int nt = 0; nt < 8; nt++)
                mma8(acc1[mt][nt], am[mt][0], am[mt][1], am[mt][2], am[mt][3],
                     bb0[nt], bb1[nt]);
    }

    float rmax[4];
    #pragma unroll
    for (int t = 0; t < 4; t++) {
        const int mt = t >> 1; const bool hi = t & 1;
        float m = -1e30f;
        #pragma unroll
        for (int nt = 0; nt < 8; nt++) {
            float4 a = acc1[mt][nt];
            m = fmaxf(m, hi ? fmaxf(a.z, a.w) : fmaxf(a.x, a.y));
        }
        m = fmaxf(m, __shfl_xor_sync(0xffffffffu, m, 1));
        m = fmaxf(m, __shfl_xor_sync(0xffffffffu, m, 2));
        rmax[t] = m;
    }
    if (tg == 0) {
        #pragma unroll
        for (int t = 0; t < 4; t++) Mred[wn * 64 + 32 * wm + 8 * t + g] = rmax[t];
    }
    __syncthreads();   // guards Qs reuse + Ks -> Ps reuse

    // prefetch v window for conv (Qs region dead) + conv weights
    {
        const float* vb = vg + (size_t)bh * SEQ * DH;
        #pragma unroll
        for (int i2 = 0; i2 < 6; i2++) {
            int id = tid + i2 * 256;                 // 1536 chunks = 96 rows x 16
            int j = id >> 4, d4 = (id & 15) << 2;
            int gi = i0 - 16 + j;
            bool ok = (gi >= 0 && gi < SEQ);
            cpa16z(&Qs[j * 64 + d4], vb + (size_t)(ok ? gi : 0) * 64 + d4, ok);
        }
        if (tid < 33) Qs[6144 + tid] = wres[h * 33 + tid];
        asm volatile("cp.async.commit_group;");
    }

    #pragma unroll
    for (int t = 0; t < 4; t++) {
        const int rl = 32 * wm + 8 * t + g;
        rmax[t] = fmaxf(fmaxf(Mred[rl], Mred[64 + rl]),
                        fmaxf(Mred[128 + rl], Mred[192 + rl]));
    }
    #pragma unroll
    for (int t = 0; t < 4; t++) {
        const int mt = t >> 1; const bool hi = t & 1;
        const int rl = 32 * wm + 8 * t + g;
        const int rh = rl >> 3;
        const float M = rmax[t];
        float s = 0.f;
        #pragma unroll
        for (int nt = 0; nt < 8; nt++) {
            float4 a = acc1[mt][nt];
            float v0 = hi ? a.z : a.x, v1 = hi ? a.w : a.y;
            float e0 = __expf(v0 - M), e1 = __expf(v1 - M);
            s += e0 + e1;
            int c0 = wn * 64 + nt * 8 + 2 * tg;
            Ps[c0 * 64 + g * 8 + (rh ^ (c0 & 7))] = to_tf32(e0);
            Ps[(c0 + 1) * 64 + g * 8 + (rh ^ ((c0 + 1) & 7))] = to_tf32(e1);
        }
        s += __shfl_xor_sync(0xffffffffu, s, 1);
        s += __shfl_xor_sync(0xffffffffu, s, 2);
        if (tg == 0) Lred[wn * 64 + rl] = s;
    }
    __syncthreads();

    // stage 2: O = P(64x256) @ Cm(256x64)
    float4 acc2[2][2];
    #pragma unroll
    for (int i = 0; i < 2; i++)
        #pragma unroll
        for (int j = 0; j < 2; j++) acc2[i][j] = make_float4(0.f, 0.f, 0.f, 0.f);

    #pragma unroll 4
    for (int s8 = 0; s8 < 256; s8 += 8) {
        const int k0 = s8 + tg, k1 = k0 + 4;
        float a_[2][4], b_[2][2];
        #pragma unroll
        for (int mt = 0; mt < 2; mt++) {
            const int rh = 4 * wm + 2 * mt;
            a_[mt][0] = Ps[k0 * 64 + g * 8 + (rh ^ (k0 & 7))];
            a_[mt][1] = Ps[k0 * 64 + g * 8 + ((rh + 1) ^ (k0 & 7))];
            a_[mt][2] = Ps[k1 * 64 + g * 8 + (rh ^ (k1 & 7))];
            a_[mt][3] = Ps[k1 * 64 + g * 8 + ((rh + 1) ^ (k1 & 7))];
        }
        #pragma unroll
        for (int nt = 0; nt < 2; nt++) {
            const int c = wn * 16 + nt * 8 + g;
            b_[nt][0] = Cs[k0 * 68 + c];
            b_[nt][1] = Cs[k1 * 68 + c];
        }
        #pragma unroll
        for (int mt = 0; mt < 2; mt++)
            #pragma unroll
            for (int nt = 0; nt < 2; nt++)
                mma8(acc2[mt][nt], a_[mt][0], a_[mt][1], a_[mt][2], a_[mt][3],
                     b_[nt][0], b_[nt][1]);
    }

    float invL[4];
    #pragma unroll
    for (int t = 0; t < 4; t++) {
        const int rl = 32 * wm + 8 * t + g;
        float L = Lred[rl] + Lred[64 + rl] + Lred[128 + rl] + Lred[192 + rl];
        invL[t] = 1.f / L;
    }

    asm volatile("cp.async.wait_group 0;");
    __syncthreads();    // stage2 reads of Cs done; Vw ready

    // stage scaled O into Osm (= Cs region, [64][68])
    #pragma unroll
    for (int mt = 0; mt < 2; mt++) {
        #pragma unroll
        for (int nt = 0; nt < 2; nt++) {
            const int c = wn * 16 + nt * 8 + 2 * tg;
            const int r0 = 32 * wm + 16 * mt + g;
            float4 v = acc2[mt][nt];
            float2 lo; lo.x = v.x * invL[2 * mt]; lo.y = v.y * invL[2 * mt];
            float2 hi; hi.x = v.z * invL[2 * mt + 1]; hi.y = v.w * invL[2 * mt + 1];
            *(float2*)&Cs[r0 * 68 + c] = lo;
            *(float2*)&Cs[(r0 + 8) * 68 + c] = hi;
        }
    }
    __syncthreads();

    // conv + write to Y (transposed layout, rounded for the out-proj GEMM)
    const float* wv = Qs + 6144;
    #pragma unroll
    for (int i2 = 0; i2 < 4; i2++) {
        int l4 = tid + i2 * 256;            // 1024 float4s = 64 rows x 16
        int i = l4 >> 4, d4 = (l4 & 15) << 2;
        float4 o = *(float4*)&Cs[i * 68 + d4];
        #pragma unroll
        for (int t = 0; t < 33; t++) {
            float wt = wv[t];
            float4 vv = *(float4*)&Qs[(i + t) * 64 + d4];
            o.x += wt * vv.x; o.y += wt * vv.y; o.z += wt * vv.z; o.w += wt * vv.w;
        }
        o.x = to_tf32(o.x); o.y = to_tf32(o.y); o.z = to_tf32(o.z); o.w = to_tf32(o.w);
        *(float4*)&Yg[(size_t)(b * SEQ + i0 + i) * DM + h * 64 + d4] = o;
    }
}

// landmarks: mean over 32 consecutive tokens (rounded outputs)
__global__ void k_land() {
    int idx = blockIdx.x * blockDim.x + threadIdx.x;   // BH*NM*DH
    int d = idx & 63, i = (idx >> 6) & 255, bh = idx >> 14;
    size_t base = (size_t)bh * SEQ * DH + (size_t)i * LG * DH + d;
    float qs = 0.f, ks = 0.f;
    #pragma unroll 8
    for (int j = 0; j < LG; j++) { qs += g_q[base + j * 64]; ks += g_k[base + j * 64]; }
    g_ql[idx] = to_tf32(qs * (1.f / LG));
    g_kl[idx] = to_tf32(ks * (1.f / LG));
}

// Row softmax (in place, rounded), 256 cols, one block per row.
__global__ void k_softmax(float* __restrict__ X) {
    const size_t base = (size_t)blockIdx.x * 256;
    const int tid = threadIdx.x, lane = tid & 31, wp = tid >> 5;
    __shared__ float red[8];
    float v = X[base + tid];
    float m = v;
    #pragma unroll
    for (int off = 16; off; off >>= 1) m = fmaxf(m, __shfl_xor_sync(0xffffffffu, m, off));
    if (!lane) red[wp] = m;
    __syncthreads();
    float M = red[0];
    #pragma unroll
    for (int w = 1; w < 8; w++) M = fmaxf(M, red[w]);
    __syncthreads();
    float e = __expf(v - M);
    float s = e;
    #pragma unroll
    for (int off = 16; off; off >>= 1) s += __shfl_xor_sync(0xffffffffu, s, off);
    if (!lane) red[wp] = s;
    __syncthreads();
    float S = 0.f;
    #pragma unroll
    for (int w = 0; w < 8; w++) S += red[w];
    X[base + tid] = to_tf32(e / S);
}

// reset: g_mx and pinv barrier counters (standalone, strictly before pinv)
__global__ void k_reset() {
    if (threadIdx.x < 2) g_mx[threadIdx.x] = 0u;
    if (threadIdx.x < BH) g_bar[threadIdx.x] = 0u;
}

__global__ void k_colrowmax() {
    const int bh = blockIdx.x, tid = threadIdx.x, lane = tid & 31, wp = tid >> 5;
    __shared__ float red[8];
    const float* Xb = g_X + (size_t)bh * NM * NM;
    float cs = 0.f;
    for (int i = 0; i < NM; i++) cs += Xb[i * NM + tid];
    float m = cs;
    #pragma unroll
    for (int off = 16; off; off >>= 1) m = fmaxf(m, __shfl_xor_sync(0xffffffffu, m, off));
    if (!lane) red[wp] = m;
    __syncthreads();
    if (tid == 0) {
        float M = red[0];
        #pragma unroll
        for (int w = 1; w < 8; w++) M = fmaxf(M, red[w]);
        atomicMax(&g_mx[1], __float_as_uint(M));
    }
    __syncthreads();
    float rs = 0.f;
    const float* Xr = Xb + (size_t)tid * NM;
    for (int j = 0; j < NM; j++) rs += Xr[j];
    m = rs;
    #pragma unroll
    for (int off = 16; off; off >>= 1) m = fmaxf(m, __shfl_xor_sync(0xffffffffu, m, off));
    if (!lane) red[wp] = m;
    __syncthreads();
    if (tid == 0) {
        float M = red[0];
        #pragma unroll
        for (int w = 1; w < 8; w++) M = fmaxf(M, red[w]);
        atomicMax(&g_mx[0], __float_as_uint(M));
    }
}

__global__ void k_zinit() {
    int idx = blockIdx.x * blockDim.x + threadIdx.x;   // BH*NM*NM
    float inv = 1.f / (__uint_as_float(g_mx[0]) * __uint_as_float(g_mx[1]));
    int j = idx & 255, i = (idx >> 8) & 255, bh = idx >> 16;
    g_Za[idx] = to_tf32(g_X[(size_t)bh * NM * NM + j * NM + i] * inv);
}

// =====================================================================
extern "C" void kernel_launch(void* const* d_in, const int* in_sizes, int n_in,
                              void* d_out, int out_size) {
    const float* x     = (const float*)d_in[0];
    const float* w_qkv = (const float*)d_in[1];
    const float* w_out = (const float*)d_in[2];
    const float* b_out = (const float*)d_in[3];
    const float* w_res = (const float*)d_in[4];
    float* out = (float*)d_out;

    float *q, *k_, *v, *ql, *kl, *X, *Za, *C2, *Cm, *Y, *wr;
    cudaGetSymbolAddress((void**)&q,   g_q);
    cudaGetSymbolAddress((void**)&k_,  g_k);
    cudaGetSymbolAddress((void**)&v,   g_v);
    cudaGetSymbolAddress((void**)&ql,  g_ql);
    cudaGetSymbolAddress((void**)&kl,  g_kl);
    cudaGetSymbolAddress((void**)&X,   g_X);
    cudaGetSymbolAddress((void**)&Za,  g_Za);
    cudaGetSymbolAddress((void**)&C2,  g_C2);
    cudaGetSymbolAddress((void**)&Cm,  g_Cm);
    cudaGetSymbolAddress((void**)&Y,   g_Y);
    cudaGetSymbolAddress((void**)&wr,  g_wr);

    // dynamic smem opt-in (floats: A 3*2560; B per layout)
    const int SM_NN128 = (3 * 2560 + 3 * 16 * 136) * 4;   // 56832
    const int SM_TN128 = (3 * 2560 + 3 * 128 * 20) * 4;   // 61440
    const int SM_NN64  = (3 * 2560 + 3 * 16 * 72) * 4;    // 44544
    cudaFuncSetAttribute(t_gemm<128, 2, false, 1, 1>, cudaFuncAttributeMaxDynamicSharedMemorySize, SM_NN128);
    cudaFuncSetAttribute(t_gemm<128, 2, false, 0, 0>, cudaFuncAttributeMaxDynamicSharedMemorySize, SM_NN128);
    cudaFuncSetAttribute(t_gemm<128, 2, true, 0, 0>,  cudaFuncAttributeMaxDynamicSharedMemorySize, SM_TN128);
    cudaFuncSetAttribute(t_gemm<64, 1, false, 0, 1>,  cudaFuncAttributeMaxDynamicSharedMemorySize, SM_NN64);
    cudaFuncSetAttribute(k_pinv,   cudaFuncAttributeMaxDynamicSharedMemorySize, SM_NN128);
    cudaFuncSetAttribute(k_fattn1, cudaFuncAttributeMaxDynamicSharedMemorySize, FA1_SMEM);
    cudaFuncSetAttribute(k_fattn3, cudaFuncAttributeMaxDynamicSharedMemorySize, FA3_SMEM);

    const float* NUL = (const float*)0;
    float* NULF = (float*)0;

    // 0. pre-round true inputs to tf32: x->g_Y, w_qkv|w_out->g_wr
    k_round3<<<17408, 256>>>(x, w_qkv, w_out);
    // 1. qkv = x_r @ w_qkv_r, scattered directly to packed q (scaled), k, v (rounded)
    t_gemm<128, 2, false, 1, 1><<<dim3(TRIPLE / 128, ROWS / 128, 1), 256, SM_NN128>>>(
        Y, DM, 0LL, wr, TRIPLE, 0LL, NUL, 0LL, NUL, q, TRIPLE, 0LL,
        DM, 1.f, 0.f, 1, q, k_, v);
    // 2. landmarks
    k_land<<<(BH * NM * DH) / 256, 256>>>();
    // 3. attn2 = softmax(q_land @ k_land^T)
    t_gemm<128, 2, true, 0, 0><<<dim3(2, 2, BH), 256, SM_TN128>>>(
        ql, DH, 16384LL, kl, DH, 16384LL, NUL, 0LL, NUL, X, NM, 65536LL,
        DH, 1.f, 0.f, 1, NULF, NULF, NULF);
    k_softmax<<<BH * NM, 256>>>(X);
    // 4. pinv init (standalone reset strictly before pinv)
    k_reset<<<1, 32>>>();
    k_colrowmax<<<BH, 256>>>();
    k_zinit<<<(BH * NM * NM) / 256, 256>>>();
    // 5. 6 Newton iterations, one persistent launch (result in g_Za)
    k_pinv<<<128, 256, SM_NN128>>>();
    // 6. fused flash sim3 path: C2 = softmax(ql @ k^T) @ v
    k_fattn3<<<dim3(4, BH), 256, FA3_SMEM>>>(ql, k_, v, C2);
    // 7. Cm = Z @ C2 (rounded)
    t_gemm<64, 1, false, 0, 1><<<dim3(1, 2, BH), 128, SM_NN64>>>(
        Za, NM, 65536LL, C2, DH, 16384LL, NUL, 0LL, NUL, Cm, DH, 16384LL,
        NM, 1.f, 0.f, 1, NULF, NULF, NULF);
    // 8. fused: Y = softmax(q @ kl^T) @ Cm + conv33(v), transposed (rounded)
    k_fattn1<<<dim3(SEQ / 64, BH), 256, FA1_SMEM>>>(q, kl, Cm, v, w_res, Y);
    // 9. out = Y @ w_out_r + b_out (full precision store)
    t_gemm<128, 2, false, 0, 0><<<dim3(DM / 128, ROWS / 128, 1), 256, SM_NN128>>>(
        Y, DM, 0LL, wr + TRIPLE * DM, DM, 0LL, NUL, 0LL, b_out, out, DM, 0LL,
        DM, 1.f, 0.f, 1, NULF, NULF, NULF);
}

// round 16
// speedup vs baseline: 3.0157x; 1.1567x over previous
#include <cuda_runtime.h>
#include <cuda_bf16.h>
#include <math.h>

#define NB      4
#define SEQ     8192
#define DM      512
#define NH      8
#define DH      64
#define NM      256
#define LG      32
#define BH      32          // NB*NH
#define TRIPLE  1536
#define ROWS    32768       // NB*SEQ

// ---------------- scratch (device globals; no allocations allowed) -------
__device__ float g_q [(size_t)BH * SEQ * DH];         // packed tf32, pre-scaled by dh^-0.5
__device__ float g_k [(size_t)BH * SEQ * DH];
__device__ float g_v [(size_t)BH * SEQ * DH];
__device__ float g_ql[BH * NM * DH];
__device__ float g_kl[BH * NM * DH];
__device__ float g_X [BH * NM * NM];                  // attn2 (tf32 after softmax)
__device__ float g_Za[BH * NM * NM];
__device__ float g_Zb[BH * NM * NM];
__device__ float g_XZ[BH * NM * NM];
__device__ float g_T1[BH * NM * NM];
__device__ float g_T2[BH * NM * NM];
__device__ float g_C2[BH * NM * DH];                  // softmax(sim3) @ v
__device__ float g_Cm[BH * NM * DH];                  // Z @ C2
__device__ float g_Y [(size_t)ROWS * DM];             // step0: x_r; step8+: pre-out-proj
__device__ float g_wr[TRIPLE * DM + DM * DM];         // rounded w_qkv | w_out
__device__ unsigned int g_mx[2];
__device__ unsigned int g_bar[BH];                    // pinv inter-CTA barrier

// ---------------- helpers ----------------
__device__ __forceinline__ float to_tf32(float x) {
    unsigned u; asm("cvt.rna.tf32.f32 %0, %1;" : "=r"(u) : "f"(x));
    return __uint_as_float(u);
}
__device__ __forceinline__ void mma8(float4& d, float a0, float a1, float a2, float a3,
                                     float b0, float b1) {
    asm volatile(
        "mma.sync.aligned.m16n8k8.row.col.f32.tf32.tf32.f32 "
        "{%0,%1,%2,%3}, {%4,%5,%6,%7}, {%8,%9}, {%0,%1,%2,%3};"
        : "+f"(d.x), "+f"(d.y), "+f"(d.z), "+f"(d.w)
        : "r"(__float_as_uint(a0)), "r"(__float_as_uint(a1)),
          "r"(__float_as_uint(a2)), "r"(__float_as_uint(a3)),
          "r"(__float_as_uint(b0)), "r"(__float_as_uint(b1)));
}
__device__ __forceinline__ void cpa16(void* s, const void* g) {
    unsigned sa = (unsigned)__cvta_generic_to_shared(s);
    asm volatile("cp.async.cg.shared.global [%0], [%1], 16;" :: "r"(sa), "l"(g));
}
__device__ __forceinline__ void cpa16z(void* s, const void* g, bool ok) {
    unsigned sa = (unsigned)__cvta_generic_to_shared(s);
    int sz = ok ? 16 : 0;
    asm volatile("cp.async.cg.shared.global [%0], [%1], 16, %2;" :: "r"(sa), "l"(g), "r"(sz));
}

// pre-round true inputs: x -> g_Y, w_qkv|w_out -> g_wr
__global__ void k_round3(const float* __restrict__ x, const float* __restrict__ wq,
                         const float* __restrict__ wo) {
    int i = blockIdx.x * 256 + threadIdx.x;
    const int NX = (ROWS * DM) >> 2;        // 4194304
    const int NW = (TRIPLE * DM) >> 2;      // 196608
    float4 v; float4* dst;
    if (i < NX)            { v = ((const float4*)x)[i];            dst = (float4*)g_Y + i; }
    else if (i < NX + NW)  { int j = i - NX;      v = ((const float4*)wq)[j]; dst = (float4*)g_wr + j; }
    else                   { int j = i - NX - NW; v = ((const float4*)wo)[j];
                             dst = (float4*)(g_wr + TRIPLE * DM) + j; }
    float4 r; r.x = to_tf32(v.x); r.y = to_tf32(v.y); r.z = to_tf32(v.z); r.w = to_tf32(v.w);
    *dst = r;
}

// =====================================================================
// TF32 tensor-core GEMM, cp.async 3-stage pipeline. Operands in memory are
// already exactly-tf32 (producer-rounded), so fragments feed MMA raw.
// BM=128, BN in {128,64}. BK=16.
// EPI==0: C = alpha*(A@B[^T]) + beta*D (+bias); RC rounds stores to tf32.
// EPI==1: qkv scatter epilogue into q/k/v (q scaled by 0.125), rounded.
// =====================================================================
template<int BN, int WARPS_N, bool TRANSB, int EPI, int RC>
__global__ __launch_bounds__(128 * WARPS_N)
void t_gemm(const float* __restrict__ A, int lda, long long sA,
            const float* __restrict__ B, int ldb, long long sB,
            const float* __restrict__ D, long long sD,
            const float* __restrict__ bias,
            float* __restrict__ C, int ldc, long long sC,
            int K, float alpha, float beta, int ksplit,
            float* __restrict__ qp, float* __restrict__ kp, float* __restrict__ vp)
{
    constexpr int NT   = 128 * WARPS_N;
    constexpr int ASTG = 128 * 20;
    constexpr int BSTG = TRANSB ? BN * 20 : 16 * (BN + 8);
    constexpr int ACH  = 512 / NT;        // 16B chunks per thread per stage
    constexpr int BCH  = 4 * BN / NT;
    extern __shared__ float smp[];
    float* As = smp;
    float* Bs = smp + 3 * ASTG;

    const int tid = threadIdx.x;
    const int z = blockIdx.z;
    const int bh = z / ksplit, sk = z - bh * ksplit;
    const float* Ab = A + (size_t)bh * sA + (size_t)blockIdx.y * 128 * lda + (size_t)sk * K;
    const float* Bb;
    if (TRANSB) Bb = B + (size_t)bh * sB + (size_t)blockIdx.x * BN * ldb + (size_t)sk * K;
    else        Bb = B + (size_t)bh * sB + (size_t)sk * K * ldb + blockIdx.x * BN;

    const int lane = tid & 31, g = lane >> 2, tg = lane & 3;
    const int wid = tid >> 5, wm = wid & 3, wn = wid >> 2;

    auto issue = [&](int kb, int st) {
        #pragma unroll
        for (int i = 0; i < ACH; i++) {
            int id = tid + i * NT;
            int row = id >> 2, c4 = id & 3;
            cpa16(&As[st * ASTG + row * 20 + c4 * 4],
                  Ab + (size_t)row * lda + kb * 16 + c4 * 4);
        }
        #pragma unroll
        for (int i = 0; i < BCH; i++) {
            int id = tid + i * NT;
            if constexpr (TRANSB) {
                int row = id >> 2, c4 = id & 3;
                cpa16(&Bs[st * BSTG + row * 20 + c4 * 4],
                      Bb + (size_t)row * ldb + kb * 16 + c4 * 4);
            } else {
                int kr = id / (BN / 4), n4 = id % (BN / 4);
                cpa16(&Bs[st * BSTG + kr * (BN + 8) + n4 * 4],
                      Bb + (size_t)(kb * 16 + kr) * ldb + n4 * 4);
            }
        }
        asm volatile("cp.async.commit_group;");
    };

    float4 acc[2][8];
    #pragma unroll
    for (int i = 0; i < 2; i++)
        #pragma unroll
        for (int j = 0; j < 8; j++) acc[i][j] = make_float4(0.f, 0.f, 0.f, 0.f);

    const int kblocks = K >> 4;
    issue(0, 0); issue(1, 1);
    for (int kb = 0; kb < kblocks; kb++) {
        if (kb + 1 < kblocks) { asm volatile("cp.async.wait_group 1;"); }
        else                  { asm volatile("cp.async.wait_group 0;"); }
        __syncthreads();
        if (kb + 2 < kblocks) issue(kb + 2, (kb + 2) % 3);
        const float* Ac = As + (kb % 3) * ASTG;
        const float* Bc = Bs + (kb % 3) * BSTG;
        #pragma unroll
        for (int s8 = 0; s8 < 16; s8 += 8) {
            float a[2][4];
            #pragma unroll
            for (int mt = 0; mt < 2; mt++) {
                const int Rm = wm * 32 + mt * 16 + g;
                a[mt][0] = Ac[Rm * 20 + s8 + tg];
                a[mt][1] = Ac[(Rm + 8) * 20 + s8 + tg];
                a[mt][2] = Ac[Rm * 20 + s8 + tg + 4];
                a[mt][3] = Ac[(Rm + 8) * 20 + s8 + tg + 4];
            }
            #pragma unroll
            for (int nt = 0; nt < 8; nt++) {
                const int c = wn * 64 + nt * 8 + g;
                float b0, b1;
                if constexpr (TRANSB) {
                    b0 = Bc[c * 20 + s8 + tg];
                    b1 = Bc[c * 20 + s8 + tg + 4];
                } else {
                    b0 = Bc[(s8 + tg) * (BN + 8) + c];
                    b1 = Bc[(s8 + tg + 4) * (BN + 8) + c];
                }
                #pragma unroll
                for (int mt = 0; mt < 2; mt++)
                    mma8(acc[mt][nt], a[mt][0], a[mt][1], a[mt][2], a[mt][3], b0, b1);
            }
        }
    }

    // epilogue
    const int r00 = blockIdx.y * 128 + wm * 32;
    #pragma unroll
    for (int mt = 0; mt < 2; mt++) {
        #pragma unroll
        for (int nt = 0; nt < 8; nt++) {
            const int r0 = r00 + mt * 16 + g;
            const int cb = blockIdx.x * BN + wn * 64 + nt * 8 + tg * 2;
            float4 v = acc[mt][nt];
            if constexpr (EPI == 1) {
                const int which = cb >> 9, rem = cb & 511;
                const int h = rem >> 6, d = rem & 63;
                const float s = (which == 0) ? 0.125f : 1.0f;
                float* dst = (which == 0) ? qp : ((which == 1) ? kp : vp);
                int b = r0 >> 13, ii = r0 & 8191;
                float2 lo; lo.x = to_tf32(v.x * s); lo.y = to_tf32(v.y * s);
                *(float2*)&dst[(((size_t)(b * 8 + h) * 8192 + ii) << 6) + d] = lo;
                const int r1 = r0 + 8; b = r1 >> 13; ii = r1 & 8191;
                float2 hi; hi.x = to_tf32(v.z * s); hi.y = to_tf32(v.w * s);
                *(float2*)&dst[(((size_t)(b * 8 + h) * 8192 + ii) << 6) + d] = hi;
            } else {
                float* Cb = C + (size_t)z * sC;
                const float* Db = D + (size_t)bh * sD;
                float2 lo, hi;
                lo.x = alpha * v.x; lo.y = alpha * v.y;
                hi.x = alpha * v.z; hi.y = alpha * v.w;
                if (beta != 0.f) {
                    float2 dlo = *(const float2*)&Db[(size_t)r0 * ldc + cb];
                    float2 dhi = *(const float2*)&Db[(size_t)(r0 + 8) * ldc + cb];
                    lo.x += beta * dlo.x; lo.y += beta * dlo.y;
                    hi.x += beta * dhi.x; hi.y += beta * dhi.y;
                }
                if (bias) {
                    float2 bv = *(const float2*)&bias[cb];
                    lo.x += bv.x; lo.y += bv.y; hi.x += bv.x; hi.y += bv.y;
                }
                if constexpr (RC) {
                    lo.x = to_tf32(lo.x); lo.y = to_tf32(lo.y);
                    hi.x = to_tf32(hi.x); hi.y = to_tf32(hi.y);
                }
                *(float2*)&Cb[(size_t)r0 * ldc + cb] = lo;
                *(float2*)&Cb[(size_t)(r0 + 8) * ldc + cb] = hi;
            }
        }
    }
}

// =====================================================================
// Persistent pinv: 24 chained GEMM steps, one launch.
// 256 CTAs, 8 per bh (128x64 tiles: by in {0,1}, bx in {0..3}).
// 2 CTAs/SM residency (296 >= 256) keeps the per-bh barrier safe.
// =====================================================================
__global__ __launch_bounds__(256)
void k_pinv() {
    constexpr int ASTG = 128 * 20;
    constexpr int BSTG = 16 * 72;
    extern __shared__ float smp[];
    float* As = smp;
    float* Bs = smp + 3 * ASTG;

    const int bh = blockIdx.x >> 3;
    const int oct = blockIdx.x & 7;
    const int by = oct >> 2, bx = oct & 3;
    const int tid = threadIdx.x;
    const int lane = tid & 31, g = lane >> 2, tg = lane & 3;
    const int wid = tid >> 5, wm = wid & 3, wn = wid >> 2;   // wn in {0,1}

    float* Xp  = g_X  + (size_t)bh * 65536;
    float* XZp = g_XZ + (size_t)bh * 65536;
    float* T1p = g_T1 + (size_t)bh * 65536;
    float* T2p = g_T2 + (size_t)bh * 65536;
    float* Zc  = g_Za + (size_t)bh * 65536;
    float* Zn  = g_Zb + (size_t)bh * 65536;
    unsigned int* bar = &g_bar[bh];

    for (int s = 0; s < 24; s++) {
        const int sub = s & 3;
        const float *Asrc, *Bsrc, *Dsrc; float* Cdst; float alpha, beta;
        if (sub == 0)      { Asrc = Xp;  Bsrc = Zc;  Dsrc = 0;   Cdst = XZp; alpha = 1.f;    beta = 0.f;   }
        else if (sub == 1) { Asrc = XZp; Bsrc = XZp; Dsrc = XZp; Cdst = T1p; alpha = -1.f;   beta = 7.f;   }
        else if (sub == 2) { Asrc = XZp; Bsrc = T1p; Dsrc = XZp; Cdst = T2p; alpha = -1.f;   beta = 15.f;  }
        else               { Asrc = Zc;  Bsrc = T2p; Dsrc = Zc;  Cdst = Zn;  alpha = -0.25f; beta = 3.25f; }

        const float* Ab = Asrc + (size_t)by * 128 * 256;
        const float* Bb = Bsrc + bx * 64;

        auto issue = [&](int kb, int st) {
            #pragma unroll
            for (int i = 0; i < 2; i++) {
                int id = tid + i * 256;
                int row = id >> 2, c4 = id & 3;
                cpa16(&As[st * ASTG + row * 20 + c4 * 4],
                      Ab + (size_t)row * 256 + kb * 16 + c4 * 4);
            }
            {
                int kr = tid >> 4, n4 = tid & 15;
                cpa16(&Bs[st * BSTG + kr * 72 + n4 * 4],
                      Bb + (size_t)(kb * 16 + kr) * 256 + n4 * 4);
            }
            asm volatile("cp.async.commit_group;");
        };

        float4 acc[2][4];
        #pragma unroll
        for (int i = 0; i < 2; i++)
            #pragma unroll
            for (int j = 0; j < 4; j++) acc[i][j] = make_float4(0.f, 0.f, 0.f, 0.f);

        issue(0, 0); issue(1, 1);
        for (int kb = 0; kb < 16; kb++) {
            if (kb + 1 < 16) { asm volatile("cp.async.wait_group 1;"); }
            else             { asm volatile("cp.async.wait_group 0;"); }
            __syncthreads();
            if (kb + 2 < 16) issue(kb + 2, (kb + 2) % 3);
            const float* Ac = As + (kb % 3) * ASTG;
            const float* Bc = Bs + (kb % 3) * BSTG;
            #pragma unroll
            for (int s8 = 0; s8 < 16; s8 += 8) {
                float a[2][4];
                #pragma unroll
                for (int mt = 0; mt < 2; mt++) {
                    const int Rm = wm * 32 + mt * 16 + g;
                    a[mt][0] = Ac[Rm * 20 + s8 + tg];
                    a[mt][1] = Ac[(Rm + 8) * 20 + s8 + tg];
                    a[mt][2] = Ac[Rm * 20 + s8 + tg + 4];
                    a[mt][3] = Ac[(Rm + 8) * 20 + s8 + tg + 4];
                }
                #pragma unroll
                for (int nt = 0; nt < 4; nt++) {
                    const int c = wn * 32 + nt * 8 + g;
                    float b0 = Bc[(s8 + tg) * 72 + c];
                    float b1 = Bc[(s8 + tg + 4) * 72 + c];
                    #pragma unroll
                    for (int mt = 0; mt < 2; mt++)
                        mma8(acc[mt][nt], a[mt][0], a[mt][1], a[mt][2], a[mt][3], b0, b1);
                }
            }
        }

        // epilogue (D via __ldcg; store rounded)
        #pragma unroll
        for (int mt = 0; mt < 2; mt++) {
            #pragma unroll
            for (int nt = 0; nt < 4; nt++) {
                const int r0 = by * 128 + wm * 32 + mt * 16 + g;
                const int cb = bx * 64 + wn * 32 + nt * 8 + tg * 2;
                float4 v = acc[mt][nt];
                float2 lo, hi;
                lo.x = alpha * v.x; lo.y = alpha * v.y;
                hi.x = alpha * v.z; hi.y = alpha * v.w;
                if (beta != 0.f) {
                    float2 dlo = __ldcg((const float2*)&Dsrc[(size_t)r0 * 256 + cb]);
                    float2 dhi = __ldcg((const float2*)&Dsrc[(size_t)(r0 + 8) * 256 + cb]);
                    lo.x += beta * dlo.x; lo.y += beta * dlo.y;
                    hi.x += beta * dhi.x; hi.y += beta * dhi.y;
                }
                lo.x = to_tf32(lo.x); lo.y = to_tf32(lo.y);
                hi.x = to_tf32(hi.x); hi.y = to_tf32(hi.y);
                *(float2*)&Cdst[(size_t)r0 * 256 + cb] = lo;
                *(float2*)&Cdst[(size_t)(r0 + 8) * 256 + cb] = hi;
            }
        }

        // per-bh barrier: all 8 CTAs finish step s before anyone starts s+1
        __threadfence();
        __syncthreads();
        if (tid == 0) {
            asm volatile("red.release.gpu.global.add.u32 [%0], %1;"
                         :: "l"(bar), "r"(1u) : "memory");
            const unsigned target = 8u * (unsigned)(s + 1);
            unsigned cur;
            do {
                __nanosleep(64);
                asm volatile("ld.acquire.gpu.global.u32 %0, [%1];" : "=r"(cur) : "l"(bar));
            } while (cur < target);
        }
        __syncthreads();

        if (sub == 3) { float* t = Zc; Zc = Zn; Zn = t; }
    }
}

// =====================================================================
// Flash-style fused sim3 path (ql/k/v producer-rounded; no fill cvt)
// =====================================================================
#define FA3_SMEM (207872)
__global__ __launch_bounds__(256)
void k_fattn3(const float* __restrict__ qlg, const float* __restrict__ kg,
              const float* __restrict__ vg, float* __restrict__ c2)
{
    extern __shared__ float sm[];
    float* Qs = sm;                         // [kk<64][g<8][x<16]
    float* Ks = sm + 8192;                  // 2 stages, [c<128][68]
    float* Vs = sm + 8192 + 2 * 8704;       // 2 stages, [c<128][68]
    float* Ps = sm + 8192 + 4 * 8704;       // [row<64][132]
    float* Mp = Ps + 8448;                  // [4][64]
    float* Lp = Mp + 256;                   // [4][64]

    const int bh = blockIdx.y;
    const int i0 = blockIdx.x * 64;
    const int tid = threadIdx.x;
    const int lane = tid & 31, g = lane >> 2, tg = lane & 3;
    const int wid = tid >> 5, wm = wid & 1, wn = wid >> 1;
    const int sw = tg << 2;

    const float* kb = kg + (size_t)bh * SEQ * DH;
    const float* vb = vg + (size_t)bh * SEQ * DH;

    auto issue = [&](int j, int st) {
        const int cb = j * 128;
        #pragma unroll
        for (int i = 0; i < 8; i++) {
            int t4 = tid + i * 256;
            int row = t4 >> 4, q4 = (t4 & 15) << 2;
            cpa16(&Ks[st * 8704 + row * 68 + q4], kb + (size_t)(cb + row) * 64 + q4);
        }
        #pragma unroll
        for (int i = 0; i < 8; i++) {
            int t4 = tid + i * 256;
            int row = t4 >> 4, q4 = (t4 & 15) << 2;
            cpa16(&Vs[st * 8704 + row * 68 + q4], vb + (size_t)(cb + row) * 64 + q4);
        }
        asm volatile("cp.async.commit_group;");
    };

    issue(0, 0);

    const float* qb = qlg + ((size_t)bh * NM + i0) * 64;
    #pragma unroll
    for (int i = 0; i < 4; i++) {
        int t4 = tid + i * 256; int row = t4 >> 4, kq = (t4 & 15) << 2;
        float4 v = *(const float4*)(qb + row * 64 + kq);
        float vv[4] = {v.x, v.y, v.z, v.w};
        #pragma unroll
        for (int j = 0; j < 4; j++) {
            int kk = kq + j;
            Qs[kk * 128 + (row & 7) * 16 + ((row >> 3) ^ ((kk & 3) << 2))] = vv[j];
        }
    }

    float4 acc2[2][2];
    #pragma unroll
    for (int i = 0; i < 2; i++)
        #pragma unroll
        for (int j = 0; j < 2; j++) acc2[i][j] = make_float4(0.f, 0.f, 0.f, 0.f);
    float Mrun[4] = {-1e30f, -1e30f, -1e30f, -1e30f};
    float Lrun[4] = {0.f, 0.f, 0.f, 0.f};

    for (int jt = 0; jt < SEQ / 128; jt++) {
        const int cur = jt & 1;
        if (jt + 1 < SEQ / 128) {
            issue(jt + 1, cur ^ 1);
            asm volatile("cp.async.wait_group 1;");
        } else {
            asm volatile("cp.async.wait_group 0;");
        }
        __syncthreads();

        const float* Kc = Ks + cur * 8704;
        const float* Vc = Vs + cur * 8704;

        float4 acc1[2][4];
        #pragma unroll
        for (int i = 0; i < 2; i++)
            #pragma unroll
            for (int j = 0; j < 4; j++) acc1[i][j] = make_float4(0.f, 0.f, 0.f, 0.f);
        #pragma unroll
        for (int s8 = 0; s8 < 64; s8 += 8) {
            const int k0 = s8 + tg;
            float4 aLo = *(const float4*)&Qs[k0 * 128 + g * 16 + ((wm * 4) ^ sw)];
            float4 aHi = *(const float4*)&Qs[(k0 + 4) * 128 + g * 16 + ((wm * 4) ^ sw)];
            float am[2][4] = {{aLo.x, aLo.y, aHi.x, aHi.y}, {aLo.z, aLo.w, aHi.z, aHi.w}};
            #pragma unroll
            for (int nt = 0; nt < 4; nt++) {
                const float* kr = Kc + (wn * 32 + nt * 8 + g) * 68;
                float b0 = kr[k0], b1 = kr[k0 + 4];
                #pragma unroll
                for (int mt = 0; mt < 2; mt++)
                    mma8(acc1[mt][nt], am[mt][0], am[mt][1], am[mt][2], am[mt][3], b0, b1);
            }
        }

        float tmax[4];
        #pragma unroll
        for (int t = 0; t < 4; t++) {
            const int mt = t >> 1; const bool hi = t & 1;
            float m = -1e30f;
            #pragma unroll
            for (int nt = 0; nt < 4; nt++) {
                float4 a = acc1[mt][nt];
                m = fmaxf(m, hi ? fmaxf(a.z, a.w) : fmaxf(a.x, a.y));
            }
            m = fmaxf(m, __shfl_xor_sync(0xffffffffu, m, 1));
            m = fmaxf(m, __shfl_xor_sync(0xffffffffu, m, 2));
            tmax[t] = m;
        }
        if (tg == 0) {
            #pragma unroll
            for (int t = 0; t < 4; t++) Mp[wn * 64 + wm * 32 + 8 * t + g] = tmax[t];
        }
        __syncthreads();

        float f[4];
        #pragma unroll
        for (int t = 0; t < 4; t++) {
            const int rl = wm * 32 + 8 * t + g;
            float tm = fmaxf(fmaxf(Mp[rl], Mp[64 + rl]),
                             fmaxf(Mp[128 + rl], Mp[192 + rl]));
            float Mn = fmaxf(Mrun[t], tm);
            f[t] = __expf(Mrun[t] - Mn);
            Mrun[t] = Mn;
        }
        #pragma unroll
        for (int mt2 = 0; mt2 < 2; mt2++)
            #pragma unroll
            for (int nt2 = 0; nt2 < 2; nt2++) {
                acc2[mt2][nt2].x *= f[2 * mt2];     acc2[mt2][nt2].y *= f[2 * mt2];
                acc2[mt2][nt2].z *= f[2 * mt2 + 1]; acc2[mt2][nt2].w *= f[2 * mt2 + 1];
            }
        #pragma unroll
        for (int t = 0; t < 4; t++) {
            const int mt = t >> 1; const bool hi = t & 1;
            const int rl = wm * 32 + 8 * t + g;
            const float M = Mrun[t];
            float s = 0.f;
            #pragma unroll
            for (int nt = 0; nt < 4; nt++) {
                float4 a = acc1[mt][nt];
                float v0 = hi ? a.z : a.x, v1 = hi ? a.w : a.y;
                float e0 = __expf(v0 - M), e1 = __expf(v1 - M);
                s += e0 + e1;
                int c0 = wn * 32 + nt * 8 + 2 * tg;
                Ps[rl * 132 + c0] = e0;
                Ps[rl * 132 + c0 + 1] = e1;
            }
            s += __shfl_xor_sync(0xffffffffu, s, 1);
            s += __shfl_xor_sync(0xffffffffu, s, 2);
            if (tg == 0) Lp[wn * 64 + rl] = s;
        }
        __syncthreads();
        #pragma unroll
        for (int t = 0; t < 4; t++) {
            const int rl = wm * 32 + 8 * t + g;
            Lrun[t] = Lrun[t] * f[t] + (Lp[rl] + Lp[64 + rl] + Lp[128 + rl] + Lp[192 + rl]);
        }

        #pragma unroll 4
        for (int s8 = 0; s8 < 128; s8 += 8) {
            const int k0 = s8 + tg, k1 = k0 + 4;
            float a_[2][4], b_[2][2];
            #pragma unroll
            for (int mt2 = 0; mt2 < 2; mt2++) {
                const int r0 = wm * 32 + 16 * mt2 + g;
                a_[mt2][0] = Ps[r0 * 132 + k0];
                a_[mt2][1] = Ps[(r0 + 8) * 132 + k0];
                a_[mt2][2] = Ps[r0 * 132 + k1];
                a_[mt2][3] = Ps[(r0 + 8) * 132 + k1];
            }
            #pragma unroll
            for (int nt2 = 0; nt2 < 2; nt2++) {
                const int c = wn * 16 + nt2 * 8 + g;
                b_[nt2][0] = Vc[k0 * 68 + c];
                b_[nt2][1] = Vc[k1 * 68 + c];
            }
            #pragma unroll
            for (int mt2 = 0; mt2 < 2; mt2++)
                #pragma unroll
                for (int nt2 = 0; nt2 < 2; nt2++)
                    mma8(acc2[mt2][nt2], a_[mt2][0], a_[mt2][1], a_[mt2][2], a_[mt2][3],
                         b_[nt2][0], b_[nt2][1]);
        }
        __syncthreads();
    }

    float invL[4];
    #pragma unroll
    for (int t = 0; t < 4; t++) invL[t] = 1.f / Lrun[t];
    float* ob = c2 + ((size_t)bh * NM + i0) * 64;
    #pragma unroll
    for (int mt2 = 0; mt2 < 2; mt2++) {
        #pragma unroll
        for (int nt2 = 0; nt2 < 2; nt2++) {
            const int c = wn * 16 + nt2 * 8 + 2 * tg;
            const int r0 = wm * 32 + 16 * mt2 + g;
            float4 v = acc2[mt2][nt2];
            float2 lo; lo.x = to_tf32(v.x * invL[2 * mt2]);     lo.y = to_tf32(v.y * invL[2 * mt2]);
            float2 hi; hi.x = to_tf32(v.z * invL[2 * mt2 + 1]); hi.y = to_tf32(v.w * invL[2 * mt2 + 1]);
            *(float2*)&ob[(size_t)r0 * 64 + c] = lo;
            *(float2*)&ob[(size_t)(r0 + 8) * 64 + c] = hi;
        }
    }
}

// =====================================================================
// Fused attn1 path + depthwise-conv residual + transpose into Y (rounded).
// Padded layouts, cp.async fills, all-scalar conflict-free fragment loads.
// smem: Qs[64][68] (later Vw[96][64]+w) | Ks[256][68] / Ps[64][260] | Cs[256][68] | red
// =====================================================================
#define FA1_SMEM (174080)
__global__ __launch_bounds__(256)
void k_fattn1(const float* __restrict__ qg, const float* __restrict__ klg,
              const float* __restrict__ cmg, const float* __restrict__ vg,
              const float* __restrict__ wres, float* __restrict__ Yg)
{
    extern __shared__ float sm[];
    float* Qs   = sm;                    // [64][68]; later Vw[96][64] + w[33]
    float* Ks   = sm + 8192;             // [256][68] = 17408
    float* Ps   = sm + 8192;             // [64][260] = 16640 (aliases Ks)
    float* Cs   = sm + 25600;            // [256][68]
    float* Mred = sm + 43008;            // [4][64]
    float* Lred = Mred + 256;            // [4][64]

    const int bh = blockIdx.y, b = bh >> 3, h = bh & 7;
    const int i0 = blockIdx.x * 64;
    const int tid = threadIdx.x;
    const int lane = tid & 31, g = lane >> 2, tg = lane & 3;
    const int wid = tid >> 5, wm = wid & 1, wn = wid >> 1;

    // fills: pure cp.async into padded row layouts (operands already tf32)
    const float* qb = qg + ((size_t)bh * SEQ + i0) * 64;
    #pragma unroll
    for (int i = 0; i < 4; i++) {
        int id = tid + i * 256; int row = id >> 4, d4 = (id & 15) << 2;
        cpa16(&Qs[row * 68 + d4], qb + row * 64 + d4);
    }
    const float* kb = klg + (size_t)bh * NM * 64;
    #pragma unroll
    for (int i = 0; i < 16; i++) {
        int id = tid + i * 256; int row = id >> 4, d4 = (id & 15) << 2;
        cpa16(&Ks[row * 68 + d4], kb + row * 64 + d4);
    }
    const float* cb = cmg + (size_t)bh * NM * 64;
    #pragma unroll
    for (int i = 0; i < 16; i++) {
        int id = tid + i * 256; int row = id >> 4, d4 = (id & 15) << 2;
        cpa16(&Cs[row * 68 + d4], cb + row * 64 + d4);
    }
    asm volatile("cp.async.commit_group;");
    asm volatile("cp.async.wait_group 0;");
    __syncthreads();

    // stage 1: scores 64x256
    float4 acc1[2][8];
    #pragma unroll
    for (int i = 0; i < 2; i++)
        #pragma unroll
        for (int j = 0; j < 8; j++) acc1[i][j] = make_float4(0.f, 0.f, 0.f, 0.f);

    #pragma unroll
    for (int s8 = 0; s8 < 64; s8 += 8) {
        const int k0 = s8 + tg;
        float a[2][4];
        #pragma unroll
        for (int mt = 0; mt < 2; mt++) {
            const int Rm = wm * 32 + mt * 16 + g;
            a[mt][0] = Qs[Rm * 68 + k0];
            a[mt][1] = Qs[(Rm + 8) * 68 + k0];
            a[mt][2] = Qs[Rm * 68 + k0 + 4];
            a[mt][3] = Qs[(Rm + 8) * 68 + k0 + 4];
        }
        #pragma unroll
        for (int nt = 0; nt < 8; nt++) {
            const int c = wn * 64 + nt * 8 + g;
            float b0 = Ks[c * 68 + k0];
            float b1 = Ks[c * 68 + k0 + 4];
            #pragma unroll
            for (int mt = 0; mt < 2; mt++)
                mma8(acc1[mt][nt], a[mt][0], a[mt][1], a[mt][2], a[mt][3], b0, b1);
        }
    }

    float rmax[4];
    #pragma unroll
    for (int t = 0; t < 4; t++) {
        const int mt = t >> 1; const bool hi = t & 1;
        float m = -1e30f;
        #pragma unroll
        for (int nt = 0; nt < 8; nt++) {
            float4 a = acc1[mt][nt];
            m = fmaxf(m, hi ? fmaxf(a.z, a.w) : fmaxf(a.x, a.y));
        }
        m = fmaxf(m, __shfl_xor_sync(0xffffffffu, m, 1));
        m = fmaxf(m, __shfl_xor_sync(0xffffffffu, m, 2));
        rmax[t] = m;
    }
    if (tg == 0) {
        #pragma unroll
        for (int t = 0; t < 4; t++) Mred[wn * 64 + 32 * wm + 8 * t + g] = rmax[t];
    }
    __syncthreads();   // stage-1 reads done: Qs/Ks regions may be reused

    // prefetch v window for conv into Qs region (dead) + conv weights
    {
        const float* vb = vg + (size_t)bh * SEQ * DH;
        #pragma unroll
        for (int i2 = 0; i2 < 6; i2++) {
            int id = tid + i2 * 256;                 // 1536 chunks = 96 rows x 16
            int j = id >> 4, d4 = (id & 15) << 2;
            int gi = i0 - 16 + j;
            bool ok = (gi >= 0 && gi < SEQ);
            cpa16z(&Qs[j * 64 + d4], vb + (size_t)(ok ? gi : 0) * 64 + d4, ok);
        }
        if (tid < 33) Qs[6144 + tid] = wres[h * 33 + tid];
        asm volatile("cp.async.commit_group;");
    }

    #pragma unroll
    for (int t = 0; t < 4; t++) {
        const int rl = 32 * wm + 8 * t + g;
        rmax[t] = fmaxf(fmaxf(Mred[rl], Mred[64 + rl]),
                        fmaxf(Mred[128 + rl], Mred[192 + rl]));
    }
    #pragma unroll
    for (int t = 0; t < 4; t++) {
        const int mt = t >> 1; const bool hi = t & 1;
        const int rl = 32 * wm + 8 * t + g;
        const float M = rmax[t];
        float s = 0.f;
        #pragma unroll
        for (int nt = 0; nt < 8; nt++) {
            float4 a = acc1[mt][nt];
            float v0 = hi ? a.z : a.x, v1 = hi ? a.w : a.y;
            float e0 = __expf(v0 - M), e1 = __expf(v1 - M);
            s += e0 + e1;
            int c0 = wn * 64 + nt * 8 + 2 * tg;
            Ps[rl * 260 + c0] = to_tf32(e0);
            Ps[rl * 260 + c0 + 1] = to_tf32(e1);
        }
        s += __shfl_xor_sync(0xffffffffu, s, 1);
        s += __shfl_xor_sync(0xffffffffu, s, 2);
        if (tg == 0) Lred[wn * 64 + rl] = s;
    }
    __syncthreads();

    // stage 2: O = P(64x256) @ Cm(256x64)
    float4 acc2[2][2];
    #pragma unroll
    for (int i = 0; i < 2; i++)
        #pragma unroll
        for (int j = 0; j < 2; j++) acc2[i][j] = make_float4(0.f, 0.f, 0.f, 0.f);

    #pragma unroll 4
    for (int s8 = 0; s8 < 256; s8 += 8) {
        const int k0 = s8 + tg, k1 = k0 + 4;
        float a_[2][4], b_[2][2];
        #pragma unroll
        for (int mt = 0; mt < 2; mt++) {
            const int r0 = wm * 32 + 16 * mt + g;
            a_[mt][0] = Ps[r0 * 260 + k0];
            a_[mt][1] = Ps[(r0 + 8) * 260 + k0];
            a_[mt][2] = Ps[r0 * 260 + k1];
            a_[mt][3] = Ps[(r0 + 8) * 260 + k1];
        }
        #pragma unroll
        for (int nt = 0; nt < 2; nt++) {
            const int c = wn * 16 + nt * 8 + g;
            b_[nt][0] = Cs[k0 * 68 + c];
            b_[nt][1] = Cs[k1 * 68 + c];
        }
        #pragma unroll
        for (int mt = 0; mt < 2; mt++)
            #pragma unroll
            for (int nt = 0; nt < 2; nt++)
                mma8(acc2[mt][nt], a_[mt][0], a_[mt][1], a_[mt][2], a_[mt][3],
                     b_[nt][0], b_[nt][1]);
    }

    float invL[4];
    #pragma unroll
    for (int t = 0; t < 4; t++) {
        const int rl = 32 * wm + 8 * t + g;
        float L = Lred[rl] + Lred[64 + rl] + Lred[128 + rl] + Lred[192 + rl];
        invL[t] = 1.f / L;
    }

    asm volatile("cp.async.wait_group 0;");
    __syncthreads();    // stage-2 reads of Cs done; Vw ready

    // stage scaled O into Osm (= Cs region, [64][68])
    #pragma unroll
    for (int mt = 0; mt < 2; mt++) {
        #pragma unroll
        for (int nt = 0; nt < 2; nt++) {
            const int c = wn * 16 + nt * 8 + 2 * tg;
            const int r0 = 32 * wm + 16 * mt + g;
            float4 v = acc2[mt][nt];
            float2 lo; lo.x = v.x * invL[2 * mt]; lo.y = v.y * invL[2 * mt];
            float2 hi; hi.x = v.z * invL[2 * mt + 1]; hi.y = v.w * invL[2 * mt + 1];
            *(float2*)&Cs[r0 * 68 + c] = lo;
            *(float2*)&Cs[(r0 + 8) * 68 + c] = hi;
        }
    }
    __syncthreads();

    // conv + write to Y (transposed layout, rounded for the out-proj GEMM)
    const float* wv = Qs + 6144;
    #pragma unroll
    for (int i2 = 0; i2 < 4; i2++) {
        int l4 = tid + i2 * 256;            // 1024 float4s = 64 rows x 16
        int i = l4 >> 4, d4 = (l4 & 15) << 2;
        float4 o = *(float4*)&Cs[i * 68 + d4];
        #pragma unroll
        for (int t = 0; t < 33; t++) {
            float wt = wv[t];
            float4 vv = *(float4*)&Qs[(i + t) * 64 + d4];
            o.x += wt * vv.x; o.y += wt * vv.y; o.z += wt * vv.z; o.w += wt * vv.w;
        }
        o.x = to_tf32(o.x); o.y = to_tf32(o.y); o.z = to_tf32(o.z); o.w = to_tf32(o.w);
        *(float4*)&Yg[(size_t)(b * SEQ + i0 + i) * DM + h * 64 + d4] = o;
    }
}

// landmarks: mean over 32 consecutive tokens (rounded outputs)
__global__ void k_land() {
    int idx = blockIdx.x * blockDim.x + threadIdx.x;   // BH*NM*DH
    int d = idx & 63, i = (idx >> 6) & 255, bh = idx >> 14;
    size_t base = (size_t)bh * SEQ * DH + (size_t)i * LG * DH + d;
    float qs = 0.f, ks = 0.f;
    #pragma unroll 8
    for (int j = 0; j < LG; j++) { qs += g_q[base + j * 64]; ks += g_k[base + j * 64]; }
    g_ql[idx] = to_tf32(qs * (1.f / LG));
    g_kl[idx] = to_tf32(ks * (1.f / LG));
}

// Row softmax (in place, rounded), 256 cols, one block per row.
__global__ void k_softmax(float* __restrict__ X) {
    const size_t base = (size_t)blockIdx.x * 256;
    const int tid = threadIdx.x, lane = tid & 31, wp = tid >> 5;
    __shared__ float red[8];
    float v = X[base + tid];
    float m = v;
    #pragma unroll
    for (int off = 16; off; off >>= 1) m = fmaxf(m, __shfl_xor_sync(0xffffffffu, m, off));
    if (!lane) red[wp] = m;
    __syncthreads();
    float M = red[0];
    #pragma unroll
    for (int w = 1; w < 8; w++) M = fmaxf(M, red[w]);
    __syncthreads();
    float e = __expf(v - M);
    float s = e;
    #pragma unroll
    for (int off = 16; off; off >>= 1) s += __shfl_xor_sync(0xffffffffu, s, off);
    if (!lane) red[wp] = s;
    __syncthreads();
    float S = 0.f;
    #pragma unroll
    for (int w = 0; w < 8; w++) S += red[w];
    X[base + tid] = to_tf32(e / S);
}

// reset: g_mx and pinv barrier counters (standalone, strictly before pinv)
__global__ void k_reset() {
    if (threadIdx.x < 2) g_mx[threadIdx.x] = 0u;
    if (threadIdx.x < BH) g_bar[threadIdx.x] = 0u;
}

__global__ void k_colrowmax() {
    const int bh = blockIdx.x, tid = threadIdx.x, lane = tid & 31, wp = tid >> 5;
    __shared__ float red[8];
    const float* Xb = g_X + (size_t)bh * NM * NM;
    float cs = 0.f;
    for (int i = 0; i < NM; i++) cs += Xb[i * NM + tid];
    float m = cs;
    #pragma unroll
    for (int off = 16; off; off >>= 1) m = fmaxf(m, __shfl_xor_sync(0xffffffffu, m, off));
    if (!lane) red[wp] = m;
    __syncthreads();
    if (tid == 0) {
        float M = red[0];
        #pragma unroll
        for (int w = 1; w < 8; w++) M = fmaxf(M, red[w]);
        atomicMax(&g_mx[1], __float_as_uint(M));
    }
    __syncthreads();
    float rs = 0.f;
    const float* Xr = Xb + (size_t)tid * NM;
    for (int j = 0; j < NM; j++) rs += Xr[j];
    m = rs;
    #pragma unroll
    for (int off = 16; off; off >>= 1) m = fmaxf(m, __shfl_xor_sync(0xffffffffu, m, off));
    if (!lane) red[wp] = m;
    __syncthreads();
    if (tid == 0) {
        float M = red[0];
        #pragma unroll
        for (int w = 1; w < 8; w++) M = fmaxf(M, red[w]);
        atomicMax(&g_mx[0], __float_as_uint(M));
    }
}

__global__ void k_zinit() {
    int idx = blockIdx.x * blockDim.x + threadIdx.x;   // BH*NM*NM
    float inv = 1.f / (__uint_as_float(g_mx[0]) * __uint_as_float(g_mx[1]));
    int j = idx & 255, i = (idx >> 8) & 255, bh = idx >> 16;
    g_Za[idx] = to_tf32(g_X[(size_t)bh * NM * NM + j * NM + i] * inv);
}

// =====================================================================
extern "C" void kernel_launch(void* const* d_in, const int* in_sizes, int n_in,
                              void* d_out, int out_size) {
    const float* x     = (const float*)d_in[0];
    const float* w_qkv = (const float*)d_in[1];
    const float* w_out = (const float*)d_in[2];
    const float* b_out = (const float*)d_in[3];
    const float* w_res = (const float*)d_in[4];
    float* out = (float*)d_out;

    float *q, *k_, *v, *ql, *kl, *X, *Za, *C2, *Cm, *Y, *wr;
    cudaGetSymbolAddress((void**)&q,   g_q);
    cudaGetSymbolAddress((void**)&k_,  g_k);
    cudaGetSymbolAddress((void**)&v,   g_v);
    cudaGetSymbolAddress((void**)&ql,  g_ql);
    cudaGetSymbolAddress((void**)&kl,  g_kl);
    cudaGetSymbolAddress((void**)&X,   g_X);
    cudaGetSymbolAddress((void**)&Za,  g_Za);
    cudaGetSymbolAddress((void**)&C2,  g_C2);
    cudaGetSymbolAddress((void**)&Cm,  g_Cm);
    cudaGetSymbolAddress((void**)&Y,   g_Y);
    cudaGetSymbolAddress((void**)&wr,  g_wr);

    // dynamic smem opt-in (floats: A 3*2560; B per layout)
    const int SM_NN128 = (3 * 2560 + 3 * 16 * 136) * 4;   // 56832
    const int SM_TN128 = (3 * 2560 + 3 * 128 * 20) * 4;   // 61440
    const int SM_NN64  = (3 * 2560 + 3 * 16 * 72) * 4;    // 44544
    cudaFuncSetAttribute(t_gemm<128, 2, false, 1, 1>, cudaFuncAttributeMaxDynamicSharedMemorySize, SM_NN128);
    cudaFuncSetAttribute(t_gemm<128, 2, false, 0, 0>, cudaFuncAttributeMaxDynamicSharedMemorySize, SM_NN128);
    cudaFuncSetAttribute(t_gemm<128, 2, true, 0, 0>,  cudaFuncAttributeMaxDynamicSharedMemorySize, SM_TN128);
    cudaFuncSetAttribute(t_gemm<64, 1, false, 0, 1>,  cudaFuncAttributeMaxDynamicSharedMemorySize, SM_NN64);
    cudaFuncSetAttribute(k_pinv,   cudaFuncAttributeMaxDynamicSharedMemorySize, SM_NN64);
    cudaFuncSetAttribute(k_fattn1, cudaFuncAttributeMaxDynamicSharedMemorySize, FA1_SMEM);
    cudaFuncSetAttribute(k_fattn3, cudaFuncAttributeMaxDynamicSharedMemorySize, FA3_SMEM);

    const float* NUL = (const float*)0;
    float* NULF = (float*)0;

    // 0. pre-round true inputs to tf32: x->g_Y, w_qkv|w_out->g_wr
    k_round3<<<17408, 256>>>(x, w_qkv, w_out);
    // 1. qkv = x_r @ w_qkv_r, scattered directly to packed q (scaled), k, v (rounded)
    t_gemm<128, 2, false, 1, 1><<<dim3(TRIPLE / 128, ROWS / 128, 1), 256, SM_NN128>>>(
        Y, DM, 0LL, wr, TRIPLE, 0LL, NUL, 0LL, NUL, q, TRIPLE, 0LL,
        DM, 1.f, 0.f, 1, q, k_, v);
    // 2. landmarks
    k_land<<<(BH * NM * DH) / 256, 256>>>();
    // 3. attn2 = softmax(q_land @ k_land^T)
    t_gemm<128, 2, true, 0, 0><<<dim3(2, 2, BH), 256, SM_TN128>>>(
        ql, DH, 16384LL, kl, DH, 16384LL, NUL, 0LL, NUL, X, NM, 65536LL,
        DH, 1.f, 0.f, 1, NULF, NULF, NULF);
    k_softmax<<<BH * NM, 256>>>(X);
    // 4. pinv init (standalone reset strictly before pinv)
    k_reset<<<1, 32>>>();
    k_colrowmax<<<BH, 256>>>();
    k_zinit<<<(BH * NM * NM) / 256, 256>>>();
    // 5. 6 Newton iterations, one persistent launch (result in g_Za)
    k_pinv<<<256, 256, SM_NN64>>>();
    // 6. fused flash sim3 path: C2 = softmax(ql @ k^T) @ v
    k_fattn3<<<dim3(4, BH), 256, FA3_SMEM>>>(ql, k_, v, C2);
    // 7. Cm = Z @ C2 (rounded)
    t_gemm<64, 1, false, 0, 1><<<dim3(1, 2, BH), 128, SM_NN64>>>(
        Za, NM, 65536LL, C2, DH, 16384LL, NUL, 0LL, NUL, Cm, DH, 16384LL,
        NM, 1.f, 0.f, 1, NULF, NULF, NULF);
    // 8. fused: Y = softmax(q @ kl^T) @ Cm + conv33(v), transposed (rounded)
    k_fattn1<<<dim3(SEQ / 64, BH), 256, FA1_SMEM>>>(q, kl, Cm, v, w_res, Y);
    // 9. out = Y @ w_out_r + b_out (full precision store)
    t_gemm<128, 2, false, 0, 0><<<dim3(DM / 128, ROWS / 128, 1), 256, SM_NN128>>>(
        Y, DM, 0LL, wr + TRIPLE * DM, DM, 0LL, NUL, 0LL, b_out, out, DM, 0LL,
        DM, 1.f, 0.f, 1, NULF, NULF, NULF);
}